// round 1
// baseline (speedup 1.0000x reference)
#include <cuda_runtime.h>
#include <math.h>

#define Bsz   4
#define Nseq  2048
#define Dm    513
#define Hh    8
#define Dhd   64
#define DhT   65
#define Mrows 8192          // B*N
#define INVK  10.0f
#define KCURV 0.1f
#define EPSf  1e-9f
#define SCALEf 0.125f       // 1/sqrt(64)

// ---------------- device scratch (no allocs allowed) ----------------
__device__ float Qg[Bsz*Hh*Nseq*DhT];     // q~ = ( t, q_space)
__device__ float Kg[Bsz*Hh*Nseq*DhT];     // k~ = (-t, k_space)
__device__ float Vg[Bsz*Hh*Nseq*DhT];     // v  = ( t, v_space)
__device__ float OutCat[(size_t)Mrows*512];  // concat of normalized head spatial parts
__device__ float HSS[Mrows*Hh];           // per (row, head): sum of squares of normalized spatial part
__device__ float Part2[Mrows*8];          // per (row, colblock) partial sum-sq of o_space

// =====================================================================
// K1: QKV projection. grid (128, 24): y -> (head, which). 64x64 tile,
// 128 threads, 4x8 microtile (interleaved cols). Epilogue attaches time.
// =====================================================================
__global__ __launch_bounds__(128) void qkv_kernel(
    const float* __restrict__ x,
    const float* __restrict__ Wq, const float* __restrict__ bq,
    const float* __restrict__ Wk, const float* __restrict__ bk,
    const float* __restrict__ Wv, const float* __restrict__ bv)
{
    const int which = blockIdx.y % 3;
    const int h     = blockIdx.y / 3;
    const float* W    = (which==0) ? Wq : (which==1) ? Wk : Wv;
    const float* bias = (which==0) ? bq : (which==1) ? bk : bv;
    float* Og         = (which==0) ? Qg : (which==1) ? Kg : Vg;
    W    += (size_t)h * Dm * Dhd;
    bias += h * Dhd;

    __shared__ float Xs[64][33];
    __shared__ float Ws[32][64];

    const int tid = threadIdx.x;
    const int rq = tid >> 3;       // 0..15 -> rows 4*rq..4*rq+3
    const int cs = tid & 7;        // cols cs + 8*j
    const int m0 = blockIdx.x * 64;

    float acc[4][8];
    #pragma unroll
    for (int i = 0; i < 4; i++)
        #pragma unroll
        for (int j = 0; j < 8; j++) acc[i][j] = 0.f;

    for (int kt = 0; kt < 17; kt++) {
        const int k0 = kt * 32;
        for (int i = tid; i < 64*32; i += 128) {
            int r = i >> 5, c = i & 31, gk = k0 + c;
            Xs[r][c] = (gk < Dm) ? x[(size_t)(m0 + r) * Dm + gk] : 0.f;
        }
        for (int i = tid; i < 32*64; i += 128) {
            int kk = i >> 6, c = i & 63, gk = k0 + kk;
            Ws[kk][c] = (gk < Dm) ? W[(size_t)gk * Dhd + c] : 0.f;
        }
        __syncthreads();
        #pragma unroll 8
        for (int kk = 0; kk < 32; kk++) {
            float xv[4], wv[8];
            #pragma unroll
            for (int i = 0; i < 4; i++) xv[i] = Xs[4*rq + i][kk];
            #pragma unroll
            for (int j = 0; j < 8; j++) wv[j] = Ws[kk][cs + 8*j];
            #pragma unroll
            for (int i = 0; i < 4; i++)
                #pragma unroll
                for (int j = 0; j < 8; j++) acc[i][j] = fmaf(xv[i], wv[j], acc[i][j]);
        }
        __syncthreads();
    }

    const float sign = (which == 1) ? -1.f : 1.f;
    #pragma unroll
    for (int i = 0; i < 4; i++) {
        int row = m0 + 4*rq + i;
        int b   = row >> 11;           // / Nseq
        int n   = row & (Nseq - 1);
        float* op = Og + (((size_t)(b*Hh + h)) * Nseq + n) * DhT;
        float ss = 0.f;
        #pragma unroll
        for (int j = 0; j < 8; j++) {
            float v = acc[i][j] + bias[cs + 8*j];
            acc[i][j] = v;
            ss += v * v;
        }
        ss += __shfl_xor_sync(0xffffffffu, ss, 1);
        ss += __shfl_xor_sync(0xffffffffu, ss, 2);
        ss += __shfl_xor_sync(0xffffffffu, ss, 4);
        if (cs == 0) op[0] = sign * sqrtf(fmaxf(INVK + ss, EPSf));
        #pragma unroll
        for (int j = 0; j < 8; j++) op[1 + cs + 8*j] = acc[i][j];
    }
}

// =====================================================================
// K2: flash attention + Lorentz midpoint. grid (32, 32): (q-tile, b*H+h).
// 128 threads. 64-query tile, 64-key tiles, 65-dim dot (time folded in).
// =====================================================================
__global__ __launch_bounds__(128) void attn_kernel()
{
    extern __shared__ float sm[];
    float* Qs = sm;                 // [64][65] row-major
    float* Ks = Qs + 64*65;         // [65][65] d-major (transposed)
    float* Vs = Ks + 65*65;         // [64][65] row-major
    float* Ps = Vs + 64*65;         // [64][65] row-major

    const int tid = threadIdx.x;
    const int rq = tid >> 3;        // 0..15
    const int cs = tid & 7;
    const int bh = blockIdx.y;
    const int b = bh >> 3, h = bh & 7;
    const int n0 = blockIdx.x * 64;
    const size_t base = ((size_t)(b*Hh + h)) * Nseq;

    for (int i = tid; i < 64*DhT; i += 128)
        Qs[i] = Qg[(base + n0) * DhT + i];

    float o[4][9];
    float m[4], l[4];
    #pragma unroll
    for (int i = 0; i < 4; i++) {
        m[i] = -1e30f; l[i] = 0.f;
        #pragma unroll
        for (int c = 0; c < 9; c++) o[i][c] = 0.f;
    }
    __syncthreads();

    for (int kt = 0; kt < 32; kt++) {
        const float* Kp = Kg + (base + kt*64) * DhT;
        const float* Vp = Vg + (base + kt*64) * DhT;
        for (int i = tid; i < 64*DhT; i += 128) {
            int r = i / DhT, d = i - r * DhT;
            Ks[d*65 + r] = Kp[i];
            Vs[i] = Vp[i];          // i == r*65+d
        }
        __syncthreads();

        float s[4][8];
        #pragma unroll
        for (int i = 0; i < 4; i++)
            #pragma unroll
            for (int j = 0; j < 8; j++) s[i][j] = 0.f;

        #pragma unroll 5
        for (int d = 0; d < 65; d++) {
            float qv[4], kv[8];
            #pragma unroll
            for (int i = 0; i < 4; i++) qv[i] = Qs[(4*rq + i)*65 + d];
            #pragma unroll
            for (int j = 0; j < 8; j++) kv[j] = Ks[d*65 + cs + 8*j];
            #pragma unroll
            for (int i = 0; i < 4; i++)
                #pragma unroll
                for (int j = 0; j < 8; j++) s[i][j] = fmaf(qv[i], kv[j], s[i][j]);
        }

        #pragma unroll
        for (int i = 0; i < 4; i++) {
            float mx = -1e30f;
            #pragma unroll
            for (int j = 0; j < 8; j++) { s[i][j] *= SCALEf; mx = fmaxf(mx, s[i][j]); }
            mx = fmaxf(mx, __shfl_xor_sync(0xffffffffu, mx, 1));
            mx = fmaxf(mx, __shfl_xor_sync(0xffffffffu, mx, 2));
            mx = fmaxf(mx, __shfl_xor_sync(0xffffffffu, mx, 4));
            float mnew = fmaxf(m[i], mx);
            float corr = __expf(m[i] - mnew);
            m[i] = mnew;
            float ls = 0.f;
            #pragma unroll
            for (int j = 0; j < 8; j++) { s[i][j] = __expf(s[i][j] - mnew); ls += s[i][j]; }
            ls += __shfl_xor_sync(0xffffffffu, ls, 1);
            ls += __shfl_xor_sync(0xffffffffu, ls, 2);
            ls += __shfl_xor_sync(0xffffffffu, ls, 4);
            l[i] = l[i] * corr + ls;
            #pragma unroll
            for (int c = 0; c < 9; c++) o[i][c] *= corr;
            #pragma unroll
            for (int j = 0; j < 8; j++) Ps[(4*rq + i)*65 + cs + 8*j] = s[i][j];
        }
        __syncthreads();

        #pragma unroll 4
        for (int jj = 0; jj < 64; jj++) {
            float pv[4], vv[9];
            #pragma unroll
            for (int i = 0; i < 4; i++) pv[i] = Ps[(4*rq + i)*65 + jj];
            #pragma unroll
            for (int c = 0; c < 9; c++) {
                int col = cs + 8*c;
                vv[c] = (col < 65) ? Vs[jj*65 + col] : 0.f;
            }
            #pragma unroll
            for (int i = 0; i < 4; i++)
                #pragma unroll
                for (int c = 0; c < 9; c++) o[i][c] = fmaf(pv[i], vv[c], o[i][c]);
        }
        __syncthreads();
    }

    // epilogue: normalize by l, Lorentz-midpoint rescale, scatter to concat buf
    #pragma unroll
    for (int i = 0; i < 4; i++) {
        float linv = 1.f / l[i];
        float ssum = 0.f;
        #pragma unroll
        for (int c = 0; c < 9; c++) {
            int col = cs + 8*c;
            if (col < 65) { o[i][c] *= linv; ssum += o[i][c] * o[i][c]; }
        }
        ssum += __shfl_xor_sync(0xffffffffu, ssum, 1);
        ssum += __shfl_xor_sync(0xffffffffu, ssum, 2);
        ssum += __shfl_xor_sync(0xffffffffu, ssum, 4);
        int lane = tid & 31;
        float s0 = __shfl_sync(0xffffffffu, o[i][0], lane & ~7);   // col 0 (time)
        float sp = ssum - s0 * s0;                                  // spatial sum-sq
        float dn = sqrtf(fmaxf(KCURV * (s0*s0 - sp), EPSf));
        float idn = 1.f / dn;
        int n = n0 + 4*rq + i;
        int row = b * Nseq + n;
        #pragma unroll
        for (int c = 0; c < 9; c++) {
            int col = cs + 8*c;
            if (col >= 1 && col < 65)
                OutCat[(size_t)row * 512 + h*64 + col - 1] = o[i][c] * idn;
        }
        if (cs == 0) HSS[row*8 + h] = sp * idn * idn;
    }
}

// =====================================================================
// K3: output LorentzFC. grid (128, 8). 64x64 tile, concat time coord t'
// synthesized from HSS when loading k==0. Row sum-sq partials -> Part2.
// =====================================================================
__global__ __launch_bounds__(128) void outproj_kernel(
    const float* __restrict__ Wo, const float* __restrict__ bo,
    float* __restrict__ out)
{
    __shared__ float Xs[64][33];
    __shared__ float Ws[32][64];
    const int tid = threadIdx.x;
    const int rq = tid >> 3, cs = tid & 7;
    const int m0 = blockIdx.x * 64;
    const int c0 = blockIdx.y * 64;

    float acc[4][8];
    #pragma unroll
    for (int i = 0; i < 4; i++)
        #pragma unroll
        for (int j = 0; j < 8; j++) acc[i][j] = 0.f;

    for (int kt = 0; kt < 17; kt++) {
        const int k0 = kt * 32;
        for (int i = tid; i < 64*32; i += 128) {
            int r = i >> 5, c = i & 31, gk = k0 + c;
            float v;
            if (gk >= Dm) v = 0.f;
            else if (gk == 0) {
                int row = m0 + r;
                float ss = 0.f;
                #pragma unroll
                for (int hh = 0; hh < 8; hh++) ss += HSS[row*8 + hh];
                v = sqrtf(fmaxf(INVK + ss, EPSf));
            } else {
                v = OutCat[(size_t)(m0 + r) * 512 + gk - 1];
            }
            Xs[r][c] = v;
        }
        for (int i = tid; i < 32*64; i += 128) {
            int kk = i >> 6, c = i & 63, gk = k0 + kk;
            Ws[kk][c] = (gk < Dm) ? Wo[(size_t)gk * 512 + c0 + c] : 0.f;
        }
        __syncthreads();
        #pragma unroll 8
        for (int kk = 0; kk < 32; kk++) {
            float xv[4], wv[8];
            #pragma unroll
            for (int i = 0; i < 4; i++) xv[i] = Xs[4*rq + i][kk];
            #pragma unroll
            for (int j = 0; j < 8; j++) wv[j] = Ws[kk][cs + 8*j];
            #pragma unroll
            for (int i = 0; i < 4; i++)
                #pragma unroll
                for (int j = 0; j < 8; j++) acc[i][j] = fmaf(xv[i], wv[j], acc[i][j]);
        }
        __syncthreads();
    }

    #pragma unroll
    for (int i = 0; i < 4; i++) {
        int row = m0 + 4*rq + i;
        float ss = 0.f;
        #pragma unroll
        for (int j = 0; j < 8; j++) {
            float v = acc[i][j] + bo[c0 + cs + 8*j];
            acc[i][j] = v;
            ss += v * v;
        }
        ss += __shfl_xor_sync(0xffffffffu, ss, 1);
        ss += __shfl_xor_sync(0xffffffffu, ss, 2);
        ss += __shfl_xor_sync(0xffffffffu, ss, 4);
        if (cs == 0) Part2[row*8 + blockIdx.y] = ss;
        #pragma unroll
        for (int j = 0; j < 8; j++)
            out[(size_t)row * Dm + 1 + c0 + cs + 8*j] = acc[i][j];
    }
}

// =====================================================================
// K4: attach final time coordinate.
// =====================================================================
__global__ void time_kernel(float* __restrict__ out)
{
    int row = blockIdx.x * 256 + threadIdx.x;
    if (row < Mrows) {
        float ss = 0.f;
        #pragma unroll
        for (int j = 0; j < 8; j++) ss += Part2[row*8 + j];
        out[(size_t)row * Dm] = sqrtf(fmaxf(INVK + ss, EPSf));
    }
}

// =====================================================================
extern "C" void kernel_launch(void* const* d_in, const int* in_sizes, int n_in,
                              void* d_out, int out_size)
{
    const float* x  = (const float*)d_in[0];
    const float* Wq = (const float*)d_in[1];
    const float* bq = (const float*)d_in[2];
    const float* Wk = (const float*)d_in[3];
    const float* bk = (const float*)d_in[4];
    const float* Wv = (const float*)d_in[5];
    const float* bv = (const float*)d_in[6];
    const float* Wo = (const float*)d_in[7];
    const float* bo = (const float*)d_in[8];
    float* out = (float*)d_out;

    const int smem_attn = (64*65*3 + 65*65) * (int)sizeof(float);  // 66820 B
    cudaFuncSetAttribute(attn_kernel, cudaFuncAttributeMaxDynamicSharedMemorySize, smem_attn);

    qkv_kernel<<<dim3(128, 24), 128>>>(x, Wq, bq, Wk, bk, Wv, bv);
    attn_kernel<<<dim3(32, 32), 128, smem_attn>>>();
    outproj_kernel<<<dim3(128, 8), 128>>>(Wo, bo, out);
    time_kernel<<<32, 256>>>(out);
}

// round 5
// speedup vs baseline: 1.1201x; 1.1201x over previous
#include <cuda_runtime.h>
#include <cuda_bf16.h>
#include <math.h>
#include <stdint.h>

#define Bsz   4
#define Nseq  2048
#define Dm    513
#define Hh    8
#define Dhd   64
#define DhT   65
#define Mrows 8192
#define KPAD  576
#define INVK  10.0f
#define KCURV 0.1f
#define EPSf  1e-9f
#define SCALEf 0.125f

// ---------------- device scratch ----------------
__device__ float Qg[Bsz*Hh*Nseq*DhT];
__device__ float Kg[Bsz*Hh*Nseq*DhT];
__device__ float Vg[Bsz*Hh*Nseq*DhT];
__device__ float OutCat[(size_t)Mrows*512];
__device__ float HSS[Mrows*Hh];
__device__ float Part2[Mrows*8];
__device__ __nv_bfloat16 Xhi[(size_t)Mrows*KPAD];
__device__ __nv_bfloat16 Xlo[(size_t)Mrows*KPAD];
__device__ __nv_bfloat16 WqkvHi[24*64*KPAD];
__device__ __nv_bfloat16 WqkvLo[24*64*KPAD];
__device__ __nv_bfloat16 WoTHi[512*KPAD];
__device__ __nv_bfloat16 WoTLo[512*KPAD];
__device__ __nv_bfloat16 Chi[(size_t)Mrows*KPAD];
__device__ __nv_bfloat16 Clo[(size_t)Mrows*KPAD];

__device__ __forceinline__ void bsplit(float v, __nv_bfloat16& h, __nv_bfloat16& l) {
    h = __float2bfloat16(v);
    l = __float2bfloat16(v - __bfloat162float(h));
}

#define MMA16816(D, A, B) \
    asm volatile("mma.sync.aligned.m16n8k16.row.col.f32.bf16.bf16.f32 " \
        "{%0,%1,%2,%3}, {%4,%5,%6,%7}, {%8,%9}, {%0,%1,%2,%3};" \
        : "+f"((D)[0]), "+f"((D)[1]), "+f"((D)[2]), "+f"((D)[3]) \
        : "r"((A)[0]), "r"((A)[1]), "r"((A)[2]), "r"((A)[3]), \
          "r"((B)[0]), "r"((B)[1]))

// smem word strides: rows padded to 72 bf16 = 36 words (conflict-free frag loads)
#define RS 36
// smem layout in 4-byte words
#define WA_HI 0                   // 128 rows * 36 = 4608 words
#define WA_LO 4608
#define WB_HI 9216                // 64 rows * 36 = 2304 words
#define WB_LO 11520
#define WBIAS 13824               // 64 words
#define WSSP  13888               // 128*2 words
#define WTOT  14144               // *4 = 56576 bytes

// =====================================================================
// conversion kernels
// =====================================================================
__global__ void cvt_w_kernel(const float* __restrict__ Wq, const float* __restrict__ Wk,
                             const float* __restrict__ Wv, const float* __restrict__ Wo)
{
    const int total1 = 24 * 64 * KPAD;
    const int total  = total1 + 512 * KPAD;
    for (int idx = blockIdx.x * blockDim.x + threadIdx.x; idx < total;
         idx += gridDim.x * blockDim.x) {
        if (idx < total1) {
            int k = idx % KPAD;
            int t = idx / KPAD;
            int n = t % 64;
            int s = t / 64;
            int which = s >> 3, h = s & 7;
            const float* W = (which == 0) ? Wq : (which == 1) ? Wk : Wv;
            float v = (k < Dm) ? W[((size_t)h * Dm + k) * 64 + n] : 0.f;
            bsplit(v, WqkvHi[idx], WqkvLo[idx]);
        } else {
            int i2 = idx - total1;
            int k = i2 % KPAD;
            int n = i2 / KPAD;
            float v = (k < Dm) ? Wo[(size_t)k * 512 + n] : 0.f;
            bsplit(v, WoTHi[i2], WoTLo[i2]);
        }
    }
}

__global__ void cvt_x_kernel(const float* __restrict__ x)
{
    const size_t total = (size_t)Mrows * KPAD;
    for (size_t idx = (size_t)blockIdx.x * blockDim.x + threadIdx.x; idx < total;
         idx += (size_t)gridDim.x * blockDim.x) {
        int k = (int)(idx % KPAD);
        size_t row = idx / KPAD;
        float v = (k < Dm) ? x[row * Dm + k] : 0.f;
        bsplit(v, Xhi[idx], Xlo[idx]);
    }
}

__global__ void cvt_cat_kernel()
{
    const size_t total = (size_t)Mrows * KPAD;
    for (size_t idx = (size_t)blockIdx.x * blockDim.x + threadIdx.x; idx < total;
         idx += (size_t)gridDim.x * blockDim.x) {
        int k = (int)(idx % KPAD);
        size_t row = idx / KPAD;
        float v;
        if (k == 0) {
            float ss = 0.f;
            #pragma unroll
            for (int hh = 0; hh < 8; hh++) ss += HSS[row * 8 + hh];
            v = sqrtf(fmaxf(INVK + ss, EPSf));
        } else if (k < Dm) {
            v = OutCat[row * 512 + k - 1];
        } else v = 0.f;
        bsplit(v, Chi[idx], Clo[idx]);
    }
}

// =====================================================================
// tile copies into padded smem (stride 72 bf16 / 144B per row)
// =====================================================================
__device__ __forceinline__ void copyA(uint32_t* smw, int dst_w,
                                      const __nv_bfloat16* __restrict__ src, int tid)
{
    // 128 rows x 64 bf16; 1024 uint4
    for (int i = tid; i < 1024; i += 256) {
        int r = i >> 3, q = i & 7;
        uint4 v = *(const uint4*)(src + (size_t)r * KPAD + q * 8);
        *(uint4*)(smw + dst_w + r * RS + q * 4) = v;
    }
}
__device__ __forceinline__ void copyB(uint32_t* smw, int dst_w,
                                      const __nv_bfloat16* __restrict__ src, int tid)
{
    // 64 rows x 64 bf16; 512 uint4
    for (int i = tid; i < 512; i += 256) {
        int r = i >> 3, q = i & 7;
        uint4 v = *(const uint4*)(src + (size_t)r * KPAD + q * 8);
        *(uint4*)(smw + dst_w + r * RS + q * 4) = v;
    }
}

// =====================================================================
// shared mainloop: block tile 128x64, 256 thr (warp grid 4m x 2n,
// warp tile 32x32 = 2 mtiles x 4 ntiles), K in 9 chunks of 64.
// bf16x3 accumulation.  acc[mt][nt][4]
// =====================================================================
__device__ __forceinline__ void gemm_mainloop(
    uint32_t* smw, int tid,
    const __nv_bfloat16* Ah, const __nv_bfloat16* Al,
    const __nv_bfloat16* Bh, const __nv_bfloat16* Bl,
    float acc[2][4][4])
{
    const int wid = tid >> 5, lane = tid & 31;
    const int wm = wid & 3, wn = wid >> 2;
    const int g = lane >> 2, t = lane & 3;

    for (int c = 0; c < 9; c++) {
        const int k0 = c * 64;
        __syncthreads();
        copyA(smw, WA_HI, Ah + k0, tid);
        copyA(smw, WA_LO, Al + k0, tid);
        copyB(smw, WB_HI, Bh + k0, tid);
        copyB(smw, WB_LO, Bl + k0, tid);
        __syncthreads();

        #pragma unroll
        for (int ks = 0; ks < 4; ks++) {
            uint32_t ah[2][4], al[2][4], bh[4][2], bl[4][2];
            const int kw = ks * 8 + t;
            #pragma unroll
            for (int mt = 0; mt < 2; mt++) {
                int r = wm * 32 + mt * 16 + g;
                ah[mt][0] = smw[WA_HI + r * RS + kw];
                ah[mt][1] = smw[WA_HI + (r + 8) * RS + kw];
                ah[mt][2] = smw[WA_HI + r * RS + kw + 4];
                ah[mt][3] = smw[WA_HI + (r + 8) * RS + kw + 4];
                al[mt][0] = smw[WA_LO + r * RS + kw];
                al[mt][1] = smw[WA_LO + (r + 8) * RS + kw];
                al[mt][2] = smw[WA_LO + r * RS + kw + 4];
                al[mt][3] = smw[WA_LO + (r + 8) * RS + kw + 4];
            }
            #pragma unroll
            for (int nt = 0; nt < 4; nt++) {
                int n = wn * 32 + nt * 8 + g;
                bh[nt][0] = smw[WB_HI + n * RS + kw];
                bh[nt][1] = smw[WB_HI + n * RS + kw + 4];
                bl[nt][0] = smw[WB_LO + n * RS + kw];
                bl[nt][1] = smw[WB_LO + n * RS + kw + 4];
            }
            #pragma unroll
            for (int mt = 0; mt < 2; mt++)
                #pragma unroll
                for (int nt = 0; nt < 4; nt++) {
                    MMA16816(acc[mt][nt], ah[mt], bh[nt]);
                    MMA16816(acc[mt][nt], ah[mt], bl[nt]);
                    MMA16816(acc[mt][nt], al[mt], bh[nt]);
                }
        }
    }
}

// =====================================================================
// K1: QKV GEMM via mma.sync. grid (64, 24)
// =====================================================================
__global__ __launch_bounds__(256) void qkv_mma(
    const float* __restrict__ bq, const float* __restrict__ bk, const float* __restrict__ bv)
{
    extern __shared__ uint32_t smw[];
    const int tid = threadIdx.x;
    const int wid = tid >> 5, lane = tid & 31;
    const int wm = wid & 3, wn = wid >> 2;
    const int g = lane >> 2, t = lane & 3;
    const int which = blockIdx.y % 3;
    const int h     = blockIdx.y / 3;
    const int slot  = which * 8 + h;
    const int m0    = blockIdx.x * 128;

    {
        const float* bias = (which == 0) ? bq : (which == 1) ? bk : bv;
        if (tid < 64) ((float*)(smw + WBIAS))[tid] = bias[h * 64 + tid];
    }

    float acc[2][4][4];
    #pragma unroll
    for (int mt = 0; mt < 2; mt++)
        #pragma unroll
        for (int nt = 0; nt < 4; nt++)
            #pragma unroll
            for (int i = 0; i < 4; i++) acc[mt][nt][i] = 0.f;

    gemm_mainloop(smw, tid,
                  Xhi + (size_t)m0 * KPAD, Xlo + (size_t)m0 * KPAD,
                  WqkvHi + (size_t)slot * 64 * KPAD, WqkvLo + (size_t)slot * 64 * KPAD,
                  acc);

    // epilogue
    const float* biass = (const float*)(smw + WBIAS);
    float* ssP = (float*)(smw + WSSP);
    float* Og = (which == 0) ? Qg : (which == 1) ? Kg : Vg;
    const float sign = (which == 1) ? -1.f : 1.f;

    __syncthreads();
    #pragma unroll
    for (int mt = 0; mt < 2; mt++) {
        #pragma unroll
        for (int half = 0; half < 2; half++) {
            int lrow = wm * 32 + mt * 16 + g + half * 8;   // 0..127
            int row = m0 + lrow;
            int b = row >> 11, n = row & (Nseq - 1);
            float* op = Og + (((size_t)(b * Hh + h)) * Nseq + n) * DhT;
            float ss = 0.f;
            #pragma unroll
            for (int nt = 0; nt < 4; nt++) {
                #pragma unroll
                for (int cc = 0; cc < 2; cc++) {
                    int col = wn * 32 + nt * 8 + 2 * t + cc;
                    float v = acc[mt][nt][half * 2 + cc] + biass[col];
                    op[1 + col] = v;
                    ss += v * v;
                }
            }
            ss += __shfl_xor_sync(0xffffffffu, ss, 1);
            ss += __shfl_xor_sync(0xffffffffu, ss, 2);
            if (t == 0) ssP[lrow * 2 + wn] = ss;
        }
    }
    __syncthreads();
    if (wn == 0 && t == 0) {
        #pragma unroll
        for (int mt = 0; mt < 2; mt++)
            #pragma unroll
            for (int half = 0; half < 2; half++) {
                int lrow = wm * 32 + mt * 16 + g + half * 8;
                int row = m0 + lrow;
                int b = row >> 11, n = row & (Nseq - 1);
                float ss = ssP[lrow * 2] + ssP[lrow * 2 + 1];
                Og[(((size_t)(b * Hh + h)) * Nseq + n) * DhT] =
                    sign * sqrtf(fmaxf(INVK + ss, EPSf));
            }
    }
}

// =====================================================================
// K3: output projection via mma.sync. grid (64, 8)
// =====================================================================
__global__ __launch_bounds__(256) void outproj_mma(
    const float* __restrict__ bo, float* __restrict__ out)
{
    extern __shared__ uint32_t smw[];
    const int tid = threadIdx.x;
    const int wid = tid >> 5, lane = tid & 31;
    const int wm = wid & 3, wn = wid >> 2;
    const int g = lane >> 2, t = lane & 3;
    const int m0 = blockIdx.x * 128;
    const int c0 = blockIdx.y * 64;

    if (tid < 64) ((float*)(smw + WBIAS))[tid] = bo[c0 + tid];

    float acc[2][4][4];
    #pragma unroll
    for (int mt = 0; mt < 2; mt++)
        #pragma unroll
        for (int nt = 0; nt < 4; nt++)
            #pragma unroll
            for (int i = 0; i < 4; i++) acc[mt][nt][i] = 0.f;

    gemm_mainloop(smw, tid,
                  Chi + (size_t)m0 * KPAD, Clo + (size_t)m0 * KPAD,
                  WoTHi + (size_t)c0 * KPAD, WoTLo + (size_t)c0 * KPAD,
                  acc);

    const float* biass = (const float*)(smw + WBIAS);
    float* ssP = (float*)(smw + WSSP);

    __syncthreads();
    #pragma unroll
    for (int mt = 0; mt < 2; mt++) {
        #pragma unroll
        for (int half = 0; half < 2; half++) {
            int lrow = wm * 32 + mt * 16 + g + half * 8;
            int row = m0 + lrow;
            float ss = 0.f;
            #pragma unroll
            for (int nt = 0; nt < 4; nt++) {
                #pragma unroll
                for (int cc = 0; cc < 2; cc++) {
                    int col = wn * 32 + nt * 8 + 2 * t + cc;
                    float v = acc[mt][nt][half * 2 + cc] + biass[col];
                    out[(size_t)row * Dm + 1 + c0 + col] = v;
                    ss += v * v;
                }
            }
            ss += __shfl_xor_sync(0xffffffffu, ss, 1);
            ss += __shfl_xor_sync(0xffffffffu, ss, 2);
            if (t == 0) ssP[lrow * 2 + wn] = ss;
        }
    }
    __syncthreads();
    if (wn == 0 && t == 0) {
        #pragma unroll
        for (int mt = 0; mt < 2; mt++)
            #pragma unroll
            for (int half = 0; half < 2; half++) {
                int lrow = wm * 32 + mt * 16 + g + half * 8;
                int row = m0 + lrow;
                Part2[row * 8 + blockIdx.y] = ssP[lrow * 2] + ssP[lrow * 2 + 1];
            }
    }
}

// =====================================================================
// K2: flash attention + Lorentz midpoint (proven fp32 path from R1).
// =====================================================================
__global__ __launch_bounds__(128) void attn_kernel()
{
    extern __shared__ float smf[];
    float* Qs = smf;
    float* Ks = Qs + 64*65;
    float* Vs = Ks + 65*65;
    float* Ps = Vs + 64*65;

    const int tid = threadIdx.x;
    const int rq = tid >> 3;
    const int cs = tid & 7;
    const int bh = blockIdx.y;
    const int b = bh >> 3, h = bh & 7;
    const int n0 = blockIdx.x * 64;
    const size_t base = ((size_t)(b*Hh + h)) * Nseq;

    for (int i = tid; i < 64*DhT; i += 128)
        Qs[i] = Qg[(base + n0) * DhT + i];

    float o[4][9];
    float m[4], l[4];
    #pragma unroll
    for (int i = 0; i < 4; i++) {
        m[i] = -1e30f; l[i] = 0.f;
        #pragma unroll
        for (int c = 0; c < 9; c++) o[i][c] = 0.f;
    }
    __syncthreads();

    for (int kt = 0; kt < 32; kt++) {
        const float* Kp = Kg + (base + kt*64) * DhT;
        const float* Vp = Vg + (base + kt*64) * DhT;
        for (int i = tid; i < 64*DhT; i += 128) {
            int r = i / DhT, d = i - r * DhT;
            Ks[d*65 + r] = Kp[i];
            Vs[i] = Vp[i];
        }
        __syncthreads();

        float s[4][8];
        #pragma unroll
        for (int i = 0; i < 4; i++)
            #pragma unroll
            for (int j = 0; j < 8; j++) s[i][j] = 0.f;

        #pragma unroll 5
        for (int d = 0; d < 65; d++) {
            float qv[4], kv[8];
            #pragma unroll
            for (int i = 0; i < 4; i++) qv[i] = Qs[(4*rq + i)*65 + d];
            #pragma unroll
            for (int j = 0; j < 8; j++) kv[j] = Ks[d*65 + cs + 8*j];
            #pragma unroll
            for (int i = 0; i < 4; i++)
                #pragma unroll
                for (int j = 0; j < 8; j++) s[i][j] = fmaf(qv[i], kv[j], s[i][j]);
        }

        #pragma unroll
        for (int i = 0; i < 4; i++) {
            float mx = -1e30f;
            #pragma unroll
            for (int j = 0; j < 8; j++) { s[i][j] *= SCALEf; mx = fmaxf(mx, s[i][j]); }
            mx = fmaxf(mx, __shfl_xor_sync(0xffffffffu, mx, 1));
            mx = fmaxf(mx, __shfl_xor_sync(0xffffffffu, mx, 2));
            mx = fmaxf(mx, __shfl_xor_sync(0xffffffffu, mx, 4));
            float mnew = fmaxf(m[i], mx);
            float corr = __expf(m[i] - mnew);
            m[i] = mnew;
            float ls = 0.f;
            #pragma unroll
            for (int j = 0; j < 8; j++) { s[i][j] = __expf(s[i][j] - mnew); ls += s[i][j]; }
            ls += __shfl_xor_sync(0xffffffffu, ls, 1);
            ls += __shfl_xor_sync(0xffffffffu, ls, 2);
            ls += __shfl_xor_sync(0xffffffffu, ls, 4);
            l[i] = l[i] * corr + ls;
            #pragma unroll
            for (int c = 0; c < 9; c++) o[i][c] *= corr;
            #pragma unroll
            for (int j = 0; j < 8; j++) Ps[(4*rq + i)*65 + cs + 8*j] = s[i][j];
        }
        __syncthreads();

        #pragma unroll 4
        for (int jj = 0; jj < 64; jj++) {
            float pv[4], vv[9];
            #pragma unroll
            for (int i = 0; i < 4; i++) pv[i] = Ps[(4*rq + i)*65 + jj];
            #pragma unroll
            for (int c = 0; c < 9; c++) {
                int col = cs + 8*c;
                vv[c] = (col < 65) ? Vs[jj*65 + col] : 0.f;
            }
            #pragma unroll
            for (int i = 0; i < 4; i++)
                #pragma unroll
                for (int c = 0; c < 9; c++) o[i][c] = fmaf(pv[i], vv[c], o[i][c]);
        }
        __syncthreads();
    }

    #pragma unroll
    for (int i = 0; i < 4; i++) {
        float linv = 1.f / l[i];
        float ssum = 0.f;
        #pragma unroll
        for (int c = 0; c < 9; c++) {
            int col = cs + 8*c;
            if (col < 65) { o[i][c] *= linv; ssum += o[i][c] * o[i][c]; }
        }
        ssum += __shfl_xor_sync(0xffffffffu, ssum, 1);
        ssum += __shfl_xor_sync(0xffffffffu, ssum, 2);
        ssum += __shfl_xor_sync(0xffffffffu, ssum, 4);
        int lane = tid & 31;
        float s0 = __shfl_sync(0xffffffffu, o[i][0], lane & ~7);
        float sp = ssum - s0 * s0;
        float dn = sqrtf(fmaxf(KCURV * (s0*s0 - sp), EPSf));
        float idn = 1.f / dn;
        int n = n0 + 4*rq + i;
        int row = b * Nseq + n;
        #pragma unroll
        for (int c = 0; c < 9; c++) {
            int col = cs + 8*c;
            if (col >= 1 && col < 65)
                OutCat[(size_t)row * 512 + h*64 + col - 1] = o[i][c] * idn;
        }
        if (cs == 0) HSS[row*8 + h] = sp * idn * idn;
    }
}

// =====================================================================
// K4: attach final time coordinate.
// =====================================================================
__global__ void time_kernel(float* __restrict__ out)
{
    int row = blockIdx.x * 256 + threadIdx.x;
    if (row < Mrows) {
        float ss = 0.f;
        #pragma unroll
        for (int j = 0; j < 8; j++) ss += Part2[row*8 + j];
        out[(size_t)row * Dm] = sqrtf(fmaxf(INVK + ss, EPSf));
    }
}

// =====================================================================
extern "C" void kernel_launch(void* const* d_in, const int* in_sizes, int n_in,
                              void* d_out, int out_size)
{
    const float* x  = (const float*)d_in[0];
    const float* Wq = (const float*)d_in[1];
    const float* bq = (const float*)d_in[2];
    const float* Wk = (const float*)d_in[3];
    const float* bk = (const float*)d_in[4];
    const float* Wv = (const float*)d_in[5];
    const float* bv = (const float*)d_in[6];
    const float* Wo = (const float*)d_in[7];
    const float* bo = (const float*)d_in[8];
    float* out = (float*)d_out;

    const int smem_attn = (64*65*3 + 65*65) * (int)sizeof(float);
    const int smem_gemm = WTOT * 4;
    cudaFuncSetAttribute(attn_kernel, cudaFuncAttributeMaxDynamicSharedMemorySize, smem_attn);
    cudaFuncSetAttribute(qkv_mma, cudaFuncAttributeMaxDynamicSharedMemorySize, smem_gemm);
    cudaFuncSetAttribute(outproj_mma, cudaFuncAttributeMaxDynamicSharedMemorySize, smem_gemm);

    cvt_w_kernel<<<1152, 1024>>>(Wq, Wk, Wv, Wo);
    cvt_x_kernel<<<4608, 1024>>>(x);
    qkv_mma<<<dim3(64, 24), 256, smem_gemm>>>(bq, bk, bv);
    attn_kernel<<<dim3(32, 32), 128, smem_attn>>>();
    cvt_cat_kernel<<<4608, 1024>>>();
    outproj_mma<<<dim3(64, 8), 256, smem_gemm>>>(bo, out);
    time_kernel<<<32, 256>>>(out);
}

// round 6
// speedup vs baseline: 1.8015x; 1.6084x over previous
#include <cuda_runtime.h>
#include <cuda_bf16.h>
#include <math.h>
#include <stdint.h>

#define Bsz   4
#define Nseq  2048
#define Dm    513
#define Hh    8
#define Mrows 8192
#define KPAD  576
#define INVK  10.0f
#define KCURV 0.1f
#define EPSf  1e-9f
#define S2f   0.18033688011112042f   // 0.125 * log2(e)

// ---------------- device scratch ----------------
__device__ float OutCat[(size_t)Mrows*512];
__device__ float HSS[Mrows*Hh];
__device__ float Part2[Mrows*8];
__device__ __nv_bfloat16 Xhi[(size_t)Mrows*KPAD];
__device__ __nv_bfloat16 Xlo[(size_t)Mrows*KPAD];
__device__ __nv_bfloat16 WqkvHi[24*64*KPAD];
__device__ __nv_bfloat16 WqkvLo[24*64*KPAD];
__device__ __nv_bfloat16 WoTHi[512*KPAD];
__device__ __nv_bfloat16 WoTLo[512*KPAD];
__device__ __nv_bfloat16 Chi[(size_t)Mrows*KPAD];
__device__ __nv_bfloat16 Clo[(size_t)Mrows*KPAD];
// attention operands (split bf16)
__device__ __nv_bfloat16 QSh[(size_t)32*2048*64];
__device__ __nv_bfloat16 QSl[(size_t)32*2048*64];
__device__ __nv_bfloat16 KSh[(size_t)32*2048*64];
__device__ __nv_bfloat16 KSl[(size_t)32*2048*64];
__device__ float Tqg[32*2048];
__device__ float Tkg[32*2048];
__device__ __nv_bfloat16 Vh_[(size_t)32*2048*65];
__device__ __nv_bfloat16 Vl_[(size_t)32*2048*65];
__device__ __nv_bfloat16 VTh[(size_t)32*72*2048];
__device__ __nv_bfloat16 VTl[(size_t)32*72*2048];

__device__ __forceinline__ void bsplit(float v, __nv_bfloat16& h, __nv_bfloat16& l) {
    h = __float2bfloat16(v);
    l = __float2bfloat16(v - __bfloat162float(h));
}
__device__ __forceinline__ uint32_t pack2(__nv_bfloat16 a, __nv_bfloat16 b) {
    __nv_bfloat162 t2; t2.x = a; t2.y = b;
    uint32_t r; memcpy(&r, &t2, 4); return r;
}

// fast exp2 for y <= 0 (FMA pipe, no MUFU)
__device__ __forceinline__ float exp2p(float y) {
    y = fmaxf(y, -120.f);
    float z = y + 12582912.f;          // round-to-nearest int via magic
    int ib = __float_as_int(z);
    float n = z - 12582912.f;
    float f = y - n;                   // [-0.5, 0.5]
    float p = 1.3333558146e-3f;
    p = fmaf(p, f, 9.6181291076e-3f);
    p = fmaf(p, f, 5.5504108664e-2f);
    p = fmaf(p, f, 2.4022650696e-1f);
    p = fmaf(p, f, 6.9314718056e-1f);
    p = fmaf(p, f, 1.0f);
    float sc = __int_as_float((((ib & 0x7FFFFF) - 0x400000) + 127) << 23);
    return p * sc;
}

#define MMA16816(D, A, B) \
    asm volatile("mma.sync.aligned.m16n8k16.row.col.f32.bf16.bf16.f32 " \
        "{%0,%1,%2,%3}, {%4,%5,%6,%7}, {%8,%9}, {%0,%1,%2,%3};" \
        : "+f"((D)[0]), "+f"((D)[1]), "+f"((D)[2]), "+f"((D)[3]) \
        : "r"((A)[0]), "r"((A)[1]), "r"((A)[2]), "r"((A)[3]), \
          "r"((B)[0]), "r"((B)[1]))

#define RS 36
#define WA_HI 0
#define WA_LO 4608
#define WB_HI 9216
#define WB_LO 11520
#define WBIAS 13824
#define WSSP  13888
#define WTOT  14144

// =====================================================================
// conversion kernels (unchanged)
// =====================================================================
__global__ void cvt_w_kernel(const float* __restrict__ Wq, const float* __restrict__ Wk,
                             const float* __restrict__ Wv, const float* __restrict__ Wo)
{
    const int total1 = 24 * 64 * KPAD;
    const int total  = total1 + 512 * KPAD;
    for (int idx = blockIdx.x * blockDim.x + threadIdx.x; idx < total;
         idx += gridDim.x * blockDim.x) {
        if (idx < total1) {
            int k = idx % KPAD;
            int t = idx / KPAD;
            int n = t % 64;
            int s = t / 64;
            int which = s >> 3, h = s & 7;
            const float* W = (which == 0) ? Wq : (which == 1) ? Wk : Wv;
            float v = (k < Dm) ? W[((size_t)h * Dm + k) * 64 + n] : 0.f;
            bsplit(v, WqkvHi[idx], WqkvLo[idx]);
        } else {
            int i2 = idx - total1;
            int k = i2 % KPAD;
            int n = i2 / KPAD;
            float v = (k < Dm) ? Wo[(size_t)k * 512 + n] : 0.f;
            bsplit(v, WoTHi[i2], WoTLo[i2]);
        }
    }
}

__global__ void cvt_x_kernel(const float* __restrict__ x)
{
    const size_t total = (size_t)Mrows * KPAD;
    for (size_t idx = (size_t)blockIdx.x * blockDim.x + threadIdx.x; idx < total;
         idx += (size_t)gridDim.x * blockDim.x) {
        int k = (int)(idx % KPAD);
        size_t row = idx / KPAD;
        float v = (k < Dm) ? x[row * Dm + k] : 0.f;
        bsplit(v, Xhi[idx], Xlo[idx]);
    }
}

__global__ void cvt_cat_kernel()
{
    const size_t total = (size_t)Mrows * KPAD;
    for (size_t idx = (size_t)blockIdx.x * blockDim.x + threadIdx.x; idx < total;
         idx += (size_t)gridDim.x * blockDim.x) {
        int k = (int)(idx % KPAD);
        size_t row = idx / KPAD;
        float v;
        if (k == 0) {
            float ss = 0.f;
            #pragma unroll
            for (int hh = 0; hh < 8; hh++) ss += HSS[row * 8 + hh];
            v = sqrtf(fmaxf(INVK + ss, EPSf));
        } else if (k < Dm) {
            v = OutCat[row * 512 + k - 1];
        } else v = 0.f;
        bsplit(v, Chi[idx], Clo[idx]);
    }
}

// =====================================================================
// GEMM mainloop pieces (from R5, working)
// =====================================================================
__device__ __forceinline__ void copyA(uint32_t* smw, int dst_w,
                                      const __nv_bfloat16* __restrict__ src, int tid)
{
    for (int i = tid; i < 1024; i += 256) {
        int r = i >> 3, q = i & 7;
        uint4 v = *(const uint4*)(src + (size_t)r * KPAD + q * 8);
        *(uint4*)(smw + dst_w + r * RS + q * 4) = v;
    }
}
__device__ __forceinline__ void copyB(uint32_t* smw, int dst_w,
                                      const __nv_bfloat16* __restrict__ src, int tid)
{
    for (int i = tid; i < 512; i += 256) {
        int r = i >> 3, q = i & 7;
        uint4 v = *(const uint4*)(src + (size_t)r * KPAD + q * 8);
        *(uint4*)(smw + dst_w + r * RS + q * 4) = v;
    }
}

__device__ __forceinline__ void gemm_mainloop(
    uint32_t* smw, int tid,
    const __nv_bfloat16* Ah, const __nv_bfloat16* Al,
    const __nv_bfloat16* Bh, const __nv_bfloat16* Bl,
    float acc[2][4][4])
{
    const int wid = tid >> 5, lane = tid & 31;
    const int wm = wid & 3, wn = wid >> 2;
    const int g = lane >> 2, t = lane & 3;

    for (int c = 0; c < 9; c++) {
        const int k0 = c * 64;
        __syncthreads();
        copyA(smw, WA_HI, Ah + k0, tid);
        copyA(smw, WA_LO, Al + k0, tid);
        copyB(smw, WB_HI, Bh + k0, tid);
        copyB(smw, WB_LO, Bl + k0, tid);
        __syncthreads();

        #pragma unroll
        for (int ks = 0; ks < 4; ks++) {
            uint32_t ah[2][4], al[2][4], bh[4][2], bl[4][2];
            const int kw = ks * 8 + t;
            #pragma unroll
            for (int mt = 0; mt < 2; mt++) {
                int r = wm * 32 + mt * 16 + g;
                ah[mt][0] = smw[WA_HI + r * RS + kw];
                ah[mt][1] = smw[WA_HI + (r + 8) * RS + kw];
                ah[mt][2] = smw[WA_HI + r * RS + kw + 4];
                ah[mt][3] = smw[WA_HI + (r + 8) * RS + kw + 4];
                al[mt][0] = smw[WA_LO + r * RS + kw];
                al[mt][1] = smw[WA_LO + (r + 8) * RS + kw];
                al[mt][2] = smw[WA_LO + r * RS + kw + 4];
                al[mt][3] = smw[WA_LO + (r + 8) * RS + kw + 4];
            }
            #pragma unroll
            for (int nt = 0; nt < 4; nt++) {
                int n = wn * 32 + nt * 8 + g;
                bh[nt][0] = smw[WB_HI + n * RS + kw];
                bh[nt][1] = smw[WB_HI + n * RS + kw + 4];
                bl[nt][0] = smw[WB_LO + n * RS + kw];
                bl[nt][1] = smw[WB_LO + n * RS + kw + 4];
            }
            #pragma unroll
            for (int mt = 0; mt < 2; mt++)
                #pragma unroll
                for (int nt = 0; nt < 4; nt++) {
                    MMA16816(acc[mt][nt], ah[mt], bh[nt]);
                    MMA16816(acc[mt][nt], ah[mt], bl[nt]);
                    MMA16816(acc[mt][nt], al[mt], bh[nt]);
                }
        }
    }
}

// =====================================================================
// K1: QKV GEMM. grid (64, 24). Epilogue writes split bf16 Q/K/V + times.
// =====================================================================
__global__ __launch_bounds__(256) void qkv_mma(
    const float* __restrict__ bq, const float* __restrict__ bk, const float* __restrict__ bv)
{
    extern __shared__ uint32_t smw[];
    const int tid = threadIdx.x;
    const int wid = tid >> 5, lane = tid & 31;
    const int wm = wid & 3, wn = wid >> 2;
    const int g = lane >> 2, t = lane & 3;
    const int which = blockIdx.y % 3;
    const int h     = blockIdx.y / 3;
    const int slot  = which * 8 + h;
    const int m0    = blockIdx.x * 128;

    {
        const float* bias = (which == 0) ? bq : (which == 1) ? bk : bv;
        if (tid < 64) ((float*)(smw + WBIAS))[tid] = bias[h * 64 + tid];
    }

    float acc[2][4][4];
    #pragma unroll
    for (int mt = 0; mt < 2; mt++)
        #pragma unroll
        for (int nt = 0; nt < 4; nt++)
            #pragma unroll
            for (int i = 0; i < 4; i++) acc[mt][nt][i] = 0.f;

    gemm_mainloop(smw, tid,
                  Xhi + (size_t)m0 * KPAD, Xlo + (size_t)m0 * KPAD,
                  WqkvHi + (size_t)slot * 64 * KPAD, WqkvLo + (size_t)slot * 64 * KPAD,
                  acc);

    const float* biass = (const float*)(smw + WBIAS);
    float* ssP = (float*)(smw + WSSP);

    __syncthreads();
    #pragma unroll
    for (int mt = 0; mt < 2; mt++) {
        #pragma unroll
        for (int half = 0; half < 2; half++) {
            int lrow = wm * 32 + mt * 16 + g + half * 8;
            int row = m0 + lrow;
            int b = row >> 11, n = row & (Nseq - 1);
            size_t rbase = (size_t)(b * 8 + h) * 2048 + n;
            float ss = 0.f;
            #pragma unroll
            for (int nt = 0; nt < 4; nt++) {
                int col0 = wn * 32 + nt * 8 + 2 * t;
                float v0 = acc[mt][nt][half * 2 + 0] + biass[col0];
                float v1 = acc[mt][nt][half * 2 + 1] + biass[col0 + 1];
                ss += v0 * v0 + v1 * v1;
                __nv_bfloat16 h0, l0, h1, l1;
                bsplit(v0, h0, l0); bsplit(v1, h1, l1);
                if (which == 0) {
                    ((uint32_t*)QSh)[rbase * 32 + (col0 >> 1)] = pack2(h0, h1);
                    ((uint32_t*)QSl)[rbase * 32 + (col0 >> 1)] = pack2(l0, l1);
                } else if (which == 1) {
                    ((uint32_t*)KSh)[rbase * 32 + (col0 >> 1)] = pack2(h0, h1);
                    ((uint32_t*)KSl)[rbase * 32 + (col0 >> 1)] = pack2(l0, l1);
                } else {
                    Vh_[rbase * 65 + 1 + col0] = h0;  Vh_[rbase * 65 + 2 + col0] = h1;
                    Vl_[rbase * 65 + 1 + col0] = l0;  Vl_[rbase * 65 + 2 + col0] = l1;
                }
            }
            ss += __shfl_xor_sync(0xffffffffu, ss, 1);
            ss += __shfl_xor_sync(0xffffffffu, ss, 2);
            if (t == 0) ssP[lrow * 2 + wn] = ss;
        }
    }
    __syncthreads();
    if (wn == 0 && t == 0) {
        #pragma unroll
        for (int mt = 0; mt < 2; mt++)
            #pragma unroll
            for (int half = 0; half < 2; half++) {
                int lrow = wm * 32 + mt * 16 + g + half * 8;
                int row = m0 + lrow;
                int b = row >> 11, n = row & (Nseq - 1);
                size_t rbase = (size_t)(b * 8 + h) * 2048 + n;
                float ss = ssP[lrow * 2] + ssP[lrow * 2 + 1];
                float tv = sqrtf(fmaxf(INVK + ss, EPSf));
                if (which == 0) Tqg[rbase] = tv;
                else if (which == 1) Tkg[rbase] = tv;
                else { bsplit(tv, Vh_[rbase * 65], Vl_[rbase * 65]); }
            }
    }
}

// =====================================================================
// V transpose: Vh_/Vl_ [bh][key][65] -> VTh/VTl [bh][72][2048] (pad 0)
// =====================================================================
__global__ __launch_bounds__(128) void vtrans()
{
    __shared__ __nv_bfloat16 sh[64][73];
    __shared__ __nv_bfloat16 sl[64][73];
    const int bh = blockIdx.y, k0 = blockIdx.x * 64, tid = threadIdx.x;
    const __nv_bfloat16 z = __float2bfloat16(0.f);
    for (int i = tid; i < 64 * 72; i += 128) {
        int r = i / 72, d = i % 72;
        sh[r][d] = (d < 65) ? Vh_[((size_t)bh * 2048 + k0 + r) * 65 + d] : z;
        sl[r][d] = (d < 65) ? Vl_[((size_t)bh * 2048 + k0 + r) * 65 + d] : z;
    }
    __syncthreads();
    for (int i = tid; i < 72 * 64; i += 128) {
        int d = i >> 6, k = i & 63;
        VTh[((size_t)bh * 72 + d) * 2048 + k0 + k] = sh[k][d];
        VTl[((size_t)bh * 72 + d) * 2048 + k0 + k] = sl[k][d];
    }
}

// =====================================================================
// K2: tensor-core flash attention. grid (32 qtiles, 32 bh), 128 thr.
// =====================================================================
#define AKH 0
#define AKL 2304
#define AVH 4608
#define AVL 7200
#define ATK 9792
#define AW  9856

__global__ __launch_bounds__(128) void attn_mma()
{
    extern __shared__ uint32_t sw[];
    const int tid = threadIdx.x;
    const int w = tid >> 5, lane = tid & 31;
    const int g = lane >> 2, t = lane & 3;
    const int bh = blockIdx.y;
    const int b = bh >> 3, h = bh & 7;
    const int n0 = blockIdx.x * 64;
    const size_t base = (size_t)bh * 2048;
    float* tks = (float*)(sw + ATK);

    // stage Q tile, extract persistent A-fragments
    {
        const uint4* qh4 = (const uint4*)(QSh + (base + n0) * 64);
        const uint4* ql4 = (const uint4*)(QSl + (base + n0) * 64);
        for (int i = tid; i < 512; i += 128) {
            int r = i >> 3, q = i & 7;
            *(uint4*)(sw + AKH + r * RS + q * 4) = qh4[i];
            *(uint4*)(sw + AKL + r * RS + q * 4) = ql4[i];
        }
    }
    __syncthreads();
    uint32_t qh[4][4], ql[4][4];
    const int r0 = w * 16 + g;
    #pragma unroll
    for (int ks = 0; ks < 4; ks++) {
        int kw = ks * 8 + t;
        qh[ks][0] = sw[AKH + r0 * RS + kw];
        qh[ks][1] = sw[AKH + (r0 + 8) * RS + kw];
        qh[ks][2] = sw[AKH + r0 * RS + kw + 4];
        qh[ks][3] = sw[AKH + (r0 + 8) * RS + kw + 4];
        ql[ks][0] = sw[AKL + r0 * RS + kw];
        ql[ks][1] = sw[AKL + (r0 + 8) * RS + kw];
        ql[ks][2] = sw[AKL + r0 * RS + kw + 4];
        ql[ks][3] = sw[AKL + (r0 + 8) * RS + kw + 4];
    }
    const float tqa = Tqg[base + n0 + r0];
    const float tqb = Tqg[base + n0 + r0 + 8];
    __syncthreads();

    float accO[9][4];
    #pragma unroll
    for (int nd = 0; nd < 9; nd++)
        #pragma unroll
        for (int c = 0; c < 4; c++) accO[nd][c] = 0.f;
    float mA = -1e5f, mB = -1e5f, lA = 0.f, lB = 0.f;

    for (int kt = 0; kt < 32; kt++) {
        // load K tile (64x64 x2) and VT tile (72x64 x2) + Tk
        {
            const uint4* kh4 = (const uint4*)(KSh + (base + kt * 64) * 64);
            const uint4* kl4 = (const uint4*)(KSl + (base + kt * 64) * 64);
            for (int i = tid; i < 512; i += 128) {
                int r = i >> 3, q = i & 7;
                *(uint4*)(sw + AKH + r * RS + q * 4) = kh4[i];
                *(uint4*)(sw + AKL + r * RS + q * 4) = kl4[i];
            }
            const uint4* vh4 = (const uint4*)(VTh + (size_t)bh * 72 * 2048);
            const uint4* vl4 = (const uint4*)(VTl + (size_t)bh * 72 * 2048);
            for (int i = tid; i < 576; i += 128) {
                int d = i >> 3, q = i & 7;
                *(uint4*)(sw + AVH + d * RS + q * 4) = vh4[d * 256 + kt * 8 + q];
                *(uint4*)(sw + AVL + d * RS + q * 4) = vl4[d * 256 + kt * 8 + q];
            }
            if (tid < 64) tks[tid] = Tkg[base + kt * 64 + tid];
        }
        __syncthreads();

        // S = Qs . Ks^T (spatial, bf16x3)
        float sacc[8][4];
        #pragma unroll
        for (int nt = 0; nt < 8; nt++)
            #pragma unroll
            for (int c = 0; c < 4; c++) sacc[nt][c] = 0.f;

        #pragma unroll
        for (int ks = 0; ks < 4; ks++) {
            const int kw = ks * 8 + t;
            #pragma unroll
            for (int nt = 0; nt < 8; nt++) {
                int n = nt * 8 + g;
                uint32_t kb[2], klr[2];
                kb[0]  = sw[AKH + n * RS + kw];
                kb[1]  = sw[AKH + n * RS + kw + 4];
                klr[0] = sw[AKL + n * RS + kw];
                klr[1] = sw[AKL + n * RS + kw + 4];
                MMA16816(sacc[nt], qh[ks], kb);
                MMA16816(sacc[nt], qh[ks], klr);
                MMA16816(sacc[nt], ql[ks], kb);
            }
        }

        // scores with exact fp32 time correction, scaled to log2 domain
        float mxA = -1e30f, mxB = -1e30f;
        #pragma unroll
        for (int nt = 0; nt < 8; nt++) {
            float tk0 = tks[nt * 8 + 2 * t];
            float tk1 = tks[nt * 8 + 2 * t + 1];
            sacc[nt][0] = (sacc[nt][0] - tqa * tk0) * S2f;
            sacc[nt][1] = (sacc[nt][1] - tqa * tk1) * S2f;
            sacc[nt][2] = (sacc[nt][2] - tqb * tk0) * S2f;
            sacc[nt][3] = (sacc[nt][3] - tqb * tk1) * S2f;
            mxA = fmaxf(mxA, fmaxf(sacc[nt][0], sacc[nt][1]));
            mxB = fmaxf(mxB, fmaxf(sacc[nt][2], sacc[nt][3]));
        }
        mxA = fmaxf(mxA, __shfl_xor_sync(0xffffffffu, mxA, 1));
        mxA = fmaxf(mxA, __shfl_xor_sync(0xffffffffu, mxA, 2));
        mxB = fmaxf(mxB, __shfl_xor_sync(0xffffffffu, mxB, 1));
        mxB = fmaxf(mxB, __shfl_xor_sync(0xffffffffu, mxB, 2));
        float mnA = fmaxf(mA, mxA), mnB = fmaxf(mB, mxB);
        float corrA = exp2p(mA - mnA), corrB = exp2p(mB - mnB);
        mA = mnA; mB = mnB;

        float sumA = 0.f, sumB = 0.f;
        #pragma unroll
        for (int nt = 0; nt < 8; nt++) {
            sacc[nt][0] = exp2p(sacc[nt][0] - mA);
            sacc[nt][1] = exp2p(sacc[nt][1] - mA);
            sacc[nt][2] = exp2p(sacc[nt][2] - mB);
            sacc[nt][3] = exp2p(sacc[nt][3] - mB);
            sumA += sacc[nt][0] + sacc[nt][1];
            sumB += sacc[nt][2] + sacc[nt][3];
        }
        sumA += __shfl_xor_sync(0xffffffffu, sumA, 1);
        sumA += __shfl_xor_sync(0xffffffffu, sumA, 2);
        sumB += __shfl_xor_sync(0xffffffffu, sumB, 1);
        sumB += __shfl_xor_sync(0xffffffffu, sumB, 2);
        lA = lA * corrA + sumA;
        lB = lB * corrB + sumB;

        #pragma unroll
        for (int nd = 0; nd < 9; nd++) {
            accO[nd][0] *= corrA;  accO[nd][1] *= corrA;
            accO[nd][2] *= corrB;  accO[nd][3] *= corrB;
        }

        // O += P . V  (P split bf16, V split bf16)
        #pragma unroll
        for (int kb = 0; kb < 4; kb++) {
            float p00 = sacc[2*kb][0],   p01 = sacc[2*kb][1];
            float p02 = sacc[2*kb][2],   p03 = sacc[2*kb][3];
            float p10 = sacc[2*kb+1][0], p11 = sacc[2*kb+1][1];
            float p12 = sacc[2*kb+1][2], p13 = sacc[2*kb+1][3];
            __nv_bfloat16 h00 = __float2bfloat16(p00), h01 = __float2bfloat16(p01);
            __nv_bfloat16 h02 = __float2bfloat16(p02), h03 = __float2bfloat16(p03);
            __nv_bfloat16 h10 = __float2bfloat16(p10), h11 = __float2bfloat16(p11);
            __nv_bfloat16 h12 = __float2bfloat16(p12), h13 = __float2bfloat16(p13);
            uint32_t Ahi[4], Alo[4];
            Ahi[0] = pack2(h00, h01);  Ahi[1] = pack2(h02, h03);
            Ahi[2] = pack2(h10, h11);  Ahi[3] = pack2(h12, h13);
            Alo[0] = pack2(__float2bfloat16(p00 - __bfloat162float(h00)),
                           __float2bfloat16(p01 - __bfloat162float(h01)));
            Alo[1] = pack2(__float2bfloat16(p02 - __bfloat162float(h02)),
                           __float2bfloat16(p03 - __bfloat162float(h03)));
            Alo[2] = pack2(__float2bfloat16(p10 - __bfloat162float(h10)),
                           __float2bfloat16(p11 - __bfloat162float(h11)));
            Alo[3] = pack2(__float2bfloat16(p12 - __bfloat162float(h12)),
                           __float2bfloat16(p13 - __bfloat162float(h13)));
            const int kw = kb * 8 + t;
            #pragma unroll
            for (int nd = 0; nd < 9; nd++) {
                int n = nd * 8 + g;
                uint32_t vb[2], vl[2];
                vb[0] = sw[AVH + n * RS + kw];
                vb[1] = sw[AVH + n * RS + kw + 4];
                vl[0] = sw[AVL + n * RS + kw];
                vl[1] = sw[AVL + n * RS + kw + 4];
                MMA16816(accO[nd], Ahi, vb);
                MMA16816(accO[nd], Alo, vb);
                MMA16816(accO[nd], Ahi, vl);
            }
        }
        __syncthreads();
    }

    // epilogue: normalize, Lorentz midpoint, scatter
    const float linA = 1.f / lA, linB = 1.f / lB;
    float ssA = 0.f, ssB = 0.f;
    #pragma unroll
    for (int nd = 0; nd < 9; nd++) {
        accO[nd][0] *= linA;  accO[nd][1] *= linA;
        accO[nd][2] *= linB;  accO[nd][3] *= linB;
        ssA += accO[nd][0] * accO[nd][0] + accO[nd][1] * accO[nd][1];
        ssB += accO[nd][2] * accO[nd][2] + accO[nd][3] * accO[nd][3];
    }
    ssA += __shfl_xor_sync(0xffffffffu, ssA, 1);
    ssA += __shfl_xor_sync(0xffffffffu, ssA, 2);
    ssB += __shfl_xor_sync(0xffffffffu, ssB, 1);
    ssB += __shfl_xor_sync(0xffffffffu, ssB, 2);
    float tA = __shfl_sync(0xffffffffu, accO[0][0], lane & ~3);
    float tB = __shfl_sync(0xffffffffu, accO[0][2], lane & ~3);
    float spA = ssA - tA * tA;
    float spB = ssB - tB * tB;
    float idnA = rsqrtf(fmaxf(KCURV * (tA * tA - spA), EPSf));
    float idnB = rsqrtf(fmaxf(KCURV * (tB * tB - spB), EPSf));

    const int rowA = b * 2048 + n0 + w * 16 + g;
    const int rowB = rowA + 8;
    #pragma unroll
    for (int nd = 0; nd < 9; nd++) {
        #pragma unroll
        for (int c = 0; c < 2; c++) {
            int d = nd * 8 + 2 * t + c;
            if (d >= 1 && d < 65) {
                OutCat[(size_t)rowA * 512 + h * 64 + d - 1] = accO[nd][c] * idnA;
                OutCat[(size_t)rowB * 512 + h * 64 + d - 1] = accO[nd][c + 2] * idnB;
            }
        }
    }
    if (t == 0) {
        HSS[rowA * 8 + h] = spA * idnA * idnA;
        HSS[rowB * 8 + h] = spB * idnB * idnB;
    }
}

// =====================================================================
// K3: output projection (unchanged from R5)
// =====================================================================
__global__ __launch_bounds__(256) void outproj_mma(
    const float* __restrict__ bo, float* __restrict__ out)
{
    extern __shared__ uint32_t smw[];
    const int tid = threadIdx.x;
    const int wid = tid >> 5, lane = tid & 31;
    const int wm = wid & 3, wn = wid >> 2;
    const int g = lane >> 2, t = lane & 3;
    const int m0 = blockIdx.x * 128;
    const int c0 = blockIdx.y * 64;

    if (tid < 64) ((float*)(smw + WBIAS))[tid] = bo[c0 + tid];

    float acc[2][4][4];
    #pragma unroll
    for (int mt = 0; mt < 2; mt++)
        #pragma unroll
        for (int nt = 0; nt < 4; nt++)
            #pragma unroll
            for (int i = 0; i < 4; i++) acc[mt][nt][i] = 0.f;

    gemm_mainloop(smw, tid,
                  Chi + (size_t)m0 * KPAD, Clo + (size_t)m0 * KPAD,
                  WoTHi + (size_t)c0 * KPAD, WoTLo + (size_t)c0 * KPAD,
                  acc);

    const float* biass = (const float*)(smw + WBIAS);
    float* ssP = (float*)(smw + WSSP);

    __syncthreads();
    #pragma unroll
    for (int mt = 0; mt < 2; mt++) {
        #pragma unroll
        for (int half = 0; half < 2; half++) {
            int lrow = wm * 32 + mt * 16 + g + half * 8;
            int row = m0 + lrow;
            float ss = 0.f;
            #pragma unroll
            for (int nt = 0; nt < 4; nt++) {
                #pragma unroll
                for (int cc = 0; cc < 2; cc++) {
                    int col = wn * 32 + nt * 8 + 2 * t + cc;
                    float v = acc[mt][nt][half * 2 + cc] + biass[col];
                    out[(size_t)row * Dm + 1 + c0 + col] = v;
                    ss += v * v;
                }
            }
            ss += __shfl_xor_sync(0xffffffffu, ss, 1);
            ss += __shfl_xor_sync(0xffffffffu, ss, 2);
            if (t == 0) ssP[lrow * 2 + wn] = ss;
        }
    }
    __syncthreads();
    if (wn == 0 && t == 0) {
        #pragma unroll
        for (int mt = 0; mt < 2; mt++)
            #pragma unroll
            for (int half = 0; half < 2; half++) {
                int lrow = wm * 32 + mt * 16 + g + half * 8;
                int row = m0 + lrow;
                Part2[row * 8 + blockIdx.y] = ssP[lrow * 2] + ssP[lrow * 2 + 1];
            }
    }
}

__global__ void time_kernel(float* __restrict__ out)
{
    int row = blockIdx.x * 256 + threadIdx.x;
    if (row < Mrows) {
        float ss = 0.f;
        #pragma unroll
        for (int j = 0; j < 8; j++) ss += Part2[row * 8 + j];
        out[(size_t)row * Dm] = sqrtf(fmaxf(INVK + ss, EPSf));
    }
}

// =====================================================================
extern "C" void kernel_launch(void* const* d_in, const int* in_sizes, int n_in,
                              void* d_out, int out_size)
{
    const float* x  = (const float*)d_in[0];
    const float* Wq = (const float*)d_in[1];
    const float* bq = (const float*)d_in[2];
    const float* Wk = (const float*)d_in[3];
    const float* bk = (const float*)d_in[4];
    const float* Wv = (const float*)d_in[5];
    const float* bv = (const float*)d_in[6];
    const float* Wo = (const float*)d_in[7];
    const float* bo = (const float*)d_in[8];
    float* out = (float*)d_out;

    const int smem_gemm = WTOT * 4;
    const int smem_attn = AW * 4;
    cudaFuncSetAttribute(qkv_mma, cudaFuncAttributeMaxDynamicSharedMemorySize, smem_gemm);
    cudaFuncSetAttribute(outproj_mma, cudaFuncAttributeMaxDynamicSharedMemorySize, smem_gemm);
    cudaFuncSetAttribute(attn_mma, cudaFuncAttributeMaxDynamicSharedMemorySize, smem_attn);

    cvt_w_kernel<<<1152, 1024>>>(Wq, Wk, Wv, Wo);
    cvt_x_kernel<<<4608, 1024>>>(x);
    qkv_mma<<<dim3(64, 24), 256, smem_gemm>>>(bq, bk, bv);
    vtrans<<<dim3(32, 32), 128>>>();
    attn_mma<<<dim3(32, 32), 128, smem_attn>>>();
    cvt_cat_kernel<<<4608, 1024>>>();
    outproj_mma<<<dim3(64, 8), 256, smem_gemm>>>(bo, out);
    time_kernel<<<32, 256>>>(out);
}

// round 7
// speedup vs baseline: 1.9564x; 1.0860x over previous
#include <cuda_runtime.h>
#include <cuda_bf16.h>
#include <math.h>
#include <stdint.h>

#define Bsz   4
#define Nseq  2048
#define Dm    513
#define Hh    8
#define Mrows 8192
#define KPAD  576
#define INVK  10.0f
#define KCURV 0.1f
#define EPSf  1e-9f
#define S2f   0.18033688011112042f   // 0.125 * log2(e)

// ---------------- device scratch ----------------
__device__ float OutCat[(size_t)Mrows*512];
__device__ float HSS[Mrows*Hh];
__device__ float Part2[Mrows*8];
__device__ __nv_bfloat16 Xhi[(size_t)Mrows*KPAD];
__device__ __nv_bfloat16 Xlo[(size_t)Mrows*KPAD];
__device__ __nv_bfloat16 WqkvHi[24*64*KPAD];
__device__ __nv_bfloat16 WqkvLo[24*64*KPAD];
__device__ __nv_bfloat16 WoTHi[512*KPAD];
__device__ __nv_bfloat16 WoTLo[512*KPAD];
__device__ __nv_bfloat16 Chi[(size_t)Mrows*KPAD];
__device__ __nv_bfloat16 Clo[(size_t)Mrows*KPAD];
__device__ __nv_bfloat16 QSh[(size_t)32*2048*64];
__device__ __nv_bfloat16 QSl[(size_t)32*2048*64];
__device__ __nv_bfloat16 KSh[(size_t)32*2048*64];
__device__ __nv_bfloat16 KSl[(size_t)32*2048*64];
__device__ float Tqg[32*2048];
__device__ float Tkg[32*2048];
__device__ __nv_bfloat16 Vh_[(size_t)32*2048*65];
__device__ __nv_bfloat16 Vl_[(size_t)32*2048*65];
__device__ __nv_bfloat16 VTh[(size_t)32*72*2048];
__device__ __nv_bfloat16 VTl[(size_t)32*72*2048];

__device__ __forceinline__ void bsplit(float v, __nv_bfloat16& h, __nv_bfloat16& l) {
    h = __float2bfloat16(v);
    l = __float2bfloat16(v - __bfloat162float(h));
}
__device__ __forceinline__ uint32_t pack2(__nv_bfloat16 a, __nv_bfloat16 b) {
    __nv_bfloat162 t2; t2.x = a; t2.y = b;
    uint32_t r; memcpy(&r, &t2, 4); return r;
}

__device__ __forceinline__ float exp2p(float y) {
    y = fmaxf(y, -120.f);
    float z = y + 12582912.f;
    int ib = __float_as_int(z);
    float n = z - 12582912.f;
    float f = y - n;
    float p = 1.3333558146e-3f;
    p = fmaf(p, f, 9.6181291076e-3f);
    p = fmaf(p, f, 5.5504108664e-2f);
    p = fmaf(p, f, 2.4022650696e-1f);
    p = fmaf(p, f, 6.9314718056e-1f);
    p = fmaf(p, f, 1.0f);
    float sc = __int_as_float((((ib & 0x7FFFFF) - 0x400000) + 127) << 23);
    return p * sc;
}

#define MMA16816(D, A, B) \
    asm volatile("mma.sync.aligned.m16n8k16.row.col.f32.bf16.bf16.f32 " \
        "{%0,%1,%2,%3}, {%4,%5,%6,%7}, {%8,%9}, {%0,%1,%2,%3};" \
        : "+f"((D)[0]), "+f"((D)[1]), "+f"((D)[2]), "+f"((D)[3]) \
        : "r"((A)[0]), "r"((A)[1]), "r"((A)[2]), "r"((A)[3]), \
          "r"((B)[0]), "r"((B)[1]))

#define CP_ASYNC16(dst, src) \
    asm volatile("cp.async.cg.shared.global [%0], [%1], 16;" :: "r"(dst), "l"(src))
#define CP_COMMIT() asm volatile("cp.async.commit_group;" ::: "memory")
#define CP_WAIT(n)  asm volatile("cp.async.wait_group %0;" :: "n"(n) : "memory")

#define RS 36
#define WA_HI 0
#define WA_LO 4608
#define WB_HI 9216
#define WB_LO 11520
#define WBIAS 13824
#define WSSP  13888
#define WTOT  14144

// =====================================================================
// conversion kernels (unchanged)
// =====================================================================
__global__ void cvt_w_kernel(const float* __restrict__ Wq, const float* __restrict__ Wk,
                             const float* __restrict__ Wv, const float* __restrict__ Wo)
{
    const int total1 = 24 * 64 * KPAD;
    const int total  = total1 + 512 * KPAD;
    for (int idx = blockIdx.x * blockDim.x + threadIdx.x; idx < total;
         idx += gridDim.x * blockDim.x) {
        if (idx < total1) {
            int k = idx % KPAD;
            int t = idx / KPAD;
            int n = t % 64;
            int s = t / 64;
            int which = s >> 3, h = s & 7;
            const float* W = (which == 0) ? Wq : (which == 1) ? Wk : Wv;
            float v = (k < Dm) ? W[((size_t)h * Dm + k) * 64 + n] : 0.f;
            bsplit(v, WqkvHi[idx], WqkvLo[idx]);
        } else {
            int i2 = idx - total1;
            int k = i2 % KPAD;
            int n = i2 / KPAD;
            float v = (k < Dm) ? Wo[(size_t)k * 512 + n] : 0.f;
            bsplit(v, WoTHi[i2], WoTLo[i2]);
        }
    }
}

__global__ void cvt_x_kernel(const float* __restrict__ x)
{
    const size_t total = (size_t)Mrows * KPAD;
    for (size_t idx = (size_t)blockIdx.x * blockDim.x + threadIdx.x; idx < total;
         idx += (size_t)gridDim.x * blockDim.x) {
        int k = (int)(idx % KPAD);
        size_t row = idx / KPAD;
        float v = (k < Dm) ? x[row * Dm + k] : 0.f;
        bsplit(v, Xhi[idx], Xlo[idx]);
    }
}

__global__ void cvt_cat_kernel()
{
    const size_t total = (size_t)Mrows * KPAD;
    for (size_t idx = (size_t)blockIdx.x * blockDim.x + threadIdx.x; idx < total;
         idx += (size_t)gridDim.x * blockDim.x) {
        int k = (int)(idx % KPAD);
        size_t row = idx / KPAD;
        float v;
        if (k == 0) {
            float ss = 0.f;
            #pragma unroll
            for (int hh = 0; hh < 8; hh++) ss += HSS[row * 8 + hh];
            v = sqrtf(fmaxf(INVK + ss, EPSf));
        } else if (k < Dm) {
            v = OutCat[row * 512 + k - 1];
        } else v = 0.f;
        bsplit(v, Chi[idx], Clo[idx]);
    }
}

// =====================================================================
// GEMM mainloop (unchanged, working)
// =====================================================================
__device__ __forceinline__ void copyA(uint32_t* smw, int dst_w,
                                      const __nv_bfloat16* __restrict__ src, int tid)
{
    for (int i = tid; i < 1024; i += 256) {
        int r = i >> 3, q = i & 7;
        uint4 v = *(const uint4*)(src + (size_t)r * KPAD + q * 8);
        *(uint4*)(smw + dst_w + r * RS + q * 4) = v;
    }
}
__device__ __forceinline__ void copyB(uint32_t* smw, int dst_w,
                                      const __nv_bfloat16* __restrict__ src, int tid)
{
    for (int i = tid; i < 512; i += 256) {
        int r = i >> 3, q = i & 7;
        uint4 v = *(const uint4*)(src + (size_t)r * KPAD + q * 8);
        *(uint4*)(smw + dst_w + r * RS + q * 4) = v;
    }
}

__device__ __forceinline__ void gemm_mainloop(
    uint32_t* smw, int tid,
    const __nv_bfloat16* Ah, const __nv_bfloat16* Al,
    const __nv_bfloat16* Bh, const __nv_bfloat16* Bl,
    float acc[2][4][4])
{
    const int wid = tid >> 5, lane = tid & 31;
    const int wm = wid & 3, wn = wid >> 2;
    const int g = lane >> 2, t = lane & 3;

    for (int c = 0; c < 9; c++) {
        const int k0 = c * 64;
        __syncthreads();
        copyA(smw, WA_HI, Ah + k0, tid);
        copyA(smw, WA_LO, Al + k0, tid);
        copyB(smw, WB_HI, Bh + k0, tid);
        copyB(smw, WB_LO, Bl + k0, tid);
        __syncthreads();

        #pragma unroll
        for (int ks = 0; ks < 4; ks++) {
            uint32_t ah[2][4], al[2][4], bh[4][2], bl[4][2];
            const int kw = ks * 8 + t;
            #pragma unroll
            for (int mt = 0; mt < 2; mt++) {
                int r = wm * 32 + mt * 16 + g;
                ah[mt][0] = smw[WA_HI + r * RS + kw];
                ah[mt][1] = smw[WA_HI + (r + 8) * RS + kw];
                ah[mt][2] = smw[WA_HI + r * RS + kw + 4];
                ah[mt][3] = smw[WA_HI + (r + 8) * RS + kw + 4];
                al[mt][0] = smw[WA_LO + r * RS + kw];
                al[mt][1] = smw[WA_LO + (r + 8) * RS + kw];
                al[mt][2] = smw[WA_LO + r * RS + kw + 4];
                al[mt][3] = smw[WA_LO + (r + 8) * RS + kw + 4];
            }
            #pragma unroll
            for (int nt = 0; nt < 4; nt++) {
                int n = wn * 32 + nt * 8 + g;
                bh[nt][0] = smw[WB_HI + n * RS + kw];
                bh[nt][1] = smw[WB_HI + n * RS + kw + 4];
                bl[nt][0] = smw[WB_LO + n * RS + kw];
                bl[nt][1] = smw[WB_LO + n * RS + kw + 4];
            }
            #pragma unroll
            for (int mt = 0; mt < 2; mt++)
                #pragma unroll
                for (int nt = 0; nt < 4; nt++) {
                    MMA16816(acc[mt][nt], ah[mt], bh[nt]);
                    MMA16816(acc[mt][nt], ah[mt], bl[nt]);
                    MMA16816(acc[mt][nt], al[mt], bh[nt]);
                }
        }
    }
}

// =====================================================================
// K1: QKV GEMM (unchanged from R6)
// =====================================================================
__global__ __launch_bounds__(256) void qkv_mma(
    const float* __restrict__ bq, const float* __restrict__ bk, const float* __restrict__ bv)
{
    extern __shared__ uint32_t smw[];
    const int tid = threadIdx.x;
    const int wid = tid >> 5, lane = tid & 31;
    const int wm = wid & 3, wn = wid >> 2;
    const int g = lane >> 2, t = lane & 3;
    const int which = blockIdx.y % 3;
    const int h     = blockIdx.y / 3;
    const int slot  = which * 8 + h;
    const int m0    = blockIdx.x * 128;

    {
        const float* bias = (which == 0) ? bq : (which == 1) ? bk : bv;
        if (tid < 64) ((float*)(smw + WBIAS))[tid] = bias[h * 64 + tid];
    }

    float acc[2][4][4];
    #pragma unroll
    for (int mt = 0; mt < 2; mt++)
        #pragma unroll
        for (int nt = 0; nt < 4; nt++)
            #pragma unroll
            for (int i = 0; i < 4; i++) acc[mt][nt][i] = 0.f;

    gemm_mainloop(smw, tid,
                  Xhi + (size_t)m0 * KPAD, Xlo + (size_t)m0 * KPAD,
                  WqkvHi + (size_t)slot * 64 * KPAD, WqkvLo + (size_t)slot * 64 * KPAD,
                  acc);

    const float* biass = (const float*)(smw + WBIAS);
    float* ssP = (float*)(smw + WSSP);

    __syncthreads();
    #pragma unroll
    for (int mt = 0; mt < 2; mt++) {
        #pragma unroll
        for (int half = 0; half < 2; half++) {
            int lrow = wm * 32 + mt * 16 + g + half * 8;
            int row = m0 + lrow;
            int b = row >> 11, n = row & (Nseq - 1);
            size_t rbase = (size_t)(b * 8 + h) * 2048 + n;
            float ss = 0.f;
            #pragma unroll
            for (int nt = 0; nt < 4; nt++) {
                int col0 = wn * 32 + nt * 8 + 2 * t;
                float v0 = acc[mt][nt][half * 2 + 0] + biass[col0];
                float v1 = acc[mt][nt][half * 2 + 1] + biass[col0 + 1];
                ss += v0 * v0 + v1 * v1;
                __nv_bfloat16 h0, l0, h1, l1;
                bsplit(v0, h0, l0); bsplit(v1, h1, l1);
                if (which == 0) {
                    ((uint32_t*)QSh)[rbase * 32 + (col0 >> 1)] = pack2(h0, h1);
                    ((uint32_t*)QSl)[rbase * 32 + (col0 >> 1)] = pack2(l0, l1);
                } else if (which == 1) {
                    ((uint32_t*)KSh)[rbase * 32 + (col0 >> 1)] = pack2(h0, h1);
                    ((uint32_t*)KSl)[rbase * 32 + (col0 >> 1)] = pack2(l0, l1);
                } else {
                    Vh_[rbase * 65 + 1 + col0] = h0;  Vh_[rbase * 65 + 2 + col0] = h1;
                    Vl_[rbase * 65 + 1 + col0] = l0;  Vl_[rbase * 65 + 2 + col0] = l1;
                }
            }
            ss += __shfl_xor_sync(0xffffffffu, ss, 1);
            ss += __shfl_xor_sync(0xffffffffu, ss, 2);
            if (t == 0) ssP[lrow * 2 + wn] = ss;
        }
    }
    __syncthreads();
    if (wn == 0 && t == 0) {
        #pragma unroll
        for (int mt = 0; mt < 2; mt++)
            #pragma unroll
            for (int half = 0; half < 2; half++) {
                int lrow = wm * 32 + mt * 16 + g + half * 8;
                int row = m0 + lrow;
                int b = row >> 11, n = row & (Nseq - 1);
                size_t rbase = (size_t)(b * 8 + h) * 2048 + n;
                float ss = ssP[lrow * 2] + ssP[lrow * 2 + 1];
                float tv = sqrtf(fmaxf(INVK + ss, EPSf));
                if (which == 0) Tqg[rbase] = tv;
                else if (which == 1) Tkg[rbase] = tv;
                else { bsplit(tv, Vh_[rbase * 65], Vl_[rbase * 65]); }
            }
    }
}

// =====================================================================
// V transpose (unchanged)
// =====================================================================
__global__ __launch_bounds__(128) void vtrans()
{
    __shared__ __nv_bfloat16 sh[64][73];
    __shared__ __nv_bfloat16 sl[64][73];
    const int bh = blockIdx.y, k0 = blockIdx.x * 64, tid = threadIdx.x;
    const __nv_bfloat16 z = __float2bfloat16(0.f);
    for (int i = tid; i < 64 * 72; i += 128) {
        int r = i / 72, d = i % 72;
        sh[r][d] = (d < 65) ? Vh_[((size_t)bh * 2048 + k0 + r) * 65 + d] : z;
        sl[r][d] = (d < 65) ? Vl_[((size_t)bh * 2048 + k0 + r) * 65 + d] : z;
    }
    __syncthreads();
    for (int i = tid; i < 72 * 64; i += 128) {
        int d = i >> 6, k = i & 63;
        VTh[((size_t)bh * 72 + d) * 2048 + k0 + k] = sh[k][d];
        VTl[((size_t)bh * 72 + d) * 2048 + k0 + k] = sl[k][d];
    }
}

// =====================================================================
// K2: pipelined tensor-core flash attention.
// grid (16 qtiles, 32 bh), 256 threads, double-buffered cp.async.
// Buffer layout (words): KH=0 KL=2304 VH=4608 VL=7200 TK=9792, size 9856.
// =====================================================================
#define ABUF 9856

__device__ __forceinline__ void attn_issue_tile(
    uint32_t smb, int bufw, int kt, int tid, int bh, size_t base)
{
    const int k0 = kt * 64;
    for (int i = tid; i < 2192; i += 256) {
        uint32_t dstw; const void* src;
        if (i < 512) {
            int r = i >> 3, q = i & 7;
            dstw = bufw + r * RS + q * 4;
            src = KSh + (base + k0 + r) * 64 + q * 8;
        } else if (i < 1024) {
            int j = i - 512, r = j >> 3, q = j & 7;
            dstw = bufw + 2304 + r * RS + q * 4;
            src = KSl + (base + k0 + r) * 64 + q * 8;
        } else if (i < 1600) {
            int j = i - 1024, d = j >> 3, q = j & 7;
            dstw = bufw + 4608 + d * RS + q * 4;
            src = VTh + ((size_t)bh * 72 + d) * 2048 + k0 + q * 8;
        } else if (i < 2176) {
            int j = i - 1600, d = j >> 3, q = j & 7;
            dstw = bufw + 7200 + d * RS + q * 4;
            src = VTl + ((size_t)bh * 72 + d) * 2048 + k0 + q * 8;
        } else {
            int j = i - 2176;
            dstw = bufw + 9792 + j * 4;
            src = Tkg + base + k0 + j * 4;
        }
        CP_ASYNC16(smb + dstw * 4, src);
    }
}

__global__ __launch_bounds__(256) void attn_mma()
{
    extern __shared__ uint32_t sw[];
    const int tid = threadIdx.x;
    const int w = tid >> 5, lane = tid & 31;
    const int g = lane >> 2, t = lane & 3;
    const int bh = blockIdx.y;
    const int b = bh >> 3, h = bh & 7;
    const int n0 = blockIdx.x * 128;
    const size_t base = (size_t)bh * 2048;
    uint32_t smb;
    asm("{ .reg .u64 tt; cvta.to.shared.u64 tt, %1; cvt.u32.u64 %0, tt; }"
        : "=r"(smb) : "l"(sw));

    // prefetch tile 0 into buffer 0
    attn_issue_tile(smb, 0, 0, tid, bh, base);
    CP_COMMIT();

    // stage Q (128 rows, hi+lo) into buffer 1 region, extract fragments
    {
        const uint4* qh4 = (const uint4*)(QSh + (base + n0) * 64);
        const uint4* ql4 = (const uint4*)(QSl + (base + n0) * 64);
        for (int i = tid; i < 1024; i += 256) {
            int r = i >> 3, q = i & 7;
            *(uint4*)(sw + ABUF + r * RS + q * 4) = qh4[i];
            *(uint4*)(sw + ABUF + 4608 + r * RS + q * 4) = ql4[i];
        }
    }
    __syncthreads();
    uint32_t qh[4][4], ql[4][4];
    const int r0 = w * 16 + g;
    #pragma unroll
    for (int ks = 0; ks < 4; ks++) {
        int kw = ks * 8 + t;
        qh[ks][0] = sw[ABUF + r0 * RS + kw];
        qh[ks][1] = sw[ABUF + (r0 + 8) * RS + kw];
        qh[ks][2] = sw[ABUF + r0 * RS + kw + 4];
        qh[ks][3] = sw[ABUF + (r0 + 8) * RS + kw + 4];
        ql[ks][0] = sw[ABUF + 4608 + r0 * RS + kw];
        ql[ks][1] = sw[ABUF + 4608 + (r0 + 8) * RS + kw];
        ql[ks][2] = sw[ABUF + 4608 + r0 * RS + kw + 4];
        ql[ks][3] = sw[ABUF + 4608 + (r0 + 8) * RS + kw + 4];
    }
    const float tqa = Tqg[base + n0 + r0];
    const float tqb = Tqg[base + n0 + r0 + 8];
    __syncthreads();   // Q frags extracted; buffer 1 free for prefetch

    float accO[9][4];
    #pragma unroll
    for (int nd = 0; nd < 9; nd++)
        #pragma unroll
        for (int c = 0; c < 4; c++) accO[nd][c] = 0.f;
    float mA = -1e5f, mB = -1e5f, lA = 0.f, lB = 0.f;

    for (int kt = 0; kt < 32; kt++) {
        const int cur = (kt & 1) * ABUF;
        if (kt < 31) {
            attn_issue_tile(smb, ((kt + 1) & 1) * ABUF, kt + 1, tid, bh, base);
            CP_COMMIT();
            CP_WAIT(1);
        } else {
            CP_WAIT(0);
        }
        __syncthreads();

        const float* tks = (const float*)(sw + cur + 9792);

        // S = Qs . Ks^T (bf16x3)
        float sacc[8][4];
        #pragma unroll
        for (int nt = 0; nt < 8; nt++)
            #pragma unroll
            for (int c = 0; c < 4; c++) sacc[nt][c] = 0.f;

        #pragma unroll
        for (int ks = 0; ks < 4; ks++) {
            const int kw = ks * 8 + t;
            #pragma unroll
            for (int nt = 0; nt < 8; nt++) {
                int n = nt * 8 + g;
                uint32_t kb[2], klr[2];
                kb[0]  = sw[cur + n * RS + kw];
                kb[1]  = sw[cur + n * RS + kw + 4];
                klr[0] = sw[cur + 2304 + n * RS + kw];
                klr[1] = sw[cur + 2304 + n * RS + kw + 4];
                MMA16816(sacc[nt], qh[ks], kb);
                MMA16816(sacc[nt], qh[ks], klr);
                MMA16816(sacc[nt], ql[ks], kb);
            }
        }

        // scores + online softmax (fp32-exact time correction)
        float mxA = -1e30f, mxB = -1e30f;
        #pragma unroll
        for (int nt = 0; nt < 8; nt++) {
            float tk0 = tks[nt * 8 + 2 * t];
            float tk1 = tks[nt * 8 + 2 * t + 1];
            sacc[nt][0] = (sacc[nt][0] - tqa * tk0) * S2f;
            sacc[nt][1] = (sacc[nt][1] - tqa * tk1) * S2f;
            sacc[nt][2] = (sacc[nt][2] - tqb * tk0) * S2f;
            sacc[nt][3] = (sacc[nt][3] - tqb * tk1) * S2f;
            mxA = fmaxf(mxA, fmaxf(sacc[nt][0], sacc[nt][1]));
            mxB = fmaxf(mxB, fmaxf(sacc[nt][2], sacc[nt][3]));
        }
        mxA = fmaxf(mxA, __shfl_xor_sync(0xffffffffu, mxA, 1));
        mxA = fmaxf(mxA, __shfl_xor_sync(0xffffffffu, mxA, 2));
        mxB = fmaxf(mxB, __shfl_xor_sync(0xffffffffu, mxB, 1));
        mxB = fmaxf(mxB, __shfl_xor_sync(0xffffffffu, mxB, 2));
        float mnA = fmaxf(mA, mxA), mnB = fmaxf(mB, mxB);
        float corrA = exp2p(mA - mnA), corrB = exp2p(mB - mnB);
        mA = mnA; mB = mnB;

        float sumA = 0.f, sumB = 0.f;
        #pragma unroll
        for (int nt = 0; nt < 8; nt++) {
            sacc[nt][0] = exp2p(sacc[nt][0] - mA);
            sacc[nt][1] = exp2p(sacc[nt][1] - mA);
            sacc[nt][2] = exp2p(sacc[nt][2] - mB);
            sacc[nt][3] = exp2p(sacc[nt][3] - mB);
            sumA += sacc[nt][0] + sacc[nt][1];
            sumB += sacc[nt][2] + sacc[nt][3];
        }
        sumA += __shfl_xor_sync(0xffffffffu, sumA, 1);
        sumA += __shfl_xor_sync(0xffffffffu, sumA, 2);
        sumB += __shfl_xor_sync(0xffffffffu, sumB, 1);
        sumB += __shfl_xor_sync(0xffffffffu, sumB, 2);
        lA = lA * corrA + sumA;
        lB = lB * corrB + sumB;

        #pragma unroll
        for (int nd = 0; nd < 9; nd++) {
            accO[nd][0] *= corrA;  accO[nd][1] *= corrA;
            accO[nd][2] *= corrB;  accO[nd][3] *= corrB;
        }

        // O += P . V  (split P, split V)
        #pragma unroll
        for (int kb = 0; kb < 4; kb++) {
            float p00 = sacc[2*kb][0],   p01 = sacc[2*kb][1];
            float p02 = sacc[2*kb][2],   p03 = sacc[2*kb][3];
            float p10 = sacc[2*kb+1][0], p11 = sacc[2*kb+1][1];
            float p12 = sacc[2*kb+1][2], p13 = sacc[2*kb+1][3];
            __nv_bfloat16 h00 = __float2bfloat16(p00), h01 = __float2bfloat16(p01);
            __nv_bfloat16 h02 = __float2bfloat16(p02), h03 = __float2bfloat16(p03);
            __nv_bfloat16 h10 = __float2bfloat16(p10), h11 = __float2bfloat16(p11);
            __nv_bfloat16 h12 = __float2bfloat16(p12), h13 = __float2bfloat16(p13);
            uint32_t Ahi[4], Alo[4];
            Ahi[0] = pack2(h00, h01);  Ahi[1] = pack2(h02, h03);
            Ahi[2] = pack2(h10, h11);  Ahi[3] = pack2(h12, h13);
            Alo[0] = pack2(__float2bfloat16(p00 - __bfloat162float(h00)),
                           __float2bfloat16(p01 - __bfloat162float(h01)));
            Alo[1] = pack2(__float2bfloat16(p02 - __bfloat162float(h02)),
                           __float2bfloat16(p03 - __bfloat162float(h03)));
            Alo[2] = pack2(__float2bfloat16(p10 - __bfloat162float(h10)),
                           __float2bfloat16(p11 - __bfloat162float(h11)));
            Alo[3] = pack2(__float2bfloat16(p12 - __bfloat162float(h12)),
                           __float2bfloat16(p13 - __bfloat162float(h13)));
            const int kw = kb * 8 + t;
            #pragma unroll
            for (int nd = 0; nd < 9; nd++) {
                int n = nd * 8 + g;
                uint32_t vb[2], vl[2];
                vb[0] = sw[cur + 4608 + n * RS + kw];
                vb[1] = sw[cur + 4608 + n * RS + kw + 4];
                vl[0] = sw[cur + 7200 + n * RS + kw];
                vl[1] = sw[cur + 7200 + n * RS + kw + 4];
                MMA16816(accO[nd], Ahi, vb);
                MMA16816(accO[nd], Alo, vb);
                MMA16816(accO[nd], Ahi, vl);
            }
        }
        __syncthreads();
    }

    // epilogue
    const float linA = 1.f / lA, linB = 1.f / lB;
    float ssA = 0.f, ssB = 0.f;
    #pragma unroll
    for (int nd = 0; nd < 9; nd++) {
        accO[nd][0] *= linA;  accO[nd][1] *= linA;
        accO[nd][2] *= linB;  accO[nd][3] *= linB;
        ssA += accO[nd][0] * accO[nd][0] + accO[nd][1] * accO[nd][1];
        ssB += accO[nd][2] * accO[nd][2] + accO[nd][3] * accO[nd][3];
    }
    ssA += __shfl_xor_sync(0xffffffffu, ssA, 1);
    ssA += __shfl_xor_sync(0xffffffffu, ssA, 2);
    ssB += __shfl_xor_sync(0xffffffffu, ssB, 1);
    ssB += __shfl_xor_sync(0xffffffffu, ssB, 2);
    float tA = __shfl_sync(0xffffffffu, accO[0][0], lane & ~3);
    float tB = __shfl_sync(0xffffffffu, accO[0][2], lane & ~3);
    float spA = ssA - tA * tA;
    float spB = ssB - tB * tB;
    float idnA = rsqrtf(fmaxf(KCURV * (tA * tA - spA), EPSf));
    float idnB = rsqrtf(fmaxf(KCURV * (tB * tB - spB), EPSf));

    const int rowA = b * 2048 + n0 + w * 16 + g;
    const int rowB = rowA + 8;
    #pragma unroll
    for (int nd = 0; nd < 9; nd++) {
        #pragma unroll
        for (int c = 0; c < 2; c++) {
            int d = nd * 8 + 2 * t + c;
            if (d >= 1 && d < 65) {
                OutCat[(size_t)rowA * 512 + h * 64 + d - 1] = accO[nd][c] * idnA;
                OutCat[(size_t)rowB * 512 + h * 64 + d - 1] = accO[nd][c + 2] * idnB;
            }
        }
    }
    if (t == 0) {
        HSS[rowA * 8 + h] = spA * idnA * idnA;
        HSS[rowB * 8 + h] = spB * idnB * idnB;
    }
}

// =====================================================================
// K3: output projection (unchanged)
// =====================================================================
__global__ __launch_bounds__(256) void outproj_mma(
    const float* __restrict__ bo, float* __restrict__ out)
{
    extern __shared__ uint32_t smw[];
    const int tid = threadIdx.x;
    const int wid = tid >> 5, lane = tid & 31;
    const int wm = wid & 3, wn = wid >> 2;
    const int g = lane >> 2, t = lane & 3;
    const int m0 = blockIdx.x * 128;
    const int c0 = blockIdx.y * 64;

    if (tid < 64) ((float*)(smw + WBIAS))[tid] = bo[c0 + tid];

    float acc[2][4][4];
    #pragma unroll
    for (int mt = 0; mt < 2; mt++)
        #pragma unroll
        for (int nt = 0; nt < 4; nt++)
            #pragma unroll
            for (int i = 0; i < 4; i++) acc[mt][nt][i] = 0.f;

    gemm_mainloop(smw, tid,
                  Chi + (size_t)m0 * KPAD, Clo + (size_t)m0 * KPAD,
                  WoTHi + (size_t)c0 * KPAD, WoTLo + (size_t)c0 * KPAD,
                  acc);

    const float* biass = (const float*)(smw + WBIAS);
    float* ssP = (float*)(smw + WSSP);

    __syncthreads();
    #pragma unroll
    for (int mt = 0; mt < 2; mt++) {
        #pragma unroll
        for (int half = 0; half < 2; half++) {
            int lrow = wm * 32 + mt * 16 + g + half * 8;
            int row = m0 + lrow;
            float ss = 0.f;
            #pragma unroll
            for (int nt = 0; nt < 4; nt++) {
                #pragma unroll
                for (int cc = 0; cc < 2; cc++) {
                    int col = wn * 32 + nt * 8 + 2 * t + cc;
                    float v = acc[mt][nt][half * 2 + cc] + biass[col];
                    out[(size_t)row * Dm + 1 + c0 + col] = v;
                    ss += v * v;
                }
            }
            ss += __shfl_xor_sync(0xffffffffu, ss, 1);
            ss += __shfl_xor_sync(0xffffffffu, ss, 2);
            if (t == 0) ssP[lrow * 2 + wn] = ss;
        }
    }
    __syncthreads();
    if (wn == 0 && t == 0) {
        #pragma unroll
        for (int mt = 0; mt < 2; mt++)
            #pragma unroll
            for (int half = 0; half < 2; half++) {
                int lrow = wm * 32 + mt * 16 + g + half * 8;
                int row = m0 + lrow;
                Part2[row * 8 + blockIdx.y] = ssP[lrow * 2] + ssP[lrow * 2 + 1];
            }
    }
}

__global__ void time_kernel(float* __restrict__ out)
{
    int row = blockIdx.x * 256 + threadIdx.x;
    if (row < Mrows) {
        float ss = 0.f;
        #pragma unroll
        for (int j = 0; j < 8; j++) ss += Part2[row * 8 + j];
        out[(size_t)row * Dm] = sqrtf(fmaxf(INVK + ss, EPSf));
    }
}

// =====================================================================
extern "C" void kernel_launch(void* const* d_in, const int* in_sizes, int n_in,
                              void* d_out, int out_size)
{
    const float* x  = (const float*)d_in[0];
    const float* Wq = (const float*)d_in[1];
    const float* bq = (const float*)d_in[2];
    const float* Wk = (const float*)d_in[3];
    const float* bk = (const float*)d_in[4];
    const float* Wv = (const float*)d_in[5];
    const float* bv = (const float*)d_in[6];
    const float* Wo = (const float*)d_in[7];
    const float* bo = (const float*)d_in[8];
    float* out = (float*)d_out;

    const int smem_gemm = WTOT * 4;
    const int smem_attn = 2 * ABUF * 4;      // 78848 bytes
    cudaFuncSetAttribute(qkv_mma, cudaFuncAttributeMaxDynamicSharedMemorySize, smem_gemm);
    cudaFuncSetAttribute(outproj_mma, cudaFuncAttributeMaxDynamicSharedMemorySize, smem_gemm);
    cudaFuncSetAttribute(attn_mma, cudaFuncAttributeMaxDynamicSharedMemorySize, smem_attn);

    cvt_w_kernel<<<1152, 1024>>>(Wq, Wk, Wv, Wo);
    cvt_x_kernel<<<4608, 1024>>>(x);
    qkv_mma<<<dim3(64, 24), 256, smem_gemm>>>(bq, bk, bv);
    vtrans<<<dim3(32, 32), 128>>>();
    attn_mma<<<dim3(16, 32), 256, smem_attn>>>();
    cvt_cat_kernel<<<4608, 1024>>>();
    outproj_mma<<<dim3(64, 8), 256, smem_gemm>>>(bo, out);
    time_kernel<<<32, 256>>>(out);
}

// round 9
// speedup vs baseline: 2.2696x; 1.1601x over previous
#include <cuda_runtime.h>
#include <cuda_bf16.h>
#include <math.h>
#include <stdint.h>

#define Bsz   4
#define Nseq  2048
#define Dm    513
#define Hh    8
#define Mrows 8192
#define KPAD  576
#define INVK  10.0f
#define KCURV 0.1f
#define EPSf  1e-9f
#define S2f   0.18033688011112042f   // 0.125 * log2(e)

// ---------------- device scratch ----------------
__device__ float OutCat[(size_t)Mrows*512];
__device__ float HSS[Mrows*Hh];
__device__ float Part2[Mrows*8];
__device__ __nv_bfloat16 Xhi[(size_t)Mrows*KPAD];
__device__ __nv_bfloat16 Xlo[(size_t)Mrows*KPAD];
__device__ __nv_bfloat16 WqkvHi[24*64*KPAD];
__device__ __nv_bfloat16 WqkvLo[24*64*KPAD];
__device__ __nv_bfloat16 WoTHi[512*KPAD];
__device__ __nv_bfloat16 WoTLo[512*KPAD];
__device__ __nv_bfloat16 Chi[(size_t)Mrows*KPAD];
__device__ __nv_bfloat16 Clo[(size_t)Mrows*KPAD];
__device__ __nv_bfloat16 QSh[(size_t)32*2048*64];
__device__ __nv_bfloat16 QSl[(size_t)32*2048*64];
__device__ __nv_bfloat16 KSh[(size_t)32*2048*64];
__device__ __nv_bfloat16 KSl[(size_t)32*2048*64];
__device__ float Tqg[32*2048];
__device__ float Tkg[32*2048];
__device__ __nv_bfloat16 Vh_[(size_t)32*2048*65];
__device__ __nv_bfloat16 Vl_[(size_t)32*2048*65];
__device__ __nv_bfloat16 VTh[(size_t)32*72*2048];
__device__ __nv_bfloat16 VTl[(size_t)32*72*2048];

__device__ __forceinline__ void bsplit(float v, __nv_bfloat16& h, __nv_bfloat16& l) {
    h = __float2bfloat16(v);
    l = __float2bfloat16(v - __bfloat162float(h));
}
__device__ __forceinline__ uint32_t pack2(__nv_bfloat16 a, __nv_bfloat16 b) {
    __nv_bfloat162 t2; t2.x = a; t2.y = b;
    uint32_t r; memcpy(&r, &t2, 4); return r;
}

__device__ __forceinline__ float exp2p(float y) {
    y = fmaxf(y, -120.f);
    float z = y + 12582912.f;
    int ib = __float_as_int(z);
    float n = z - 12582912.f;
    float f = y - n;
    float p = 1.3333558146e-3f;
    p = fmaf(p, f, 9.6181291076e-3f);
    p = fmaf(p, f, 5.5504108664e-2f);
    p = fmaf(p, f, 2.4022650696e-1f);
    p = fmaf(p, f, 6.9314718056e-1f);
    p = fmaf(p, f, 1.0f);
    float sc = __int_as_float((((ib & 0x7FFFFF) - 0x400000) + 127) << 23);
    return p * sc;
}

#define MMA16816(D, A, B) \
    asm volatile("mma.sync.aligned.m16n8k16.row.col.f32.bf16.bf16.f32 " \
        "{%0,%1,%2,%3}, {%4,%5,%6,%7}, {%8,%9}, {%0,%1,%2,%3};" \
        : "+f"((D)[0]), "+f"((D)[1]), "+f"((D)[2]), "+f"((D)[3]) \
        : "r"((A)[0]), "r"((A)[1]), "r"((A)[2]), "r"((A)[3]), \
          "r"((B)[0]), "r"((B)[1]))

#define CP_ASYNC16(dst, src) \
    asm volatile("cp.async.cg.shared.global [%0], [%1], 16;" :: "r"(dst), "l"(src))
#define CP_COMMIT() asm volatile("cp.async.commit_group;" ::: "memory")
#define CP_WAIT(n)  asm volatile("cp.async.wait_group %0;" :: "n"(n) : "memory")

#define RS 36
#define WA_HI 0
#define WA_LO 4608
#define WB_HI 9216
#define WB_LO 11520
#define WBIAS 13824
#define WSSP  13888
#define WTOT  14144

// =====================================================================
// merged input conversion: W splits + X splits in one launch
// =====================================================================
__global__ void cvt_in_kernel(const float* __restrict__ Wq, const float* __restrict__ Wk,
                              const float* __restrict__ Wv, const float* __restrict__ Wo,
                              const float* __restrict__ x)
{
    const int totW1 = 24 * 64 * KPAD;
    const int totW  = totW1 + 512 * KPAD;
    const size_t totX = (size_t)Mrows * KPAD;
    const size_t total = totW + totX;
    for (size_t idx = (size_t)blockIdx.x * blockDim.x + threadIdx.x; idx < total;
         idx += (size_t)gridDim.x * blockDim.x) {
        if (idx < (size_t)totW1) {
            int i = (int)idx;
            int k = i % KPAD;
            int t = i / KPAD;
            int n = t % 64;
            int s = t / 64;
            int which = s >> 3, h = s & 7;
            const float* W = (which == 0) ? Wq : (which == 1) ? Wk : Wv;
            float v = (k < Dm) ? W[((size_t)h * Dm + k) * 64 + n] : 0.f;
            bsplit(v, WqkvHi[i], WqkvLo[i]);
        } else if (idx < (size_t)totW) {
            int i2 = (int)idx - totW1;
            int k = i2 % KPAD;
            int n = i2 / KPAD;
            float v = (k < Dm) ? Wo[(size_t)k * 512 + n] : 0.f;
            bsplit(v, WoTHi[i2], WoTLo[i2]);
        } else {
            size_t i3 = idx - totW;
            int k = (int)(i3 % KPAD);
            size_t row = i3 / KPAD;
            float v = (k < Dm) ? x[row * Dm + k] : 0.f;
            bsplit(v, Xhi[i3], Xlo[i3]);
        }
    }
}

__global__ void cvt_cat_kernel()
{
    const size_t total = (size_t)Mrows * KPAD;
    for (size_t idx = (size_t)blockIdx.x * blockDim.x + threadIdx.x; idx < total;
         idx += (size_t)gridDim.x * blockDim.x) {
        int k = (int)(idx % KPAD);
        size_t row = idx / KPAD;
        float v;
        if (k == 0) {
            float ss = 0.f;
            #pragma unroll
            for (int hh = 0; hh < 8; hh++) ss += HSS[row * 8 + hh];
            v = sqrtf(fmaxf(INVK + ss, EPSf));
        } else if (k < Dm) {
            v = OutCat[row * 512 + k - 1];
        } else v = 0.f;
        bsplit(v, Chi[idx], Clo[idx]);
    }
}

// =====================================================================
// GEMM mainloop (unchanged, working)
// =====================================================================
__device__ __forceinline__ void copyA(uint32_t* smw, int dst_w,
                                      const __nv_bfloat16* __restrict__ src, int tid)
{
    for (int i = tid; i < 1024; i += 256) {
        int r = i >> 3, q = i & 7;
        uint4 v = *(const uint4*)(src + (size_t)r * KPAD + q * 8);
        *(uint4*)(smw + dst_w + r * RS + q * 4) = v;
    }
}
__device__ __forceinline__ void copyB(uint32_t* smw, int dst_w,
                                      const __nv_bfloat16* __restrict__ src, int tid)
{
    for (int i = tid; i < 512; i += 256) {
        int r = i >> 3, q = i & 7;
        uint4 v = *(const uint4*)(src + (size_t)r * KPAD + q * 8);
        *(uint4*)(smw + dst_w + r * RS + q * 4) = v;
    }
}

__device__ __forceinline__ void gemm_mainloop(
    uint32_t* smw, int tid,
    const __nv_bfloat16* Ah, const __nv_bfloat16* Al,
    const __nv_bfloat16* Bh, const __nv_bfloat16* Bl,
    float acc[2][4][4])
{
    const int wid = tid >> 5, lane = tid & 31;
    const int wm = wid & 3, wn = wid >> 2;
    const int g = lane >> 2, t = lane & 3;

    for (int c = 0; c < 9; c++) {
        const int k0 = c * 64;
        __syncthreads();
        copyA(smw, WA_HI, Ah + k0, tid);
        copyA(smw, WA_LO, Al + k0, tid);
        copyB(smw, WB_HI, Bh + k0, tid);
        copyB(smw, WB_LO, Bl + k0, tid);
        __syncthreads();

        #pragma unroll
        for (int ks = 0; ks < 4; ks++) {
            uint32_t ah[2][4], al[2][4], bh[4][2], bl[4][2];
            const int kw = ks * 8 + t;
            #pragma unroll
            for (int mt = 0; mt < 2; mt++) {
                int r = wm * 32 + mt * 16 + g;
                ah[mt][0] = smw[WA_HI + r * RS + kw];
                ah[mt][1] = smw[WA_HI + (r + 8) * RS + kw];
                ah[mt][2] = smw[WA_HI + r * RS + kw + 4];
                ah[mt][3] = smw[WA_HI + (r + 8) * RS + kw + 4];
                al[mt][0] = smw[WA_LO + r * RS + kw];
                al[mt][1] = smw[WA_LO + (r + 8) * RS + kw];
                al[mt][2] = smw[WA_LO + r * RS + kw + 4];
                al[mt][3] = smw[WA_LO + (r + 8) * RS + kw + 4];
            }
            #pragma unroll
            for (int nt = 0; nt < 4; nt++) {
                int n = wn * 32 + nt * 8 + g;
                bh[nt][0] = smw[WB_HI + n * RS + kw];
                bh[nt][1] = smw[WB_HI + n * RS + kw + 4];
                bl[nt][0] = smw[WB_LO + n * RS + kw];
                bl[nt][1] = smw[WB_LO + n * RS + kw + 4];
            }
            #pragma unroll
            for (int mt = 0; mt < 2; mt++)
                #pragma unroll
                for (int nt = 0; nt < 4; nt++) {
                    MMA16816(acc[mt][nt], ah[mt], bh[nt]);
                    MMA16816(acc[mt][nt], ah[mt], bl[nt]);
                    MMA16816(acc[mt][nt], al[mt], bh[nt]);
                }
        }
    }
}

// =====================================================================
// K1: QKV GEMM (unchanged)
// =====================================================================
__global__ __launch_bounds__(256) void qkv_mma(
    const float* __restrict__ bq, const float* __restrict__ bk, const float* __restrict__ bv)
{
    extern __shared__ uint32_t smw[];
    const int tid = threadIdx.x;
    const int wid = tid >> 5, lane = tid & 31;
    const int wm = wid & 3, wn = wid >> 2;
    const int g = lane >> 2, t = lane & 3;
    const int which = blockIdx.y % 3;
    const int h     = blockIdx.y / 3;
    const int slot  = which * 8 + h;
    const int m0    = blockIdx.x * 128;

    {
        const float* bias = (which == 0) ? bq : (which == 1) ? bk : bv;
        if (tid < 64) ((float*)(smw + WBIAS))[tid] = bias[h * 64 + tid];
    }

    float acc[2][4][4];
    #pragma unroll
    for (int mt = 0; mt < 2; mt++)
        #pragma unroll
        for (int nt = 0; nt < 4; nt++)
            #pragma unroll
            for (int i = 0; i < 4; i++) acc[mt][nt][i] = 0.f;

    gemm_mainloop(smw, tid,
                  Xhi + (size_t)m0 * KPAD, Xlo + (size_t)m0 * KPAD,
                  WqkvHi + (size_t)slot * 64 * KPAD, WqkvLo + (size_t)slot * 64 * KPAD,
                  acc);

    const float* biass = (const float*)(smw + WBIAS);
    float* ssP = (float*)(smw + WSSP);

    __syncthreads();
    #pragma unroll
    for (int mt = 0; mt < 2; mt++) {
        #pragma unroll
        for (int half = 0; half < 2; half++) {
            int lrow = wm * 32 + mt * 16 + g + half * 8;
            int row = m0 + lrow;
            int b = row >> 11, n = row & (Nseq - 1);
            size_t rbase = (size_t)(b * 8 + h) * 2048 + n;
            float ss = 0.f;
            #pragma unroll
            for (int nt = 0; nt < 4; nt++) {
                int col0 = wn * 32 + nt * 8 + 2 * t;
                float v0 = acc[mt][nt][half * 2 + 0] + biass[col0];
                float v1 = acc[mt][nt][half * 2 + 1] + biass[col0 + 1];
                ss += v0 * v0 + v1 * v1;
                __nv_bfloat16 h0, l0, h1, l1;
                bsplit(v0, h0, l0); bsplit(v1, h1, l1);
                if (which == 0) {
                    ((uint32_t*)QSh)[rbase * 32 + (col0 >> 1)] = pack2(h0, h1);
                    ((uint32_t*)QSl)[rbase * 32 + (col0 >> 1)] = pack2(l0, l1);
                } else if (which == 1) {
                    ((uint32_t*)KSh)[rbase * 32 + (col0 >> 1)] = pack2(h0, h1);
                    ((uint32_t*)KSl)[rbase * 32 + (col0 >> 1)] = pack2(l0, l1);
                } else {
                    Vh_[rbase * 65 + 1 + col0] = h0;  Vh_[rbase * 65 + 2 + col0] = h1;
                    Vl_[rbase * 65 + 1 + col0] = l0;  Vl_[rbase * 65 + 2 + col0] = l1;
                }
            }
            ss += __shfl_xor_sync(0xffffffffu, ss, 1);
            ss += __shfl_xor_sync(0xffffffffu, ss, 2);
            if (t == 0) ssP[lrow * 2 + wn] = ss;
        }
    }
    __syncthreads();
    if (wn == 0 && t == 0) {
        #pragma unroll
        for (int mt = 0; mt < 2; mt++)
            #pragma unroll
            for (int half = 0; half < 2; half++) {
                int lrow = wm * 32 + mt * 16 + g + half * 8;
                int row = m0 + lrow;
                int b = row >> 11, n = row & (Nseq - 1);
                size_t rbase = (size_t)(b * 8 + h) * 2048 + n;
                float ss = ssP[lrow * 2] + ssP[lrow * 2 + 1];
                float tv = sqrtf(fmaxf(INVK + ss, EPSf));
                if (which == 0) Tqg[rbase] = tv;
                else if (which == 1) Tkg[rbase] = tv;
                else { bsplit(tv, Vh_[rbase * 65], Vl_[rbase * 65]); }
            }
    }
}

// =====================================================================
// V transpose (unchanged)
// =====================================================================
__global__ __launch_bounds__(128) void vtrans()
{
    __shared__ __nv_bfloat16 sh[64][73];
    __shared__ __nv_bfloat16 sl[64][73];
    const int bh = blockIdx.y, k0 = blockIdx.x * 64, tid = threadIdx.x;
    const __nv_bfloat16 z = __float2bfloat16(0.f);
    for (int i = tid; i < 64 * 72; i += 128) {
        int r = i / 72, d = i % 72;
        sh[r][d] = (d < 65) ? Vh_[((size_t)bh * 2048 + k0 + r) * 65 + d] : z;
        sl[r][d] = (d < 65) ? Vl_[((size_t)bh * 2048 + k0 + r) * 65 + d] : z;
    }
    __syncthreads();
    for (int i = tid; i < 72 * 64; i += 128) {
        int d = i >> 6, k = i & 63;
        VTh[((size_t)bh * 72 + d) * 2048 + k0 + k] = sh[k][d];
        VTl[((size_t)bh * 72 + d) * 2048 + k0 + k] = sl[k][d];
    }
}

// =====================================================================
// K2: pipelined tensor-core flash attention, max-free softmax.
// grid (16 qtiles, 32 bh), 256 threads, 2 CTAs/SM forced.
// =====================================================================
#define ABUF 9856

__device__ __forceinline__ void attn_issue_tile(
    uint32_t smb, int bufw, int kt, int tid, int bh, size_t base)
{
    const int k0 = kt * 64;
    for (int i = tid; i < 2192; i += 256) {
        uint32_t dstw; const void* src;
        if (i < 512) {
            int r = i >> 3, q = i & 7;
            dstw = bufw + r * RS + q * 4;
            src = KSh + (base + k0 + r) * 64 + q * 8;
        } else if (i < 1024) {
            int j = i - 512, r = j >> 3, q = j & 7;
            dstw = bufw + 2304 + r * RS + q * 4;
            src = KSl + (base + k0 + r) * 64 + q * 8;
        } else if (i < 1600) {
            int j = i - 1024, d = j >> 3, q = j & 7;
            dstw = bufw + 4608 + d * RS + q * 4;
            src = VTh + ((size_t)bh * 72 + d) * 2048 + k0 + q * 8;
        } else if (i < 2176) {
            int j = i - 1600, d = j >> 3, q = j & 7;
            dstw = bufw + 7200 + d * RS + q * 4;
            src = VTl + ((size_t)bh * 72 + d) * 2048 + k0 + q * 8;
        } else {
            int j = i - 2176;
            dstw = bufw + 9792 + j * 4;
            src = Tkg + base + k0 + j * 4;
        }
        CP_ASYNC16(smb + dstw * 4, src);
    }
}

__global__ __launch_bounds__(256, 2) void attn_mma()
{
    extern __shared__ uint32_t sw[];
    const int tid = threadIdx.x;
    const int w = tid >> 5, lane = tid & 31;
    const int g = lane >> 2, t = lane & 3;
    const int bh = blockIdx.y;
    const int b = bh >> 3, h = bh & 7;
    const int n0 = blockIdx.x * 128;
    const size_t base = (size_t)bh * 2048;
    uint32_t smb;
    asm("{ .reg .u64 tt; cvta.to.shared.u64 tt, %1; cvt.u32.u64 %0, tt; }"
        : "=r"(smb) : "l"(sw));

    attn_issue_tile(smb, 0, 0, tid, bh, base);
    CP_COMMIT();

    {
        const uint4* qh4 = (const uint4*)(QSh + (base + n0) * 64);
        const uint4* ql4 = (const uint4*)(QSl + (base + n0) * 64);
        for (int i = tid; i < 1024; i += 256) {
            int r = i >> 3, q = i & 7;
            *(uint4*)(sw + ABUF + r * RS + q * 4) = qh4[i];
            *(uint4*)(sw + ABUF + 4608 + r * RS + q * 4) = ql4[i];
        }
    }
    __syncthreads();
    uint32_t qh[4][4], ql[4][4];
    const int r0 = w * 16 + g;
    #pragma unroll
    for (int ks = 0; ks < 4; ks++) {
        int kw = ks * 8 + t;
        qh[ks][0] = sw[ABUF + r0 * RS + kw];
        qh[ks][1] = sw[ABUF + (r0 + 8) * RS + kw];
        qh[ks][2] = sw[ABUF + r0 * RS + kw + 4];
        qh[ks][3] = sw[ABUF + (r0 + 8) * RS + kw + 4];
        ql[ks][0] = sw[ABUF + 4608 + r0 * RS + kw];
        ql[ks][1] = sw[ABUF + 4608 + (r0 + 8) * RS + kw];
        ql[ks][2] = sw[ABUF + 4608 + r0 * RS + kw + 4];
        ql[ks][3] = sw[ABUF + 4608 + (r0 + 8) * RS + kw + 4];
    }
    const float tqa = Tqg[base + n0 + r0];
    const float tqb = Tqg[base + n0 + r0 + 8];
    __syncthreads();

    float accO[9][4];
    #pragma unroll
    for (int nd = 0; nd < 9; nd++)
        #pragma unroll
        for (int c = 0; c < 4; c++) accO[nd][c] = 0.f;
    float lA = 0.f, lB = 0.f;   // lane-local unnormalized row sums

    for (int kt = 0; kt < 32; kt++) {
        const int cur = (kt & 1) * ABUF;
        if (kt < 31) {
            attn_issue_tile(smb, ((kt + 1) & 1) * ABUF, kt + 1, tid, bh, base);
            CP_COMMIT();
            CP_WAIT(1);
        } else {
            CP_WAIT(0);
        }
        __syncthreads();

        const float* tks = (const float*)(sw + cur + 9792);

        float sacc[8][4];
        #pragma unroll
        for (int nt = 0; nt < 8; nt++)
            #pragma unroll
            for (int c = 0; c < 4; c++) sacc[nt][c] = 0.f;

        #pragma unroll
        for (int ks = 0; ks < 4; ks++) {
            const int kw = ks * 8 + t;
            #pragma unroll
            for (int nt = 0; nt < 8; nt++) {
                int n = nt * 8 + g;
                uint32_t kb[2], klr[2];
                kb[0]  = sw[cur + n * RS + kw];
                kb[1]  = sw[cur + n * RS + kw + 4];
                klr[0] = sw[cur + 2304 + n * RS + kw];
                klr[1] = sw[cur + 2304 + n * RS + kw + 4];
                MMA16816(sacc[nt], qh[ks], kb);
                MMA16816(sacc[nt], qh[ks], klr);
                MMA16816(sacc[nt], ql[ks], kb);
            }
        }

        // max-free softmax: scores <= -1/(8k) < 0 always (hyperboloid bound)
        #pragma unroll
        for (int nt = 0; nt < 8; nt++) {
            float tk0 = tks[nt * 8 + 2 * t];
            float tk1 = tks[nt * 8 + 2 * t + 1];
            sacc[nt][0] = exp2p((sacc[nt][0] - tqa * tk0) * S2f);
            sacc[nt][1] = exp2p((sacc[nt][1] - tqa * tk1) * S2f);
            sacc[nt][2] = exp2p((sacc[nt][2] - tqb * tk0) * S2f);
            sacc[nt][3] = exp2p((sacc[nt][3] - tqb * tk1) * S2f);
            lA += sacc[nt][0] + sacc[nt][1];
            lB += sacc[nt][2] + sacc[nt][3];
        }

        // O += P . V  (split P, split V)
        #pragma unroll
        for (int kb = 0; kb < 4; kb++) {
            float p00 = sacc[2*kb][0],   p01 = sacc[2*kb][1];
            float p02 = sacc[2*kb][2],   p03 = sacc[2*kb][3];
            float p10 = sacc[2*kb+1][0], p11 = sacc[2*kb+1][1];
            float p12 = sacc[2*kb+1][2], p13 = sacc[2*kb+1][3];
            __nv_bfloat16 h00 = __float2bfloat16(p00), h01 = __float2bfloat16(p01);
            __nv_bfloat16 h02 = __float2bfloat16(p02), h03 = __float2bfloat16(p03);
            __nv_bfloat16 h10 = __float2bfloat16(p10), h11 = __float2bfloat16(p11);
            __nv_bfloat16 h12 = __float2bfloat16(p12), h13 = __float2bfloat16(p13);
            uint32_t Ahi[4], Alo[4];
            Ahi[0] = pack2(h00, h01);  Ahi[1] = pack2(h02, h03);
            Ahi[2] = pack2(h10, h11);  Ahi[3] = pack2(h12, h13);
            Alo[0] = pack2(__float2bfloat16(p00 - __bfloat162float(h00)),
                           __float2bfloat16(p01 - __bfloat162float(h01)));
            Alo[1] = pack2(__float2bfloat16(p02 - __bfloat162float(h02)),
                           __float2bfloat16(p03 - __bfloat162float(h03)));
            Alo[2] = pack2(__float2bfloat16(p10 - __bfloat162float(h10)),
                           __float2bfloat16(p11 - __bfloat162float(h11)));
            Alo[3] = pack2(__float2bfloat16(p12 - __bfloat162float(h12)),
                           __float2bfloat16(p13 - __bfloat162float(h13)));
            const int kw = kb * 8 + t;
            #pragma unroll
            for (int nd = 0; nd < 9; nd++) {
                int n = nd * 8 + g;
                uint32_t vb[2], vl[2];
                vb[0] = sw[cur + 4608 + n * RS + kw];
                vb[1] = sw[cur + 4608 + n * RS + kw + 4];
                vl[0] = sw[cur + 7200 + n * RS + kw];
                vl[1] = sw[cur + 7200 + n * RS + kw + 4];
                MMA16816(accO[nd], Ahi, vb);
                MMA16816(accO[nd], Alo, vb);
                MMA16816(accO[nd], Ahi, vl);
            }
        }
        __syncthreads();
    }

    // final row-sum reduction (once)
    lA += __shfl_xor_sync(0xffffffffu, lA, 1);
    lA += __shfl_xor_sync(0xffffffffu, lA, 2);
    lB += __shfl_xor_sync(0xffffffffu, lB, 1);
    lB += __shfl_xor_sync(0xffffffffu, lB, 2);

    const float linA = 1.f / lA, linB = 1.f / lB;
    float ssA = 0.f, ssB = 0.f;
    #pragma unroll
    for (int nd = 0; nd < 9; nd++) {
        accO[nd][0] *= linA;  accO[nd][1] *= linA;
        accO[nd][2] *= linB;  accO[nd][3] *= linB;
        ssA += accO[nd][0] * accO[nd][0] + accO[nd][1] * accO[nd][1];
        ssB += accO[nd][2] * accO[nd][2] + accO[nd][3] * accO[nd][3];
    }
    ssA += __shfl_xor_sync(0xffffffffu, ssA, 1);
    ssA += __shfl_xor_sync(0xffffffffu, ssA, 2);
    ssB += __shfl_xor_sync(0xffffffffu, ssB, 1);
    ssB += __shfl_xor_sync(0xffffffffu, ssB, 2);
    float tA = __shfl_sync(0xffffffffu, accO[0][0], lane & ~3);
    float tB = __shfl_sync(0xffffffffu, accO[0][2], lane & ~3);
    float spA = ssA - tA * tA;
    float spB = ssB - tB * tB;
    float idnA = rsqrtf(fmaxf(KCURV * (tA * tA - spA), EPSf));
    float idnB = rsqrtf(fmaxf(KCURV * (tB * tB - spB), EPSf));

    const int rowA = b * 2048 + n0 + w * 16 + g;
    const int rowB = rowA + 8;
    #pragma unroll
    for (int nd = 0; nd < 9; nd++) {
        #pragma unroll
        for (int c = 0; c < 2; c++) {
            int d = nd * 8 + 2 * t + c;
            if (d >= 1 && d < 65) {
                OutCat[(size_t)rowA * 512 + h * 64 + d - 1] = accO[nd][c] * idnA;
                OutCat[(size_t)rowB * 512 + h * 64 + d - 1] = accO[nd][c + 2] * idnB;
            }
        }
    }
    if (t == 0) {
        HSS[rowA * 8 + h] = spA * idnA * idnA;
        HSS[rowB * 8 + h] = spB * idnB * idnB;
    }
}

// =====================================================================
// K3: output projection (unchanged)
// =====================================================================
__global__ __launch_bounds__(256) void outproj_mma(
    const float* __restrict__ bo, float* __restrict__ out)
{
    extern __shared__ uint32_t smw[];
    const int tid = threadIdx.x;
    const int wid = tid >> 5, lane = tid & 31;
    const int wm = wid & 3, wn = wid >> 2;
    const int g = lane >> 2, t = lane & 3;
    const int m0 = blockIdx.x * 128;
    const int c0 = blockIdx.y * 64;

    if (tid < 64) ((float*)(smw + WBIAS))[tid] = bo[c0 + tid];

    float acc[2][4][4];
    #pragma unroll
    for (int mt = 0; mt < 2; mt++)
        #pragma unroll
        for (int nt = 0; nt < 4; nt++)
            #pragma unroll
            for (int i = 0; i < 4; i++) acc[mt][nt][i] = 0.f;

    gemm_mainloop(smw, tid,
                  Chi + (size_t)m0 * KPAD, Clo + (size_t)m0 * KPAD,
                  WoTHi + (size_t)c0 * KPAD, WoTLo + (size_t)c0 * KPAD,
                  acc);

    const float* biass = (const float*)(smw + WBIAS);
    float* ssP = (float*)(smw + WSSP);

    __syncthreads();
    #pragma unroll
    for (int mt = 0; mt < 2; mt++) {
        #pragma unroll
        for (int half = 0; half < 2; half++) {
            int lrow = wm * 32 + mt * 16 + g + half * 8;
            int row = m0 + lrow;
            float ss = 0.f;
            #pragma unroll
            for (int nt = 0; nt < 4; nt++) {
                #pragma unroll
                for (int cc = 0; cc < 2; cc++) {
                    int col = wn * 32 + nt * 8 + 2 * t + cc;
                    float v = acc[mt][nt][half * 2 + cc] + biass[col];
                    out[(size_t)row * Dm + 1 + c0 + col] = v;
                    ss += v * v;
                }
            }
            ss += __shfl_xor_sync(0xffffffffu, ss, 1);
            ss += __shfl_xor_sync(0xffffffffu, ss, 2);
            if (t == 0) ssP[lrow * 2 + wn] = ss;
        }
    }
    __syncthreads();
    if (wn == 0 && t == 0) {
        #pragma unroll
        for (int mt = 0; mt < 2; mt++)
            #pragma unroll
            for (int half = 0; half < 2; half++) {
                int lrow = wm * 32 + mt * 16 + g + half * 8;
                int row = m0 + lrow;
                Part2[row * 8 + blockIdx.y] = ssP[lrow * 2] + ssP[lrow * 2 + 1];
            }
    }
}

__global__ void time_kernel(float* __restrict__ out)
{
    int row = blockIdx.x * 256 + threadIdx.x;
    if (row < Mrows) {
        float ss = 0.f;
        #pragma unroll
        for (int j = 0; j < 8; j++) ss += Part2[row * 8 + j];
        out[(size_t)row * Dm] = sqrtf(fmaxf(INVK + ss, EPSf));
    }
}

// =====================================================================
extern "C" void kernel_launch(void* const* d_in, const int* in_sizes, int n_in,
                              void* d_out, int out_size)
{
    const float* x  = (const float*)d_in[0];
    const float* Wq = (const float*)d_in[1];
    const float* bq = (const float*)d_in[2];
    const float* Wk = (const float*)d_in[3];
    const float* bk = (const float*)d_in[4];
    const float* Wv = (const float*)d_in[5];
    const float* bv = (const float*)d_in[6];
    const float* Wo = (const float*)d_in[7];
    const float* bo = (const float*)d_in[8];
    float* out = (float*)d_out;

    const int smem_gemm = WTOT * 4;
    const int smem_attn = 2 * ABUF * 4;
    cudaFuncSetAttribute(qkv_mma, cudaFuncAttributeMaxDynamicSharedMemorySize, smem_gemm);
    cudaFuncSetAttribute(outproj_mma, cudaFuncAttributeMaxDynamicSharedMemorySize, smem_gemm);
    cudaFuncSetAttribute(attn_mma, cudaFuncAttributeMaxDynamicSharedMemorySize, smem_attn);

    cvt_in_kernel<<<5760, 1024>>>(Wq, Wk, Wv, Wo, x);
    qkv_mma<<<dim3(64, 24), 256, smem_gemm>>>(bq, bk, bv);
    vtrans<<<dim3(32, 32), 128>>>();
    attn_mma<<<dim3(16, 32), 256, smem_attn>>>();
    cvt_cat_kernel<<<4608, 1024>>>();
    outproj_mma<<<dim3(64, 8), 256, smem_gemm>>>(bo, out);
    time_kernel<<<32, 256>>>(out);
}

// round 10
// speedup vs baseline: 2.3285x; 1.0260x over previous
#include <cuda_runtime.h>
#include <cuda_bf16.h>
#include <math.h>
#include <stdint.h>

#define Bsz   4
#define Nseq  2048
#define Dm    513
#define Hh    8
#define Mrows 8192
#define KPAD  576
#define INVK  10.0f
#define KCURV 0.1f
#define EPSf  1e-9f
#define S2f   0.18033688011112042f   // 0.125 * log2(e)

// ---------------- device scratch ----------------
__device__ float OutCat[(size_t)Mrows*512];
__device__ float HSS[Mrows*Hh];
__device__ float Part2[Mrows*8];
__device__ __nv_bfloat16 Xhi[(size_t)Mrows*KPAD];
__device__ __nv_bfloat16 Xlo[(size_t)Mrows*KPAD];
__device__ __nv_bfloat16 WqkvHi[24*64*KPAD];
__device__ __nv_bfloat16 WqkvLo[24*64*KPAD];
__device__ __nv_bfloat16 WoTHi[512*KPAD];
__device__ __nv_bfloat16 WoTLo[512*KPAD];
__device__ __nv_bfloat16 Chi[(size_t)Mrows*KPAD];
__device__ __nv_bfloat16 Clo[(size_t)Mrows*KPAD];
// attention operands: interleaved (hi0,hi1,lo0,lo1) per (ks,t) group, 64 words/row
__device__ uint32_t QKiW[(size_t)32*2048*64];   // Q
__device__ uint32_t KKiW[(size_t)32*2048*64];   // K
__device__ float Tqg[32*2048];
__device__ float Tkg[32*2048];
__device__ __nv_bfloat16 Vh_[(size_t)32*2048*65];
__device__ __nv_bfloat16 Vl_[(size_t)32*2048*65];
// V transposed: [bh][72 d-rows][32 key-blocks][128 bf16: interleaved hi/lo words]
__device__ __nv_bfloat16 VTiE[(size_t)32*72*32*128];

__device__ __forceinline__ void bsplit(float v, __nv_bfloat16& h, __nv_bfloat16& l) {
    h = __float2bfloat16(v);
    l = __float2bfloat16(v - __bfloat162float(h));
}
__device__ __forceinline__ uint32_t pack2(__nv_bfloat16 a, __nv_bfloat16 b) {
    __nv_bfloat162 t2; t2.x = a; t2.y = b;
    uint32_t r; memcpy(&r, &t2, 4); return r;
}
// pack two fp32 to bf16x2 (lo in lower half)
__device__ __forceinline__ uint32_t cvtpk(float lo, float hi) {
    uint32_t r;
    asm("cvt.rn.bf16x2.f32 %0, %1, %2;" : "=r"(r) : "f"(hi), "f"(lo));
    return r;
}

__device__ __forceinline__ float exp2p(float y) {
    y = fmaxf(y, -120.f);
    float z = y + 12582912.f;
    int ib = __float_as_int(z);
    float n = z - 12582912.f;
    float f = y - n;
    float p = 1.3333558146e-3f;
    p = fmaf(p, f, 9.6181291076e-3f);
    p = fmaf(p, f, 5.5504108664e-2f);
    p = fmaf(p, f, 2.4022650696e-1f);
    p = fmaf(p, f, 6.9314718056e-1f);
    p = fmaf(p, f, 1.0f);
    // low 9 bits of ib == n mod 512; add n directly into the exponent field
    return __int_as_float(__float_as_int(p) + (ib << 23));
}

#define MMA16816(D, A, B) \
    asm volatile("mma.sync.aligned.m16n8k16.row.col.f32.bf16.bf16.f32 " \
        "{%0,%1,%2,%3}, {%4,%5,%6,%7}, {%8,%9}, {%0,%1,%2,%3};" \
        : "+f"((D)[0]), "+f"((D)[1]), "+f"((D)[2]), "+f"((D)[3]) \
        : "r"((A)[0]), "r"((A)[1]), "r"((A)[2]), "r"((A)[3]), \
          "r"((B)[0]), "r"((B)[1]))

#define CP_ASYNC16(dst, src) \
    asm volatile("cp.async.cg.shared.global [%0], [%1], 16;" :: "r"(dst), "l"(src))
#define CP_COMMIT() asm volatile("cp.async.commit_group;" ::: "memory")
#define CP_WAIT(n)  asm volatile("cp.async.wait_group %0;" :: "n"(n) : "memory")

#define RS 36
#define WA_HI 0
#define WA_LO 4608
#define WB_HI 9216
#define WB_LO 11520
#define WBIAS 13824
#define WSSP  13888
#define WTOT  14144

// attention smem geometry (words)
#define RSA   80          // padded row stride (conflict-free LDS.128)
#define VOFF  5120        // 64 K-rows * 80
#define TKOFF 10880       // + 72 V-rows * 80
#define ABUF  10944       // + 64 tk floats

// interleaved word position for column-pair j (0..31)
__device__ __forceinline__ int ipos(int j) {
    return 16 * (j >> 3) + 4 * (j & 3) + ((j >> 2) & 1);
}

// =====================================================================
// merged input conversion
// =====================================================================
__global__ void cvt_in_kernel(const float* __restrict__ Wq, const float* __restrict__ Wk,
                              const float* __restrict__ Wv, const float* __restrict__ Wo,
                              const float* __restrict__ x)
{
    const int totW1 = 24 * 64 * KPAD;
    const int totW  = totW1 + 512 * KPAD;
    const size_t totX = (size_t)Mrows * KPAD;
    const size_t total = totW + totX;
    for (size_t idx = (size_t)blockIdx.x * blockDim.x + threadIdx.x; idx < total;
         idx += (size_t)gridDim.x * blockDim.x) {
        if (idx < (size_t)totW1) {
            int i = (int)idx;
            int k = i % KPAD;
            int t = i / KPAD;
            int n = t % 64;
            int s = t / 64;
            int which = s >> 3, h = s & 7;
            const float* W = (which == 0) ? Wq : (which == 1) ? Wk : Wv;
            float v = (k < Dm) ? W[((size_t)h * Dm + k) * 64 + n] : 0.f;
            bsplit(v, WqkvHi[i], WqkvLo[i]);
        } else if (idx < (size_t)totW) {
            int i2 = (int)idx - totW1;
            int k = i2 % KPAD;
            int n = i2 / KPAD;
            float v = (k < Dm) ? Wo[(size_t)k * 512 + n] : 0.f;
            bsplit(v, WoTHi[i2], WoTLo[i2]);
        } else {
            size_t i3 = idx - totW;
            int k = (int)(i3 % KPAD);
            size_t row = i3 / KPAD;
            float v = (k < Dm) ? x[row * Dm + k] : 0.f;
            bsplit(v, Xhi[i3], Xlo[i3]);
        }
    }
}

__global__ void cvt_cat_kernel()
{
    const size_t total = (size_t)Mrows * KPAD;
    for (size_t idx = (size_t)blockIdx.x * blockDim.x + threadIdx.x; idx < total;
         idx += (size_t)gridDim.x * blockDim.x) {
        int k = (int)(idx % KPAD);
        size_t row = idx / KPAD;
        float v;
        if (k == 0) {
            float ss = 0.f;
            #pragma unroll
            for (int hh = 0; hh < 8; hh++) ss += HSS[row * 8 + hh];
            v = sqrtf(fmaxf(INVK + ss, EPSf));
        } else if (k < Dm) {
            v = OutCat[row * 512 + k - 1];
        } else v = 0.f;
        bsplit(v, Chi[idx], Clo[idx]);
    }
}

// =====================================================================
// projection GEMM mainloop (unchanged, proven)
// =====================================================================
__device__ __forceinline__ void copyA(uint32_t* smw, int dst_w,
                                      const __nv_bfloat16* __restrict__ src, int tid)
{
    for (int i = tid; i < 1024; i += 256) {
        int r = i >> 3, q = i & 7;
        uint4 v = *(const uint4*)(src + (size_t)r * KPAD + q * 8);
        *(uint4*)(smw + dst_w + r * RS + q * 4) = v;
    }
}
__device__ __forceinline__ void copyB(uint32_t* smw, int dst_w,
                                      const __nv_bfloat16* __restrict__ src, int tid)
{
    for (int i = tid; i < 512; i += 256) {
        int r = i >> 3, q = i & 7;
        uint4 v = *(const uint4*)(src + (size_t)r * KPAD + q * 8);
        *(uint4*)(smw + dst_w + r * RS + q * 4) = v;
    }
}

__device__ __forceinline__ void gemm_mainloop(
    uint32_t* smw, int tid,
    const __nv_bfloat16* Ah, const __nv_bfloat16* Al,
    const __nv_bfloat16* Bh, const __nv_bfloat16* Bl,
    float acc[2][4][4])
{
    const int wid = tid >> 5, lane = tid & 31;
    const int wm = wid & 3, wn = wid >> 2;
    const int g = lane >> 2, t = lane & 3;

    for (int c = 0; c < 9; c++) {
        const int k0 = c * 64;
        __syncthreads();
        copyA(smw, WA_HI, Ah + k0, tid);
        copyA(smw, WA_LO, Al + k0, tid);
        copyB(smw, WB_HI, Bh + k0, tid);
        copyB(smw, WB_LO, Bl + k0, tid);
        __syncthreads();

        #pragma unroll
        for (int ks = 0; ks < 4; ks++) {
            uint32_t ah[2][4], al[2][4], bh[4][2], bl[4][2];
            const int kw = ks * 8 + t;
            #pragma unroll
            for (int mt = 0; mt < 2; mt++) {
                int r = wm * 32 + mt * 16 + g;
                ah[mt][0] = smw[WA_HI + r * RS + kw];
                ah[mt][1] = smw[WA_HI + (r + 8) * RS + kw];
                ah[mt][2] = smw[WA_HI + r * RS + kw + 4];
                ah[mt][3] = smw[WA_HI + (r + 8) * RS + kw + 4];
                al[mt][0] = smw[WA_LO + r * RS + kw];
                al[mt][1] = smw[WA_LO + (r + 8) * RS + kw];
                al[mt][2] = smw[WA_LO + r * RS + kw + 4];
                al[mt][3] = smw[WA_LO + (r + 8) * RS + kw + 4];
            }
            #pragma unroll
            for (int nt = 0; nt < 4; nt++) {
                int n = wn * 32 + nt * 8 + g;
                bh[nt][0] = smw[WB_HI + n * RS + kw];
                bh[nt][1] = smw[WB_HI + n * RS + kw + 4];
                bl[nt][0] = smw[WB_LO + n * RS + kw];
                bl[nt][1] = smw[WB_LO + n * RS + kw + 4];
            }
            #pragma unroll
            for (int mt = 0; mt < 2; mt++)
                #pragma unroll
                for (int nt = 0; nt < 4; nt++) {
                    MMA16816(acc[mt][nt], ah[mt], bh[nt]);
                    MMA16816(acc[mt][nt], ah[mt], bl[nt]);
                    MMA16816(acc[mt][nt], al[mt], bh[nt]);
                }
        }
    }
}

// =====================================================================
// K1: QKV GEMM; epilogue writes interleaved Q/K rows + V rows + times
// =====================================================================
__global__ __launch_bounds__(256) void qkv_mma(
    const float* __restrict__ bq, const float* __restrict__ bk, const float* __restrict__ bv)
{
    extern __shared__ uint32_t smw[];
    const int tid = threadIdx.x;
    const int wid = tid >> 5, lane = tid & 31;
    const int wm = wid & 3, wn = wid >> 2;
    const int g = lane >> 2, t = lane & 3;
    const int which = blockIdx.y % 3;
    const int h     = blockIdx.y / 3;
    const int slot  = which * 8 + h;
    const int m0    = blockIdx.x * 128;

    {
        const float* bias = (which == 0) ? bq : (which == 1) ? bk : bv;
        if (tid < 64) ((float*)(smw + WBIAS))[tid] = bias[h * 64 + tid];
    }

    float acc[2][4][4];
    #pragma unroll
    for (int mt = 0; mt < 2; mt++)
        #pragma unroll
        for (int nt = 0; nt < 4; nt++)
            #pragma unroll
            for (int i = 0; i < 4; i++) acc[mt][nt][i] = 0.f;

    gemm_mainloop(smw, tid,
                  Xhi + (size_t)m0 * KPAD, Xlo + (size_t)m0 * KPAD,
                  WqkvHi + (size_t)slot * 64 * KPAD, WqkvLo + (size_t)slot * 64 * KPAD,
                  acc);

    const float* biass = (const float*)(smw + WBIAS);
    float* ssP = (float*)(smw + WSSP);

    __syncthreads();
    #pragma unroll
    for (int mt = 0; mt < 2; mt++) {
        #pragma unroll
        for (int half = 0; half < 2; half++) {
            int lrow = wm * 32 + mt * 16 + g + half * 8;
            int row = m0 + lrow;
            int b = row >> 11, n = row & (Nseq - 1);
            size_t rbase = (size_t)(b * 8 + h) * 2048 + n;
            float ss = 0.f;
            #pragma unroll
            for (int nt = 0; nt < 4; nt++) {
                int col0 = wn * 32 + nt * 8 + 2 * t;
                float v0 = acc[mt][nt][half * 2 + 0] + biass[col0];
                float v1 = acc[mt][nt][half * 2 + 1] + biass[col0 + 1];
                ss += v0 * v0 + v1 * v1;
                __nv_bfloat16 h0, l0, h1, l1;
                bsplit(v0, h0, l0); bsplit(v1, h1, l1);
                if (which == 2) {
                    Vh_[rbase * 65 + 1 + col0] = h0;  Vh_[rbase * 65 + 2 + col0] = h1;
                    Vl_[rbase * 65 + 1 + col0] = l0;  Vl_[rbase * 65 + 2 + col0] = l1;
                } else {
                    int j = col0 >> 1;
                    int pos = ipos(j);
                    uint32_t* dst = (which == 0) ? QKiW : KKiW;
                    dst[rbase * 64 + pos]     = pack2(h0, h1);
                    dst[rbase * 64 + pos + 2] = pack2(l0, l1);
                }
            }
            ss += __shfl_xor_sync(0xffffffffu, ss, 1);
            ss += __shfl_xor_sync(0xffffffffu, ss, 2);
            if (t == 0) ssP[lrow * 2 + wn] = ss;
        }
    }
    __syncthreads();
    if (wn == 0 && t == 0) {
        #pragma unroll
        for (int mt = 0; mt < 2; mt++)
            #pragma unroll
            for (int half = 0; half < 2; half++) {
                int lrow = wm * 32 + mt * 16 + g + half * 8;
                int row = m0 + lrow;
                int b = row >> 11, n = row & (Nseq - 1);
                size_t rbase = (size_t)(b * 8 + h) * 2048 + n;
                float ss = ssP[lrow * 2] + ssP[lrow * 2 + 1];
                float tv = sqrtf(fmaxf(INVK + ss, EPSf));
                if (which == 0) Tqg[rbase] = tv;
                else if (which == 1) Tkg[rbase] = tv;
                else { bsplit(tv, Vh_[rbase * 65], Vl_[rbase * 65]); }
            }
    }
}

// =====================================================================
// V transpose into interleaved blocked layout
// =====================================================================
__global__ __launch_bounds__(128) void vtrans()
{
    __shared__ __nv_bfloat16 sh[64][73];
    __shared__ __nv_bfloat16 sl[64][73];
    const int bh = blockIdx.y, k0 = blockIdx.x * 64, tid = threadIdx.x;
    const int blk = blockIdx.x;
    const __nv_bfloat16 z = __float2bfloat16(0.f);
    for (int i = tid; i < 64 * 72; i += 128) {
        int r = i / 72, d = i % 72;
        sh[r][d] = (d < 65) ? Vh_[((size_t)bh * 2048 + k0 + r) * 65 + d] : z;
        sl[r][d] = (d < 65) ? Vl_[((size_t)bh * 2048 + k0 + r) * 65 + d] : z;
    }
    __syncthreads();
    for (int i = tid; i < 72 * 64; i += 128) {
        int d = i >> 6, k = i & 63;
        int jj = k >> 1, e = k & 1;
        int pos = ipos(jj);
        size_t eb = (((size_t)bh * 72 + d) * 32 + blk) * 128;
        VTiE[eb + pos * 2 + e]       = sh[k][d];
        VTiE[eb + (pos + 2) * 2 + e] = sl[k][d];
    }
}

// =====================================================================
// K2: pipelined tensor-core flash attention (interleaved LDS.128 frags)
// grid (16 qtiles, 32 bh), 256 threads, 2 CTAs/SM.
// =====================================================================
__device__ __forceinline__ void attn_issue_tile(
    uint32_t smb, int bufw, int kt, int tid, int bh, size_t base)
{
    const int k0 = kt * 64;
    for (int i = tid; i < 2192; i += 256) {
        uint32_t dstw; const void* src;
        if (i < 1024) {
            int r = i >> 4, ch = i & 15;
            dstw = bufw + r * RSA + ch * 4;
            src = KKiW + (base + k0 + r) * 64 + ch * 4;
        } else if (i < 2176) {
            int j = i - 1024, d = j >> 4, ch = j & 15;
            dstw = bufw + VOFF + d * RSA + ch * 4;
            src = VTiE + (((size_t)bh * 72 + d) * 32 + kt) * 128 + ch * 8;
        } else {
            int j = i - 2176;
            dstw = bufw + TKOFF + j * 4;
            src = Tkg + base + k0 + j * 4;
        }
        CP_ASYNC16(smb + dstw * 4, src);
    }
}

__global__ __launch_bounds__(256, 2) void attn_mma()
{
    extern __shared__ uint32_t sw[];
    const int tid = threadIdx.x;
    const int w = tid >> 5, lane = tid & 31;
    const int g = lane >> 2, t = lane & 3;
    const int bh = blockIdx.y;
    const int b = bh >> 3, h = bh & 7;
    const int n0 = blockIdx.x * 128;
    const size_t base = (size_t)bh * 2048;
    uint32_t smb;
    asm("{ .reg .u64 tt; cvta.to.shared.u64 tt, %1; cvt.u32.u64 %0, tt; }"
        : "=r"(smb) : "l"(sw));

    attn_issue_tile(smb, 0, 0, tid, bh, base);
    CP_COMMIT();

    // stage Q (128 rows x 64 words) into buffer 1 region
    for (int i = tid; i < 2048; i += 256) {
        int r = i >> 4, ch = i & 15;
        *(uint4*)(sw + ABUF + r * RSA + ch * 4) =
            *(const uint4*)(QKiW + (base + n0 + r) * 64 + ch * 4);
    }
    __syncthreads();
    uint32_t qh[4][4], ql[4][4];
    const int r0 = w * 16 + g;
    #pragma unroll
    for (int ks = 0; ks < 4; ks++) {
        uint4 a  = *(const uint4*)(sw + ABUF + r0 * RSA + 16 * ks + 4 * t);
        uint4 b2 = *(const uint4*)(sw + ABUF + (r0 + 8) * RSA + 16 * ks + 4 * t);
        qh[ks][0] = a.x;  qh[ks][1] = b2.x;  qh[ks][2] = a.y;  qh[ks][3] = b2.y;
        ql[ks][0] = a.z;  ql[ks][1] = b2.z;  ql[ks][2] = a.w;  ql[ks][3] = b2.w;
    }
    const float tqa = Tqg[base + n0 + r0];
    const float tqb = Tqg[base + n0 + r0 + 8];
    __syncthreads();

    float accO[9][4];
    #pragma unroll
    for (int nd = 0; nd < 9; nd++)
        #pragma unroll
        for (int c = 0; c < 4; c++) accO[nd][c] = 0.f;
    float lA = 0.f, lB = 0.f;

    for (int kt = 0; kt < 32; kt++) {
        const int cur = (kt & 1) * ABUF;
        if (kt < 31) {
            attn_issue_tile(smb, ((kt + 1) & 1) * ABUF, kt + 1, tid, bh, base);
            CP_COMMIT();
            CP_WAIT(1);
        } else {
            CP_WAIT(0);
        }
        __syncthreads();

        const float* tks = (const float*)(sw + cur + TKOFF);

        float sacc[8][4];
        #pragma unroll
        for (int nt = 0; nt < 8; nt++)
            #pragma unroll
            for (int c = 0; c < 4; c++) sacc[nt][c] = 0.f;

        #pragma unroll
        for (int ks = 0; ks < 4; ks++) {
            #pragma unroll
            for (int nt = 0; nt < 8; nt++) {
                int n = nt * 8 + g;
                uint4 kv = *(const uint4*)(sw + cur + n * RSA + 16 * ks + 4 * t);
                uint32_t kb[2]  = { kv.x, kv.y };
                uint32_t klr[2] = { kv.z, kv.w };
                MMA16816(sacc[nt], qh[ks], kb);
                MMA16816(sacc[nt], qh[ks], klr);
                MMA16816(sacc[nt], ql[ks], kb);
            }
        }

        // max-free softmax (scores always < 0 on the hyperboloid)
        #pragma unroll
        for (int nt = 0; nt < 8; nt++) {
            float2 tk = *(const float2*)(tks + nt * 8 + 2 * t);
            sacc[nt][0] = exp2p((sacc[nt][0] - tqa * tk.x) * S2f);
            sacc[nt][1] = exp2p((sacc[nt][1] - tqa * tk.y) * S2f);
            sacc[nt][2] = exp2p((sacc[nt][2] - tqb * tk.x) * S2f);
            sacc[nt][3] = exp2p((sacc[nt][3] - tqb * tk.y) * S2f);
            lA += sacc[nt][0] + sacc[nt][1];
            lB += sacc[nt][2] + sacc[nt][3];
        }

        // O += P . V (split P via packed cvt, split V from interleaved smem)
        #pragma unroll
        for (int kb2 = 0; kb2 < 4; kb2++) {
            uint32_t Ahi[4], Alo[4];
            #pragma unroll
            for (int q2 = 0; q2 < 4; q2++) {
                // q2: 0 -> (rowA, cols01), 1 -> (rowA, cols23 of next nt) ... mapping:
                // pairs: [0]=(p00,p01) [1]=(p02,p03) [2]=(p10,p11) [3]=(p12,p13)
                int nt = 2 * kb2 + (q2 >> 1);
                int c0 = (q2 & 1) * 2;
                float p0 = sacc[nt][(q2 & 1) ? 2 : 0];
                float p1 = sacc[nt][(q2 & 1) ? 3 : 1];
                (void)c0;
                uint32_t hw = cvtpk(p0, p1);
                Ahi[q2] = hw;
                float h0f = __int_as_float(hw << 16);
                float h1f = __int_as_float(hw & 0xFFFF0000u);
                Alo[q2] = cvtpk(p0 - h0f, p1 - h1f);
            }
            // reorder to fragment convention: A-frag regs = {r.k01, r8... }
            // built order above: q2=0: nt=2kb2 cols(0,1) rowsA? sacc[nt][0],[1] are rowA cols 2t,2t+1;
            // sacc[nt][2],[3] are rowB. Fragment needs:
            // A[0]=(rowA,k01) A[1]=(rowB? ...) -- m16n8k16 A: a0,a1 = rowA k0..1, rowA+8 k0..1? 
            // Keep the exact same ordering as R9 (verified): Ahi[0]=(p00,p01) Ahi[1]=(p02,p03)
            // Ahi[2]=(p10,p11) Ahi[3]=(p12,p13) with p0x=sacc[2kb][x], p1x=sacc[2kb+1][x]
            #pragma unroll
            for (int nd = 0; nd < 9; nd++) {
                int n = nd * 8 + g;
                uint4 vv = *(const uint4*)(sw + cur + VOFF + n * RSA + 16 * kb2 + 4 * t);
                uint32_t vb[2] = { vv.x, vv.y };
                uint32_t vl[2] = { vv.z, vv.w };
                MMA16816(accO[nd], Ahi, vb);
                MMA16816(accO[nd], Alo, vb);
                MMA16816(accO[nd], Ahi, vl);
            }
        }
        __syncthreads();
    }

    lA += __shfl_xor_sync(0xffffffffu, lA, 1);
    lA += __shfl_xor_sync(0xffffffffu, lA, 2);
    lB += __shfl_xor_sync(0xffffffffu, lB, 1);
    lB += __shfl_xor_sync(0xffffffffu, lB, 2);

    const float linA = 1.f / lA, linB = 1.f / lB;
    float ssA = 0.f, ssB = 0.f;
    #pragma unroll
    for (int nd = 0; nd < 9; nd++) {
        accO[nd][0] *= linA;  accO[nd][1] *= linA;
        accO[nd][2] *= linB;  accO[nd][3] *= linB;
        ssA += accO[nd][0] * accO[nd][0] + accO[nd][1] * accO[nd][1];
        ssB += accO[nd][2] * accO[nd][2] + accO[nd][3] * accO[nd][3];
    }
    ssA += __shfl_xor_sync(0xffffffffu, ssA, 1);
    ssA += __shfl_xor_sync(0xffffffffu, ssA, 2);
    ssB += __shfl_xor_sync(0xffffffffu, ssB, 1);
    ssB += __shfl_xor_sync(0xffffffffu, ssB, 2);
    float tA = __shfl_sync(0xffffffffu, accO[0][0], lane & ~3);
    float tB = __shfl_sync(0xffffffffu, accO[0][2], lane & ~3);
    float spA = ssA - tA * tA;
    float spB = ssB - tB * tB;
    float idnA = rsqrtf(fmaxf(KCURV * (tA * tA - spA), EPSf));
    float idnB = rsqrtf(fmaxf(KCURV * (tB * tB - spB), EPSf));

    const int rowA = b * 2048 + n0 + w * 16 + g;
    const int rowB = rowA + 8;
    #pragma unroll
    for (int nd = 0; nd < 9; nd++) {
        #pragma unroll
        for (int c = 0; c < 2; c++) {
            int d = nd * 8 + 2 * t + c;
            if (d >= 1 && d < 65) {
                OutCat[(size_t)rowA * 512 + h * 64 + d - 1] = accO[nd][c] * idnA;
                OutCat[(size_t)rowB * 512 + h * 64 + d - 1] = accO[nd][c + 2] * idnB;
            }
        }
    }
    if (t == 0) {
        HSS[rowA * 8 + h] = spA * idnA * idnA;
        HSS[rowB * 8 + h] = spB * idnB * idnB;
    }
}

// =====================================================================
// K3: output projection (unchanged)
// =====================================================================
__global__ __launch_bounds__(256) void outproj_mma(
    const float* __restrict__ bo, float* __restrict__ out)
{
    extern __shared__ uint32_t smw[];
    const int tid = threadIdx.x;
    const int wid = tid >> 5, lane = tid & 31;
    const int wm = wid & 3, wn = wid >> 2;
    const int g = lane >> 2, t = lane & 3;
    const int m0 = blockIdx.x * 128;
    const int c0 = blockIdx.y * 64;

    if (tid < 64) ((float*)(smw + WBIAS))[tid] = bo[c0 + tid];

    float acc[2][4][4];
    #pragma unroll
    for (int mt = 0; mt < 2; mt++)
        #pragma unroll
        for (int nt = 0; nt < 4; nt++)
            #pragma unroll
            for (int i = 0; i < 4; i++) acc[mt][nt][i] = 0.f;

    gemm_mainloop(smw, tid,
                  Chi + (size_t)m0 * KPAD, Clo + (size_t)m0 * KPAD,
                  WoTHi + (size_t)c0 * KPAD, WoTLo + (size_t)c0 * KPAD,
                  acc);

    const float* biass = (const float*)(smw + WBIAS);
    float* ssP = (float*)(smw + WSSP);

    __syncthreads();
    #pragma unroll
    for (int mt = 0; mt < 2; mt++) {
        #pragma unroll
        for (int half = 0; half < 2; half++) {
            int lrow = wm * 32 + mt * 16 + g + half * 8;
            int row = m0 + lrow;
            float ss = 0.f;
            #pragma unroll
            for (int nt = 0; nt < 4; nt++) {
                #pragma unroll
                for (int cc = 0; cc < 2; cc++) {
                    int col = wn * 32 + nt * 8 + 2 * t + cc;
                    float v = acc[mt][nt][half * 2 + cc] + biass[col];
                    out[(size_t)row * Dm + 1 + c0 + col] = v;
                    ss += v * v;
                }
            }
            ss += __shfl_xor_sync(0xffffffffu, ss, 1);
            ss += __shfl_xor_sync(0xffffffffu, ss, 2);
            if (t == 0) ssP[lrow * 2 + wn] = ss;
        }
    }
    __syncthreads();
    if (wn == 0 && t == 0) {
        #pragma unroll
        for (int mt = 0; mt < 2; mt++)
            #pragma unroll
            for (int half = 0; half < 2; half++) {
                int lrow = wm * 32 + mt * 16 + g + half * 8;
                int row = m0 + lrow;
                Part2[row * 8 + blockIdx.y] = ssP[lrow * 2] + ssP[lrow * 2 + 1];
            }
    }
}

__global__ void time_kernel(float* __restrict__ out)
{
    int row = blockIdx.x * 256 + threadIdx.x;
    if (row < Mrows) {
        float ss = 0.f;
        #pragma unroll
        for (int j = 0; j < 8; j++) ss += Part2[row * 8 + j];
        out[(size_t)row * Dm] = sqrtf(fmaxf(INVK + ss, EPSf));
    }
}

// =====================================================================
extern "C" void kernel_launch(void* const* d_in, const int* in_sizes, int n_in,
                              void* d_out, int out_size)
{
    const float* x  = (const float*)d_in[0];
    const float* Wq = (const float*)d_in[1];
    const float* bq = (const float*)d_in[2];
    const float* Wk = (const float*)d_in[3];
    const float* bk = (const float*)d_in[4];
    const float* Wv = (const float*)d_in[5];
    const float* bv = (const float*)d_in[6];
    const float* Wo = (const float*)d_in[7];
    const float* bo = (const float*)d_in[8];
    float* out = (float*)d_out;

    const int smem_gemm = WTOT * 4;
    const int smem_attn = 2 * ABUF * 4;     // 87552 bytes
    cudaFuncSetAttribute(qkv_mma, cudaFuncAttributeMaxDynamicSharedMemorySize, smem_gemm);
    cudaFuncSetAttribute(outproj_mma, cudaFuncAttributeMaxDynamicSharedMemorySize, smem_gemm);
    cudaFuncSetAttribute(attn_mma, cudaFuncAttributeMaxDynamicSharedMemorySize, smem_attn);

    cvt_in_kernel<<<5760, 1024>>>(Wq, Wk, Wv, Wo, x);
    qkv_mma<<<dim3(64, 24), 256, smem_gemm>>>(bq, bk, bv);
    vtrans<<<dim3(32, 32), 128>>>();
    attn_mma<<<dim3(16, 32), 256, smem_attn>>>();
    cvt_cat_kernel<<<4608, 1024>>>();
    outproj_mma<<<dim3(64, 8), 256, smem_gemm>>>(bo, out);
    time_kernel<<<32, 256>>>(out);
}

// round 11
// speedup vs baseline: 2.4094x; 1.0347x over previous
#include <cuda_runtime.h>
#include <cuda_bf16.h>
#include <math.h>
#include <stdint.h>

#define Bsz   4
#define Nseq  2048
#define Dm    513
#define Hh    8
#define Mrows 8192
#define KPAD  576
#define INVK  10.0f
#define KCURV 0.1f
#define EPSf  1e-9f
#define S2f   0.18033688011112042f   // 0.125 * log2(e)

// ---------------- device scratch ----------------
__device__ float OutCat[(size_t)Mrows*512];
__device__ float HSS[Mrows*Hh];
__device__ float Part2[Mrows*8];
__device__ __nv_bfloat16 Xhi[(size_t)Mrows*KPAD];
__device__ __nv_bfloat16 Xlo[(size_t)Mrows*KPAD];
__device__ __nv_bfloat16 WqkvHi[24*64*KPAD];
__device__ __nv_bfloat16 WqkvLo[24*64*KPAD];
__device__ __nv_bfloat16 WoTHi[512*KPAD];
__device__ __nv_bfloat16 WoTLo[512*KPAD];
__device__ __nv_bfloat16 Chi[(size_t)Mrows*KPAD];
__device__ __nv_bfloat16 Clo[(size_t)Mrows*KPAD];
__device__ uint32_t QKiW[(size_t)32*2048*64];
__device__ uint32_t KKiW[(size_t)32*2048*64];
__device__ float Tqg[32*2048];
__device__ float Tkg[32*2048];
__device__ __nv_bfloat16 Vh_[(size_t)32*2048*65];
__device__ __nv_bfloat16 Vl_[(size_t)32*2048*65];
__device__ __nv_bfloat16 VTiE[(size_t)32*72*32*128];

__device__ __forceinline__ void bsplit(float v, __nv_bfloat16& h, __nv_bfloat16& l) {
    h = __float2bfloat16(v);
    l = __float2bfloat16(v - __bfloat162float(h));
}
__device__ __forceinline__ uint32_t pack2(__nv_bfloat16 a, __nv_bfloat16 b) {
    __nv_bfloat162 t2; t2.x = a; t2.y = b;
    uint32_t r; memcpy(&r, &t2, 4); return r;
}
__device__ __forceinline__ uint32_t cvtpk(float lo, float hi) {
    uint32_t r;
    asm("cvt.rn.bf16x2.f32 %0, %1, %2;" : "=r"(r) : "f"(hi), "f"(lo));
    return r;
}

__device__ __forceinline__ float exp2p(float y) {
    y = fmaxf(y, -120.f);
    float z = y + 12582912.f;
    int ib = __float_as_int(z);
    float n = z - 12582912.f;
    float f = y - n;
    float p = 1.3333558146e-3f;
    p = fmaf(p, f, 9.6181291076e-3f);
    p = fmaf(p, f, 5.5504108664e-2f);
    p = fmaf(p, f, 2.4022650696e-1f);
    p = fmaf(p, f, 6.9314718056e-1f);
    p = fmaf(p, f, 1.0f);
    return __int_as_float(__float_as_int(p) + (ib << 23));
}

#define MMA16816(D, A, B) \
    asm volatile("mma.sync.aligned.m16n8k16.row.col.f32.bf16.bf16.f32 " \
        "{%0,%1,%2,%3}, {%4,%5,%6,%7}, {%8,%9}, {%0,%1,%2,%3};" \
        : "+f"((D)[0]), "+f"((D)[1]), "+f"((D)[2]), "+f"((D)[3]) \
        : "r"((A)[0]), "r"((A)[1]), "r"((A)[2]), "r"((A)[3]), \
          "r"((B)[0]), "r"((B)[1]))

#define CP_ASYNC16(dst, src) \
    asm volatile("cp.async.cg.shared.global [%0], [%1], 16;" :: "r"(dst), "l"(src))
#define CP_COMMIT() asm volatile("cp.async.commit_group;" ::: "memory")
#define CP_WAIT(n)  asm volatile("cp.async.wait_group %0;" :: "n"(n) : "memory")

#define RS 36
#define WA_HI 0
#define WA_LO 4608
#define WB_HI 9216
#define WB_LO 11520
#define WBIAS 13824
#define WSSP  13888
#define WTOT  14144

// attention smem geometry (words)
#define RSA   80
#define VOFF  5120
#define TKOFF 10880
#define ABUF  10944

__device__ __forceinline__ int ipos(int j) {
    return 16 * (j >> 3) + 4 * (j & 3) + ((j >> 2) & 1);
}

// =====================================================================
// merged input conversion
// =====================================================================
__global__ void cvt_in_kernel(const float* __restrict__ Wq, const float* __restrict__ Wk,
                              const float* __restrict__ Wv, const float* __restrict__ Wo,
                              const float* __restrict__ x)
{
    const int totW1 = 24 * 64 * KPAD;
    const int totW  = totW1 + 512 * KPAD;
    const size_t totX = (size_t)Mrows * KPAD;
    const size_t total = totW + totX;
    for (size_t idx = (size_t)blockIdx.x * blockDim.x + threadIdx.x; idx < total;
         idx += (size_t)gridDim.x * blockDim.x) {
        if (idx < (size_t)totW1) {
            int i = (int)idx;
            int k = i % KPAD;
            int t = i / KPAD;
            int n = t % 64;
            int s = t / 64;
            int which = s >> 3, h = s & 7;
            const float* W = (which == 0) ? Wq : (which == 1) ? Wk : Wv;
            float v = (k < Dm) ? W[((size_t)h * Dm + k) * 64 + n] : 0.f;
            bsplit(v, WqkvHi[i], WqkvLo[i]);
        } else if (idx < (size_t)totW) {
            int i2 = (int)idx - totW1;
            int k = i2 % KPAD;
            int n = i2 / KPAD;
            float v = (k < Dm) ? Wo[(size_t)k * 512 + n] : 0.f;
            bsplit(v, WoTHi[i2], WoTLo[i2]);
        } else {
            size_t i3 = idx - totW;
            int k = (int)(i3 % KPAD);
            size_t row = i3 / KPAD;
            float v = (k < Dm) ? x[row * Dm + k] : 0.f;
            bsplit(v, Xhi[i3], Xlo[i3]);
        }
    }
}

__global__ void cvt_cat_kernel()
{
    const size_t total = (size_t)Mrows * KPAD;
    for (size_t idx = (size_t)blockIdx.x * blockDim.x + threadIdx.x; idx < total;
         idx += (size_t)gridDim.x * blockDim.x) {
        int k = (int)(idx % KPAD);
        size_t row = idx / KPAD;
        float v;
        if (k == 0) {
            float ss = 0.f;
            #pragma unroll
            for (int hh = 0; hh < 8; hh++) ss += HSS[row * 8 + hh];
            v = sqrtf(fmaxf(INVK + ss, EPSf));
        } else if (k < Dm) {
            v = OutCat[row * 512 + k - 1];
        } else v = 0.f;
        bsplit(v, Chi[idx], Clo[idx]);
    }
}

// =====================================================================
// projection GEMM mainloop (unchanged, proven)
// =====================================================================
__device__ __forceinline__ void copyA(uint32_t* smw, int dst_w,
                                      const __nv_bfloat16* __restrict__ src, int tid)
{
    for (int i = tid; i < 1024; i += 256) {
        int r = i >> 3, q = i & 7;
        uint4 v = *(const uint4*)(src + (size_t)r * KPAD + q * 8);
        *(uint4*)(smw + dst_w + r * RS + q * 4) = v;
    }
}
__device__ __forceinline__ void copyB(uint32_t* smw, int dst_w,
                                      const __nv_bfloat16* __restrict__ src, int tid)
{
    for (int i = tid; i < 512; i += 256) {
        int r = i >> 3, q = i & 7;
        uint4 v = *(const uint4*)(src + (size_t)r * KPAD + q * 8);
        *(uint4*)(smw + dst_w + r * RS + q * 4) = v;
    }
}

__device__ __forceinline__ void gemm_mainloop(
    uint32_t* smw, int tid,
    const __nv_bfloat16* Ah, const __nv_bfloat16* Al,
    const __nv_bfloat16* Bh, const __nv_bfloat16* Bl,
    float acc[2][4][4])
{
    const int wid = tid >> 5, lane = tid & 31;
    const int wm = wid & 3, wn = wid >> 2;
    const int g = lane >> 2, t = lane & 3;

    for (int c = 0; c < 9; c++) {
        const int k0 = c * 64;
        __syncthreads();
        copyA(smw, WA_HI, Ah + k0, tid);
        copyA(smw, WA_LO, Al + k0, tid);
        copyB(smw, WB_HI, Bh + k0, tid);
        copyB(smw, WB_LO, Bl + k0, tid);
        __syncthreads();

        #pragma unroll
        for (int ks = 0; ks < 4; ks++) {
            uint32_t ah[2][4], al[2][4], bh[4][2], bl[4][2];
            const int kw = ks * 8 + t;
            #pragma unroll
            for (int mt = 0; mt < 2; mt++) {
                int r = wm * 32 + mt * 16 + g;
                ah[mt][0] = smw[WA_HI + r * RS + kw];
                ah[mt][1] = smw[WA_HI + (r + 8) * RS + kw];
                ah[mt][2] = smw[WA_HI + r * RS + kw + 4];
                ah[mt][3] = smw[WA_HI + (r + 8) * RS + kw + 4];
                al[mt][0] = smw[WA_LO + r * RS + kw];
                al[mt][1] = smw[WA_LO + (r + 8) * RS + kw];
                al[mt][2] = smw[WA_LO + r * RS + kw + 4];
                al[mt][3] = smw[WA_LO + (r + 8) * RS + kw + 4];
            }
            #pragma unroll
            for (int nt = 0; nt < 4; nt++) {
                int n = wn * 32 + nt * 8 + g;
                bh[nt][0] = smw[WB_HI + n * RS + kw];
                bh[nt][1] = smw[WB_HI + n * RS + kw + 4];
                bl[nt][0] = smw[WB_LO + n * RS + kw];
                bl[nt][1] = smw[WB_LO + n * RS + kw + 4];
            }
            #pragma unroll
            for (int mt = 0; mt < 2; mt++)
                #pragma unroll
                for (int nt = 0; nt < 4; nt++) {
                    MMA16816(acc[mt][nt], ah[mt], bh[nt]);
                    MMA16816(acc[mt][nt], ah[mt], bl[nt]);
                    MMA16816(acc[mt][nt], al[mt], bh[nt]);
                }
        }
    }
}

// =====================================================================
// K1: QKV GEMM (unchanged from R10)
// =====================================================================
__global__ __launch_bounds__(256) void qkv_mma(
    const float* __restrict__ bq, const float* __restrict__ bk, const float* __restrict__ bv)
{
    extern __shared__ uint32_t smw[];
    const int tid = threadIdx.x;
    const int wid = tid >> 5, lane = tid & 31;
    const int wm = wid & 3, wn = wid >> 2;
    const int g = lane >> 2, t = lane & 3;
    const int which = blockIdx.y % 3;
    const int h     = blockIdx.y / 3;
    const int slot  = which * 8 + h;
    const int m0    = blockIdx.x * 128;

    {
        const float* bias = (which == 0) ? bq : (which == 1) ? bk : bv;
        if (tid < 64) ((float*)(smw + WBIAS))[tid] = bias[h * 64 + tid];
    }

    float acc[2][4][4];
    #pragma unroll
    for (int mt = 0; mt < 2; mt++)
        #pragma unroll
        for (int nt = 0; nt < 4; nt++)
            #pragma unroll
            for (int i = 0; i < 4; i++) acc[mt][nt][i] = 0.f;

    gemm_mainloop(smw, tid,
                  Xhi + (size_t)m0 * KPAD, Xlo + (size_t)m0 * KPAD,
                  WqkvHi + (size_t)slot * 64 * KPAD, WqkvLo + (size_t)slot * 64 * KPAD,
                  acc);

    const float* biass = (const float*)(smw + WBIAS);
    float* ssP = (float*)(smw + WSSP);

    __syncthreads();
    #pragma unroll
    for (int mt = 0; mt < 2; mt++) {
        #pragma unroll
        for (int half = 0; half < 2; half++) {
            int lrow = wm * 32 + mt * 16 + g + half * 8;
            int row = m0 + lrow;
            int b = row >> 11, n = row & (Nseq - 1);
            size_t rbase = (size_t)(b * 8 + h) * 2048 + n;
            float ss = 0.f;
            #pragma unroll
            for (int nt = 0; nt < 4; nt++) {
                int col0 = wn * 32 + nt * 8 + 2 * t;
                float v0 = acc[mt][nt][half * 2 + 0] + biass[col0];
                float v1 = acc[mt][nt][half * 2 + 1] + biass[col0 + 1];
                ss += v0 * v0 + v1 * v1;
                __nv_bfloat16 h0, l0, h1, l1;
                bsplit(v0, h0, l0); bsplit(v1, h1, l1);
                if (which == 2) {
                    Vh_[rbase * 65 + 1 + col0] = h0;  Vh_[rbase * 65 + 2 + col0] = h1;
                    Vl_[rbase * 65 + 1 + col0] = l0;  Vl_[rbase * 65 + 2 + col0] = l1;
                } else {
                    int j = col0 >> 1;
                    int pos = ipos(j);
                    uint32_t* dst = (which == 0) ? QKiW : KKiW;
                    dst[rbase * 64 + pos]     = pack2(h0, h1);
                    dst[rbase * 64 + pos + 2] = pack2(l0, l1);
                }
            }
            ss += __shfl_xor_sync(0xffffffffu, ss, 1);
            ss += __shfl_xor_sync(0xffffffffu, ss, 2);
            if (t == 0) ssP[lrow * 2 + wn] = ss;
        }
    }
    __syncthreads();
    if (wn == 0 && t == 0) {
        #pragma unroll
        for (int mt = 0; mt < 2; mt++)
            #pragma unroll
            for (int half = 0; half < 2; half++) {
                int lrow = wm * 32 + mt * 16 + g + half * 8;
                int row = m0 + lrow;
                int b = row >> 11, n = row & (Nseq - 1);
                size_t rbase = (size_t)(b * 8 + h) * 2048 + n;
                float ss = ssP[lrow * 2] + ssP[lrow * 2 + 1];
                float tv = sqrtf(fmaxf(INVK + ss, EPSf));
                if (which == 0) Tqg[rbase] = tv;
                else if (which == 1) Tkg[rbase] = tv;
                else { bsplit(tv, Vh_[rbase * 65], Vl_[rbase * 65]); }
            }
    }
}

// =====================================================================
// V transpose (unchanged)
// =====================================================================
__global__ __launch_bounds__(128) void vtrans()
{
    __shared__ __nv_bfloat16 sh[64][73];
    __shared__ __nv_bfloat16 sl[64][73];
    const int bh = blockIdx.y, k0 = blockIdx.x * 64, tid = threadIdx.x;
    const int blk = blockIdx.x;
    const __nv_bfloat16 z = __float2bfloat16(0.f);
    for (int i = tid; i < 64 * 72; i += 128) {
        int r = i / 72, d = i % 72;
        sh[r][d] = (d < 65) ? Vh_[((size_t)bh * 2048 + k0 + r) * 65 + d] : z;
        sl[r][d] = (d < 65) ? Vl_[((size_t)bh * 2048 + k0 + r) * 65 + d] : z;
    }
    __syncthreads();
    for (int i = tid; i < 72 * 64; i += 128) {
        int d = i >> 6, k = i & 63;
        int jj = k >> 1, e = k & 1;
        int pos = ipos(jj);
        size_t eb = (((size_t)bh * 72 + d) * 32 + blk) * 128;
        VTiE[eb + pos * 2 + e]       = sh[k][d];
        VTiE[eb + (pos + 2) * 2 + e] = sl[k][d];
    }
}

// =====================================================================
// K2: pipelined flash attention, softmax fused into PV chunks
// =====================================================================
__device__ __forceinline__ void attn_issue_tile(
    uint32_t smb, int bufw, int kt, int tid, int bh, size_t base)
{
    const int k0 = kt * 64;
    for (int i = tid; i < 2192; i += 256) {
        uint32_t dstw; const void* src;
        if (i < 1024) {
            int r = i >> 4, ch = i & 15;
            dstw = bufw + r * RSA + ch * 4;
            src = KKiW + (base + k0 + r) * 64 + ch * 4;
        } else if (i < 2176) {
            int j = i - 1024, d = j >> 4, ch = j & 15;
            dstw = bufw + VOFF + d * RSA + ch * 4;
            src = VTiE + (((size_t)bh * 72 + d) * 32 + kt) * 128 + ch * 8;
        } else {
            int j = i - 2176;
            dstw = bufw + TKOFF + j * 4;
            src = Tkg + base + k0 + j * 4;
        }
        CP_ASYNC16(smb + dstw * 4, src);
    }
}

__global__ __launch_bounds__(256, 2) void attn_mma()
{
    extern __shared__ uint32_t sw[];
    const int tid = threadIdx.x;
    const int w = tid >> 5, lane = tid & 31;
    const int g = lane >> 2, t = lane & 3;
    const int bh = blockIdx.y;
    const int b = bh >> 3, h = bh & 7;
    const int n0 = blockIdx.x * 128;
    const size_t base = (size_t)bh * 2048;
    uint32_t smb;
    asm("{ .reg .u64 tt; cvta.to.shared.u64 tt, %1; cvt.u32.u64 %0, tt; }"
        : "=r"(smb) : "l"(sw));

    attn_issue_tile(smb, 0, 0, tid, bh, base);
    CP_COMMIT();

    for (int i = tid; i < 2048; i += 256) {
        int r = i >> 4, ch = i & 15;
        *(uint4*)(sw + ABUF + r * RSA + ch * 4) =
            *(const uint4*)(QKiW + (base + n0 + r) * 64 + ch * 4);
    }
    __syncthreads();
    uint32_t qh[4][4], ql[4][4];
    const int r0 = w * 16 + g;
    #pragma unroll
    for (int ks = 0; ks < 4; ks++) {
        uint4 a  = *(const uint4*)(sw + ABUF + r0 * RSA + 16 * ks + 4 * t);
        uint4 b2 = *(const uint4*)(sw + ABUF + (r0 + 8) * RSA + 16 * ks + 4 * t);
        qh[ks][0] = a.x;  qh[ks][1] = b2.x;  qh[ks][2] = a.y;  qh[ks][3] = b2.y;
        ql[ks][0] = a.z;  ql[ks][1] = b2.z;  ql[ks][2] = a.w;  ql[ks][3] = b2.w;
    }
    const float tqa = Tqg[base + n0 + r0];
    const float tqb = Tqg[base + n0 + r0 + 8];
    __syncthreads();

    float accO[9][4];
    #pragma unroll
    for (int nd = 0; nd < 9; nd++)
        #pragma unroll
        for (int c = 0; c < 4; c++) accO[nd][c] = 0.f;
    float lA = 0.f, lB = 0.f;

    for (int kt = 0; kt < 32; kt++) {
        const int cur = (kt & 1) * ABUF;
        if (kt < 31) {
            attn_issue_tile(smb, ((kt + 1) & 1) * ABUF, kt + 1, tid, bh, base);
            CP_COMMIT();
            CP_WAIT(1);
        } else {
            CP_WAIT(0);
        }
        __syncthreads();

        const float* tks = (const float*)(sw + cur + TKOFF);

        float sacc[8][4];
        #pragma unroll
        for (int nt = 0; nt < 8; nt++)
            #pragma unroll
            for (int c = 0; c < 4; c++) sacc[nt][c] = 0.f;

        #pragma unroll
        for (int ks = 0; ks < 4; ks++) {
            #pragma unroll
            for (int nt = 0; nt < 8; nt++) {
                int n = nt * 8 + g;
                uint4 kv = *(const uint4*)(sw + cur + n * RSA + 16 * ks + 4 * t);
                uint32_t kb[2]  = { kv.x, kv.y };
                uint32_t klr[2] = { kv.z, kv.w };
                MMA16816(sacc[nt], qh[ks], kb);
                MMA16816(sacc[nt], qh[ks], klr);
                MMA16816(sacc[nt], ql[ks], kb);
            }
        }

        // fused softmax + PV per kb2 chunk: exp/P-split of chunk kb2+1
        // issues while chunk kb2's 27 MMAs drain the tensor pipe.
        #pragma unroll
        for (int kb2 = 0; kb2 < 4; kb2++) {
            uint32_t Ahi[4], Alo[4];
            #pragma unroll
            for (int half = 0; half < 2; half++) {
                const int nt = 2 * kb2 + half;
                float2 tk = *(const float2*)(tks + nt * 8 + 2 * t);
                float e0 = exp2p((sacc[nt][0] - tqa * tk.x) * S2f);
                float e1 = exp2p((sacc[nt][1] - tqa * tk.y) * S2f);
                float e2 = exp2p((sacc[nt][2] - tqb * tk.x) * S2f);
                float e3 = exp2p((sacc[nt][3] - tqb * tk.y) * S2f);
                lA += e0 + e1;
                lB += e2 + e3;
                uint32_t hw0 = cvtpk(e0, e1);
                uint32_t hw1 = cvtpk(e2, e3);
                Ahi[half * 2 + 0] = hw0;
                Ahi[half * 2 + 1] = hw1;
                float h00 = __int_as_float(hw0 << 16);
                float h01 = __int_as_float(hw0 & 0xFFFF0000u);
                float h10 = __int_as_float(hw1 << 16);
                float h11 = __int_as_float(hw1 & 0xFFFF0000u);
                Alo[half * 2 + 0] = cvtpk(e0 - h00, e1 - h01);
                Alo[half * 2 + 1] = cvtpk(e2 - h10, e3 - h11);
            }
            #pragma unroll
            for (int nd = 0; nd < 9; nd++) {
                int n = nd * 8 + g;
                uint4 vv = *(const uint4*)(sw + cur + VOFF + n * RSA + 16 * kb2 + 4 * t);
                uint32_t vb[2] = { vv.x, vv.y };
                uint32_t vl[2] = { vv.z, vv.w };
                MMA16816(accO[nd], Ahi, vb);
                MMA16816(accO[nd], Alo, vb);
                MMA16816(accO[nd], Ahi, vl);
            }
        }
        __syncthreads();
    }

    lA += __shfl_xor_sync(0xffffffffu, lA, 1);
    lA += __shfl_xor_sync(0xffffffffu, lA, 2);
    lB += __shfl_xor_sync(0xffffffffu, lB, 1);
    lB += __shfl_xor_sync(0xffffffffu, lB, 2);

    const float linA = 1.f / lA, linB = 1.f / lB;
    float ssA = 0.f, ssB = 0.f;
    #pragma unroll
    for (int nd = 0; nd < 9; nd++) {
        accO[nd][0] *= linA;  accO[nd][1] *= linA;
        accO[nd][2] *= linB;  accO[nd][3] *= linB;
        ssA += accO[nd][0] * accO[nd][0] + accO[nd][1] * accO[nd][1];
        ssB += accO[nd][2] * accO[nd][2] + accO[nd][3] * accO[nd][3];
    }
    ssA += __shfl_xor_sync(0xffffffffu, ssA, 1);
    ssA += __shfl_xor_sync(0xffffffffu, ssA, 2);
    ssB += __shfl_xor_sync(0xffffffffu, ssB, 1);
    ssB += __shfl_xor_sync(0xffffffffu, ssB, 2);
    float tA = __shfl_sync(0xffffffffu, accO[0][0], lane & ~3);
    float tB = __shfl_sync(0xffffffffu, accO[0][2], lane & ~3);
    float spA = ssA - tA * tA;
    float spB = ssB - tB * tB;
    float idnA = rsqrtf(fmaxf(KCURV * (tA * tA - spA), EPSf));
    float idnB = rsqrtf(fmaxf(KCURV * (tB * tB - spB), EPSf));

    const int rowA = b * 2048 + n0 + w * 16 + g;
    const int rowB = rowA + 8;
    #pragma unroll
    for (int nd = 0; nd < 9; nd++) {
        #pragma unroll
        for (int c = 0; c < 2; c++) {
            int d = nd * 8 + 2 * t + c;
            if (d >= 1 && d < 65) {
                OutCat[(size_t)rowA * 512 + h * 64 + d - 1] = accO[nd][c] * idnA;
                OutCat[(size_t)rowB * 512 + h * 64 + d - 1] = accO[nd][c + 2] * idnB;
            }
        }
    }
    if (t == 0) {
        HSS[rowA * 8 + h] = spA * idnA * idnA;
        HSS[rowB * 8 + h] = spB * idnB * idnB;
    }
}

// =====================================================================
// K3: output projection (unchanged)
// =====================================================================
__global__ __launch_bounds__(256) void outproj_mma(
    const float* __restrict__ bo, float* __restrict__ out)
{
    extern __shared__ uint32_t smw[];
    const int tid = threadIdx.x;
    const int wid = tid >> 5, lane = tid & 31;
    const int wm = wid & 3, wn = wid >> 2;
    const int g = lane >> 2, t = lane & 3;
    const int m0 = blockIdx.x * 128;
    const int c0 = blockIdx.y * 64;

    if (tid < 64) ((float*)(smw + WBIAS))[tid] = bo[c0 + tid];

    float acc[2][4][4];
    #pragma unroll
    for (int mt = 0; mt < 2; mt++)
        #pragma unroll
        for (int nt = 0; nt < 4; nt++)
            #pragma unroll
            for (int i = 0; i < 4; i++) acc[mt][nt][i] = 0.f;

    gemm_mainloop(smw, tid,
                  Chi + (size_t)m0 * KPAD, Clo + (size_t)m0 * KPAD,
                  WoTHi + (size_t)c0 * KPAD, WoTLo + (size_t)c0 * KPAD,
                  acc);

    const float* biass = (const float*)(smw + WBIAS);
    float* ssP = (float*)(smw + WSSP);

    __syncthreads();
    #pragma unroll
    for (int mt = 0; mt < 2; mt++) {
        #pragma unroll
        for (int half = 0; half < 2; half++) {
            int lrow = wm * 32 + mt * 16 + g + half * 8;
            int row = m0 + lrow;
            float ss = 0.f;
            #pragma unroll
            for (int nt = 0; nt < 4; nt++) {
                #pragma unroll
                for (int cc = 0; cc < 2; cc++) {
                    int col = wn * 32 + nt * 8 + 2 * t + cc;
                    float v = acc[mt][nt][half * 2 + cc] + biass[col];
                    out[(size_t)row * Dm + 1 + c0 + col] = v;
                    ss += v * v;
                }
            }
            ss += __shfl_xor_sync(0xffffffffu, ss, 1);
            ss += __shfl_xor_sync(0xffffffffu, ss, 2);
            if (t == 0) ssP[lrow * 2 + wn] = ss;
        }
    }
    __syncthreads();
    if (wn == 0 && t == 0) {
        #pragma unroll
        for (int mt = 0; mt < 2; mt++)
            #pragma unroll
            for (int half = 0; half < 2; half++) {
                int lrow = wm * 32 + mt * 16 + g + half * 8;
                int row = m0 + lrow;
                Part2[row * 8 + blockIdx.y] = ssP[lrow * 2] + ssP[lrow * 2 + 1];
            }
    }
}

__global__ void time_kernel(float* __restrict__ out)
{
    int row = blockIdx.x * 256 + threadIdx.x;
    if (row < Mrows) {
        float ss = 0.f;
        #pragma unroll
        for (int j = 0; j < 8; j++) ss += Part2[row * 8 + j];
        out[(size_t)row * Dm] = sqrtf(fmaxf(INVK + ss, EPSf));
    }
}

// =====================================================================
extern "C" void kernel_launch(void* const* d_in, const int* in_sizes, int n_in,
                              void* d_out, int out_size)
{
    const float* x  = (const float*)d_in[0];
    const float* Wq = (const float*)d_in[1];
    const float* bq = (const float*)d_in[2];
    const float* Wk = (const float*)d_in[3];
    const float* bk = (const float*)d_in[4];
    const float* Wv = (const float*)d_in[5];
    const float* bv = (const float*)d_in[6];
    const float* Wo = (const float*)d_in[7];
    const float* bo = (const float*)d_in[8];
    float* out = (float*)d_out;

    const int smem_gemm = WTOT * 4;
    const int smem_attn = 2 * ABUF * 4;
    cudaFuncSetAttribute(qkv_mma, cudaFuncAttributeMaxDynamicSharedMemorySize, smem_gemm);
    cudaFuncSetAttribute(outproj_mma, cudaFuncAttributeMaxDynamicSharedMemorySize, smem_gemm);
    cudaFuncSetAttribute(attn_mma, cudaFuncAttributeMaxDynamicSharedMemorySize, smem_attn);

    cvt_in_kernel<<<5760, 1024>>>(Wq, Wk, Wv, Wo, x);
    qkv_mma<<<dim3(64, 24), 256, smem_gemm>>>(bq, bk, bv);
    vtrans<<<dim3(32, 32), 128>>>();
    attn_mma<<<dim3(16, 32), 256, smem_attn>>>();
    cvt_cat_kernel<<<4608, 1024>>>();
    outproj_mma<<<dim3(64, 8), 256, smem_gemm>>>(bo, out);
    time_kernel<<<32, 256>>>(out);
}

// round 12
// speedup vs baseline: 2.6359x; 1.0940x over previous
#include <cuda_runtime.h>
#include <cuda_bf16.h>
#include <math.h>
#include <stdint.h>

#define Bsz   4
#define Nseq  2048
#define Dm    513
#define Hh    8
#define Mrows 8192
#define KPAD  576
#define INVK  10.0f
#define KCURV 0.1f
#define EPSf  1e-9f
#define S2f   0.18033688011112042f   // 0.125 * log2(e)

// ---------------- device scratch ----------------
__device__ float OutCat[(size_t)Mrows*512];
__device__ float HSS[Mrows*Hh];
__device__ float Part2[Mrows*8];
__device__ __nv_bfloat16 Xhi[(size_t)Mrows*KPAD];
__device__ __nv_bfloat16 Xlo[(size_t)Mrows*KPAD];
__device__ __nv_bfloat16 WqkvHi[24*64*KPAD];
__device__ __nv_bfloat16 WqkvLo[24*64*KPAD];
__device__ __nv_bfloat16 WoTHi[512*KPAD];
__device__ __nv_bfloat16 WoTLo[512*KPAD];
__device__ __nv_bfloat16 Chi[(size_t)Mrows*KPAD];
__device__ __nv_bfloat16 Clo[(size_t)Mrows*KPAD];
__device__ uint32_t QKiW[(size_t)32*2048*64];
__device__ uint32_t KKiW[(size_t)32*2048*64];
__device__ float Tqg[32*2048];
__device__ float Tkg[32*2048];
__device__ __nv_bfloat16 Vh_[(size_t)32*2048*65];
__device__ __nv_bfloat16 Vl_[(size_t)32*2048*65];
__device__ __nv_bfloat16 VTiE[(size_t)32*72*32*128];

__device__ __forceinline__ void bsplit(float v, __nv_bfloat16& h, __nv_bfloat16& l) {
    h = __float2bfloat16(v);
    l = __float2bfloat16(v - __bfloat162float(h));
}
__device__ __forceinline__ uint32_t pack2(__nv_bfloat16 a, __nv_bfloat16 b) {
    __nv_bfloat162 t2; t2.x = a; t2.y = b;
    uint32_t r; memcpy(&r, &t2, 4); return r;
}
__device__ __forceinline__ uint32_t cvtpk(float lo, float hi) {
    uint32_t r;
    asm("cvt.rn.bf16x2.f32 %0, %1, %2;" : "=r"(r) : "f"(hi), "f"(lo));
    return r;
}

__device__ __forceinline__ float exp2p(float y) {
    y = fmaxf(y, -120.f);
    float z = y + 12582912.f;
    int ib = __float_as_int(z);
    float n = z - 12582912.f;
    float f = y - n;
    float p = 1.3333558146e-3f;
    p = fmaf(p, f, 9.6181291076e-3f);
    p = fmaf(p, f, 5.5504108664e-2f);
    p = fmaf(p, f, 2.4022650696e-1f);
    p = fmaf(p, f, 6.9314718056e-1f);
    p = fmaf(p, f, 1.0f);
    return __int_as_float(__float_as_int(p) + (ib << 23));
}

#define MMA16816(D, A, B) \
    asm volatile("mma.sync.aligned.m16n8k16.row.col.f32.bf16.bf16.f32 " \
        "{%0,%1,%2,%3}, {%4,%5,%6,%7}, {%8,%9}, {%0,%1,%2,%3};" \
        : "+f"((D)[0]), "+f"((D)[1]), "+f"((D)[2]), "+f"((D)[3]) \
        : "r"((A)[0]), "r"((A)[1]), "r"((A)[2]), "r"((A)[3]), \
          "r"((B)[0]), "r"((B)[1]))

#define CP_ASYNC16(dst, src) \
    asm volatile("cp.async.cg.shared.global [%0], [%1], 16;" :: "r"(dst), "l"(src))
#define CP_COMMIT() asm volatile("cp.async.commit_group;" ::: "memory")
#define CP_WAIT(n)  asm volatile("cp.async.wait_group %0;" :: "n"(n) : "memory")

#define RS 36
#define WA_HI 0
#define WA_LO 4608
#define WB_HI 9216
#define WB_LO 11520
#define WBIAS 13824
#define WSSP  13888
#define WTOT  14144

// attention smem geometry (words)
#define RSA   80
#define VOFF  5120
#define TKOFF 10880
#define ABUF  10944

__device__ __forceinline__ int ipos(int j) {
    return 16 * (j >> 3) + 4 * (j & 3) + ((j >> 2) & 1);
}

// =====================================================================
// input conversion, row-indexed (no div/mod in the hot path)
// grid: 1536 Wqkv rows | 512 Wo rows | 8192 X rows; 576 threads = k
// =====================================================================
__global__ __launch_bounds__(576) void cvt_in_kernel(
    const float* __restrict__ Wq, const float* __restrict__ Wk,
    const float* __restrict__ Wv, const float* __restrict__ Wo,
    const float* __restrict__ x)
{
    const int bid = blockIdx.x;
    const int k = threadIdx.x;
    if (bid < 1536) {
        int n = bid & 63;
        int s = bid >> 6;                 // slot = which*8+h
        int which = s >> 3, h = s & 7;
        const float* W = (which == 0) ? Wq : (which == 1) ? Wk : Wv;
        float v = (k < Dm) ? W[((size_t)h * Dm + k) * 64 + n] : 0.f;
        size_t i = (size_t)bid * KPAD + k;
        bsplit(v, WqkvHi[i], WqkvLo[i]);
    } else if (bid < 2048) {
        int n = bid - 1536;
        float v = (k < Dm) ? Wo[(size_t)k * 512 + n] : 0.f;
        size_t i = (size_t)n * KPAD + k;
        bsplit(v, WoTHi[i], WoTLo[i]);
    } else {
        size_t row = bid - 2048;
        float v = (k < Dm) ? x[row * Dm + k] : 0.f;
        size_t i = row * KPAD + k;
        bsplit(v, Xhi[i], Xlo[i]);
    }
}

// grid: 8192 rows; 576 threads = k
__global__ __launch_bounds__(576) void cvt_cat_kernel()
{
    const size_t row = blockIdx.x;
    const int k = threadIdx.x;
    float v;
    if (k == 0) {
        float ss = 0.f;
        #pragma unroll
        for (int hh = 0; hh < 8; hh++) ss += HSS[row * 8 + hh];
        v = sqrtf(fmaxf(INVK + ss, EPSf));
    } else if (k < Dm) {
        v = OutCat[row * 512 + k - 1];
    } else v = 0.f;
    size_t i = row * KPAD + k;
    bsplit(v, Chi[i], Clo[i]);
}

// =====================================================================
// projection GEMM mainloop (unchanged, proven)
// =====================================================================
__device__ __forceinline__ void copyA(uint32_t* smw, int dst_w,
                                      const __nv_bfloat16* __restrict__ src, int tid)
{
    for (int i = tid; i < 1024; i += 256) {
        int r = i >> 3, q = i & 7;
        uint4 v = *(const uint4*)(src + (size_t)r * KPAD + q * 8);
        *(uint4*)(smw + dst_w + r * RS + q * 4) = v;
    }
}
__device__ __forceinline__ void copyB(uint32_t* smw, int dst_w,
                                      const __nv_bfloat16* __restrict__ src, int tid)
{
    for (int i = tid; i < 512; i += 256) {
        int r = i >> 3, q = i & 7;
        uint4 v = *(const uint4*)(src + (size_t)r * KPAD + q * 8);
        *(uint4*)(smw + dst_w + r * RS + q * 4) = v;
    }
}

__device__ __forceinline__ void gemm_mainloop(
    uint32_t* smw, int tid,
    const __nv_bfloat16* Ah, const __nv_bfloat16* Al,
    const __nv_bfloat16* Bh, const __nv_bfloat16* Bl,
    float acc[2][4][4])
{
    const int wid = tid >> 5, lane = tid & 31;
    const int wm = wid & 3, wn = wid >> 2;
    const int g = lane >> 2, t = lane & 3;

    for (int c = 0; c < 9; c++) {
        const int k0 = c * 64;
        __syncthreads();
        copyA(smw, WA_HI, Ah + k0, tid);
        copyA(smw, WA_LO, Al + k0, tid);
        copyB(smw, WB_HI, Bh + k0, tid);
        copyB(smw, WB_LO, Bl + k0, tid);
        __syncthreads();

        #pragma unroll
        for (int ks = 0; ks < 4; ks++) {
            uint32_t ah[2][4], al[2][4], bh[4][2], bl[4][2];
            const int kw = ks * 8 + t;
            #pragma unroll
            for (int mt = 0; mt < 2; mt++) {
                int r = wm * 32 + mt * 16 + g;
                ah[mt][0] = smw[WA_HI + r * RS + kw];
                ah[mt][1] = smw[WA_HI + (r + 8) * RS + kw];
                ah[mt][2] = smw[WA_HI + r * RS + kw + 4];
                ah[mt][3] = smw[WA_HI + (r + 8) * RS + kw + 4];
                al[mt][0] = smw[WA_LO + r * RS + kw];
                al[mt][1] = smw[WA_LO + (r + 8) * RS + kw];
                al[mt][2] = smw[WA_LO + r * RS + kw + 4];
                al[mt][3] = smw[WA_LO + (r + 8) * RS + kw + 4];
            }
            #pragma unroll
            for (int nt = 0; nt < 4; nt++) {
                int n = wn * 32 + nt * 8 + g;
                bh[nt][0] = smw[WB_HI + n * RS + kw];
                bh[nt][1] = smw[WB_HI + n * RS + kw + 4];
                bl[nt][0] = smw[WB_LO + n * RS + kw];
                bl[nt][1] = smw[WB_LO + n * RS + kw + 4];
            }
            #pragma unroll
            for (int mt = 0; mt < 2; mt++)
                #pragma unroll
                for (int nt = 0; nt < 4; nt++) {
                    MMA16816(acc[mt][nt], ah[mt], bh[nt]);
                    MMA16816(acc[mt][nt], ah[mt], bl[nt]);
                    MMA16816(acc[mt][nt], al[mt], bh[nt]);
                }
        }
    }
}

// =====================================================================
// K1: QKV GEMM (unchanged)
// =====================================================================
__global__ __launch_bounds__(256) void qkv_mma(
    const float* __restrict__ bq, const float* __restrict__ bk, const float* __restrict__ bv)
{
    extern __shared__ uint32_t smw[];
    const int tid = threadIdx.x;
    const int wid = tid >> 5, lane = tid & 31;
    const int wm = wid & 3, wn = wid >> 2;
    const int g = lane >> 2, t = lane & 3;
    const int which = blockIdx.y % 3;
    const int h     = blockIdx.y / 3;
    const int slot  = which * 8 + h;
    const int m0    = blockIdx.x * 128;

    {
        const float* bias = (which == 0) ? bq : (which == 1) ? bk : bv;
        if (tid < 64) ((float*)(smw + WBIAS))[tid] = bias[h * 64 + tid];
    }

    float acc[2][4][4];
    #pragma unroll
    for (int mt = 0; mt < 2; mt++)
        #pragma unroll
        for (int nt = 0; nt < 4; nt++)
            #pragma unroll
            for (int i = 0; i < 4; i++) acc[mt][nt][i] = 0.f;

    gemm_mainloop(smw, tid,
                  Xhi + (size_t)m0 * KPAD, Xlo + (size_t)m0 * KPAD,
                  WqkvHi + (size_t)slot * 64 * KPAD, WqkvLo + (size_t)slot * 64 * KPAD,
                  acc);

    const float* biass = (const float*)(smw + WBIAS);
    float* ssP = (float*)(smw + WSSP);

    __syncthreads();
    #pragma unroll
    for (int mt = 0; mt < 2; mt++) {
        #pragma unroll
        for (int half = 0; half < 2; half++) {
            int lrow = wm * 32 + mt * 16 + g + half * 8;
            int row = m0 + lrow;
            int b = row >> 11, n = row & (Nseq - 1);
            size_t rbase = (size_t)(b * 8 + h) * 2048 + n;
            float ss = 0.f;
            #pragma unroll
            for (int nt = 0; nt < 4; nt++) {
                int col0 = wn * 32 + nt * 8 + 2 * t;
                float v0 = acc[mt][nt][half * 2 + 0] + biass[col0];
                float v1 = acc[mt][nt][half * 2 + 1] + biass[col0 + 1];
                ss += v0 * v0 + v1 * v1;
                __nv_bfloat16 h0, l0, h1, l1;
                bsplit(v0, h0, l0); bsplit(v1, h1, l1);
                if (which == 2) {
                    Vh_[rbase * 65 + 1 + col0] = h0;  Vh_[rbase * 65 + 2 + col0] = h1;
                    Vl_[rbase * 65 + 1 + col0] = l0;  Vl_[rbase * 65 + 2 + col0] = l1;
                } else {
                    int j = col0 >> 1;
                    int pos = ipos(j);
                    uint32_t* dst = (which == 0) ? QKiW : KKiW;
                    dst[rbase * 64 + pos]     = pack2(h0, h1);
                    dst[rbase * 64 + pos + 2] = pack2(l0, l1);
                }
            }
            ss += __shfl_xor_sync(0xffffffffu, ss, 1);
            ss += __shfl_xor_sync(0xffffffffu, ss, 2);
            if (t == 0) ssP[lrow * 2 + wn] = ss;
        }
    }
    __syncthreads();
    if (wn == 0 && t == 0) {
        #pragma unroll
        for (int mt = 0; mt < 2; mt++)
            #pragma unroll
            for (int half = 0; half < 2; half++) {
                int lrow = wm * 32 + mt * 16 + g + half * 8;
                int row = m0 + lrow;
                int b = row >> 11, n = row & (Nseq - 1);
                size_t rbase = (size_t)(b * 8 + h) * 2048 + n;
                float ss = ssP[lrow * 2] + ssP[lrow * 2 + 1];
                float tv = sqrtf(fmaxf(INVK + ss, EPSf));
                if (which == 0) Tqg[rbase] = tv;
                else if (which == 1) Tkg[rbase] = tv;
                else { bsplit(tv, Vh_[rbase * 65], Vl_[rbase * 65]); }
            }
    }
}

// =====================================================================
// V transpose (unchanged)
// =====================================================================
__global__ __launch_bounds__(128) void vtrans()
{
    __shared__ __nv_bfloat16 sh[64][73];
    __shared__ __nv_bfloat16 sl[64][73];
    const int bh = blockIdx.y, k0 = blockIdx.x * 64, tid = threadIdx.x;
    const int blk = blockIdx.x;
    const __nv_bfloat16 z = __float2bfloat16(0.f);
    for (int i = tid; i < 64 * 72; i += 128) {
        int r = i / 72, d = i % 72;
        sh[r][d] = (d < 65) ? Vh_[((size_t)bh * 2048 + k0 + r) * 65 + d] : z;
        sl[r][d] = (d < 65) ? Vl_[((size_t)bh * 2048 + k0 + r) * 65 + d] : z;
    }
    __syncthreads();
    for (int i = tid; i < 72 * 64; i += 128) {
        int d = i >> 6, k = i & 63;
        int jj = k >> 1, e = k & 1;
        int pos = ipos(jj);
        size_t eb = (((size_t)bh * 72 + d) * 32 + blk) * 128;
        VTiE[eb + pos * 2 + e]       = sh[k][d];
        VTiE[eb + (pos + 2) * 2 + e] = sl[k][d];
    }
}

// =====================================================================
// K2: pipelined flash attention; PV uses Phi only (V stays split)
// =====================================================================
__device__ __forceinline__ void attn_issue_tile(
    uint32_t smb, int bufw, int kt, int tid, int bh, size_t base)
{
    const int k0 = kt * 64;
    for (int i = tid; i < 2192; i += 256) {
        uint32_t dstw; const void* src;
        if (i < 1024) {
            int r = i >> 4, ch = i & 15;
            dstw = bufw + r * RSA + ch * 4;
            src = KKiW + (base + k0 + r) * 64 + ch * 4;
        } else if (i < 2176) {
            int j = i - 1024, d = j >> 4, ch = j & 15;
            dstw = bufw + VOFF + d * RSA + ch * 4;
            src = VTiE + (((size_t)bh * 72 + d) * 32 + kt) * 128 + ch * 8;
        } else {
            int j = i - 2176;
            dstw = bufw + TKOFF + j * 4;
            src = Tkg + base + k0 + j * 4;
        }
        CP_ASYNC16(smb + dstw * 4, src);
    }
}

__global__ __launch_bounds__(256, 2) void attn_mma()
{
    extern __shared__ uint32_t sw[];
    const int tid = threadIdx.x;
    const int w = tid >> 5, lane = tid & 31;
    const int g = lane >> 2, t = lane & 3;
    const int bh = blockIdx.y;
    const int b = bh >> 3, h = bh & 7;
    const int n0 = blockIdx.x * 128;
    const size_t base = (size_t)bh * 2048;
    uint32_t smb;
    asm("{ .reg .u64 tt; cvta.to.shared.u64 tt, %1; cvt.u32.u64 %0, tt; }"
        : "=r"(smb) : "l"(sw));

    attn_issue_tile(smb, 0, 0, tid, bh, base);
    CP_COMMIT();

    for (int i = tid; i < 2048; i += 256) {
        int r = i >> 4, ch = i & 15;
        *(uint4*)(sw + ABUF + r * RSA + ch * 4) =
            *(const uint4*)(QKiW + (base + n0 + r) * 64 + ch * 4);
    }
    __syncthreads();
    uint32_t qh[4][4], ql[4][4];
    const int r0 = w * 16 + g;
    #pragma unroll
    for (int ks = 0; ks < 4; ks++) {
        uint4 a  = *(const uint4*)(sw + ABUF + r0 * RSA + 16 * ks + 4 * t);
        uint4 b2 = *(const uint4*)(sw + ABUF + (r0 + 8) * RSA + 16 * ks + 4 * t);
        qh[ks][0] = a.x;  qh[ks][1] = b2.x;  qh[ks][2] = a.y;  qh[ks][3] = b2.y;
        ql[ks][0] = a.z;  ql[ks][1] = b2.z;  ql[ks][2] = a.w;  ql[ks][3] = b2.w;
    }
    const float tqa = Tqg[base + n0 + r0];
    const float tqb = Tqg[base + n0 + r0 + 8];
    __syncthreads();

    float accO[9][4];
    #pragma unroll
    for (int nd = 0; nd < 9; nd++)
        #pragma unroll
        for (int c = 0; c < 4; c++) accO[nd][c] = 0.f;
    float lA = 0.f, lB = 0.f;

    for (int kt = 0; kt < 32; kt++) {
        const int cur = (kt & 1) * ABUF;
        if (kt < 31) {
            attn_issue_tile(smb, ((kt + 1) & 1) * ABUF, kt + 1, tid, bh, base);
            CP_COMMIT();
            CP_WAIT(1);
        } else {
            CP_WAIT(0);
        }
        __syncthreads();

        const float* tks = (const float*)(sw + cur + TKOFF);

        float sacc[8][4];
        #pragma unroll
        for (int nt = 0; nt < 8; nt++)
            #pragma unroll
            for (int c = 0; c < 4; c++) sacc[nt][c] = 0.f;

        #pragma unroll
        for (int ks = 0; ks < 4; ks++) {
            #pragma unroll
            for (int nt = 0; nt < 8; nt++) {
                int n = nt * 8 + g;
                uint4 kv = *(const uint4*)(sw + cur + n * RSA + 16 * ks + 4 * t);
                uint32_t kb[2]  = { kv.x, kv.y };
                uint32_t klr[2] = { kv.z, kv.w };
                MMA16816(sacc[nt], qh[ks], kb);
                MMA16816(sacc[nt], qh[ks], klr);
                MMA16816(sacc[nt], ql[ks], kb);
            }
        }

        // fused softmax + PV per chunk; P in bf16 hi only (normalization
        // cancels the common-mode rounding; V remains split)
        #pragma unroll
        for (int kb2 = 0; kb2 < 4; kb2++) {
            uint32_t Ahi[4];
            #pragma unroll
            for (int half = 0; half < 2; half++) {
                const int nt = 2 * kb2 + half;
                float2 tk = *(const float2*)(tks + nt * 8 + 2 * t);
                float e0 = exp2p((sacc[nt][0] - tqa * tk.x) * S2f);
                float e1 = exp2p((sacc[nt][1] - tqa * tk.y) * S2f);
                float e2 = exp2p((sacc[nt][2] - tqb * tk.x) * S2f);
                float e3 = exp2p((sacc[nt][3] - tqb * tk.y) * S2f);
                lA += e0 + e1;
                lB += e2 + e3;
                Ahi[half * 2 + 0] = cvtpk(e0, e1);
                Ahi[half * 2 + 1] = cvtpk(e2, e3);
            }
            #pragma unroll
            for (int nd = 0; nd < 9; nd++) {
                int n = nd * 8 + g;
                uint4 vv = *(const uint4*)(sw + cur + VOFF + n * RSA + 16 * kb2 + 4 * t);
                uint32_t vb[2] = { vv.x, vv.y };
                uint32_t vl[2] = { vv.z, vv.w };
                MMA16816(accO[nd], Ahi, vb);
                MMA16816(accO[nd], Ahi, vl);
            }
        }
        __syncthreads();
    }

    lA += __shfl_xor_sync(0xffffffffu, lA, 1);
    lA += __shfl_xor_sync(0xffffffffu, lA, 2);
    lB += __shfl_xor_sync(0xffffffffu, lB, 1);
    lB += __shfl_xor_sync(0xffffffffu, lB, 2);

    const float linA = 1.f / lA, linB = 1.f / lB;
    float ssA = 0.f, ssB = 0.f;
    #pragma unroll
    for (int nd = 0; nd < 9; nd++) {
        accO[nd][0] *= linA;  accO[nd][1] *= linA;
        accO[nd][2] *= linB;  accO[nd][3] *= linB;
        ssA += accO[nd][0] * accO[nd][0] + accO[nd][1] * accO[nd][1];
        ssB += accO[nd][2] * accO[nd][2] + accO[nd][3] * accO[nd][3];
    }
    ssA += __shfl_xor_sync(0xffffffffu, ssA, 1);
    ssA += __shfl_xor_sync(0xffffffffu, ssA, 2);
    ssB += __shfl_xor_sync(0xffffffffu, ssB, 1);
    ssB += __shfl_xor_sync(0xffffffffu, ssB, 2);
    float tA = __shfl_sync(0xffffffffu, accO[0][0], lane & ~3);
    float tB = __shfl_sync(0xffffffffu, accO[0][2], lane & ~3);
    float spA = ssA - tA * tA;
    float spB = ssB - tB * tB;
    float idnA = rsqrtf(fmaxf(KCURV * (tA * tA - spA), EPSf));
    float idnB = rsqrtf(fmaxf(KCURV * (tB * tB - spB), EPSf));

    const int rowA = b * 2048 + n0 + w * 16 + g;
    const int rowB = rowA + 8;
    #pragma unroll
    for (int nd = 0; nd < 9; nd++) {
        #pragma unroll
        for (int c = 0; c < 2; c++) {
            int d = nd * 8 + 2 * t + c;
            if (d >= 1 && d < 65) {
                OutCat[(size_t)rowA * 512 + h * 64 + d - 1] = accO[nd][c] * idnA;
                OutCat[(size_t)rowB * 512 + h * 64 + d - 1] = accO[nd][c + 2] * idnB;
            }
        }
    }
    if (t == 0) {
        HSS[rowA * 8 + h] = spA * idnA * idnA;
        HSS[rowB * 8 + h] = spB * idnB * idnB;
    }
}

// =====================================================================
// K3: output projection (unchanged)
// =====================================================================
__global__ __launch_bounds__(256) void outproj_mma(
    const float* __restrict__ bo, float* __restrict__ out)
{
    extern __shared__ uint32_t smw[];
    const int tid = threadIdx.x;
    const int wid = tid >> 5, lane = tid & 31;
    const int wm = wid & 3, wn = wid >> 2;
    const int g = lane >> 2, t = lane & 3;
    const int m0 = blockIdx.x * 128;
    const int c0 = blockIdx.y * 64;

    if (tid < 64) ((float*)(smw + WBIAS))[tid] = bo[c0 + tid];

    float acc[2][4][4];
    #pragma unroll
    for (int mt = 0; mt < 2; mt++)
        #pragma unroll
        for (int nt = 0; nt < 4; nt++)
            #pragma unroll
            for (int i = 0; i < 4; i++) acc[mt][nt][i] = 0.f;

    gemm_mainloop(smw, tid,
                  Chi + (size_t)m0 * KPAD, Clo + (size_t)m0 * KPAD,
                  WoTHi + (size_t)c0 * KPAD, WoTLo + (size_t)c0 * KPAD,
                  acc);

    const float* biass = (const float*)(smw + WBIAS);
    float* ssP = (float*)(smw + WSSP);

    __syncthreads();
    #pragma unroll
    for (int mt = 0; mt < 2; mt++) {
        #pragma unroll
        for (int half = 0; half < 2; half++) {
            int lrow = wm * 32 + mt * 16 + g + half * 8;
            int row = m0 + lrow;
            float ss = 0.f;
            #pragma unroll
            for (int nt = 0; nt < 4; nt++) {
                #pragma unroll
                for (int cc = 0; cc < 2; cc++) {
                    int col = wn * 32 + nt * 8 + 2 * t + cc;
                    float v = acc[mt][nt][half * 2 + cc] + biass[col];
                    out[(size_t)row * Dm + 1 + c0 + col] = v;
                    ss += v * v;
                }
            }
            ss += __shfl_xor_sync(0xffffffffu, ss, 1);
            ss += __shfl_xor_sync(0xffffffffu, ss, 2);
            if (t == 0) ssP[lrow * 2 + wn] = ss;
        }
    }
    __syncthreads();
    if (wn == 0 && t == 0) {
        #pragma unroll
        for (int mt = 0; mt < 2; mt++)
            #pragma unroll
            for (int half = 0; half < 2; half++) {
                int lrow = wm * 32 + mt * 16 + g + half * 8;
                int row = m0 + lrow;
                Part2[row * 8 + blockIdx.y] = ssP[lrow * 2] + ssP[lrow * 2 + 1];
            }
    }
}

__global__ void time_kernel(float* __restrict__ out)
{
    int row = blockIdx.x * 256 + threadIdx.x;
    if (row < Mrows) {
        float ss = 0.f;
        #pragma unroll
        for (int j = 0; j < 8; j++) ss += Part2[row * 8 + j];
        out[(size_t)row * Dm] = sqrtf(fmaxf(INVK + ss, EPSf));
    }
}

// =====================================================================
extern "C" void kernel_launch(void* const* d_in, const int* in_sizes, int n_in,
                              void* d_out, int out_size)
{
    const float* x  = (const float*)d_in[0];
    const float* Wq = (const float*)d_in[1];
    const float* bq = (const float*)d_in[2];
    const float* Wk = (const float*)d_in[3];
    const float* bk = (const float*)d_in[4];
    const float* Wv = (const float*)d_in[5];
    const float* bv = (const float*)d_in[6];
    const float* Wo = (const float*)d_in[7];
    const float* bo = (const float*)d_in[8];
    float* out = (float*)d_out;

    const int smem_gemm = WTOT * 4;
    const int smem_attn = 2 * ABUF * 4;
    cudaFuncSetAttribute(qkv_mma, cudaFuncAttributeMaxDynamicSharedMemorySize, smem_gemm);
    cudaFuncSetAttribute(outproj_mma, cudaFuncAttributeMaxDynamicSharedMemorySize, smem_gemm);
    cudaFuncSetAttribute(attn_mma, cudaFuncAttributeMaxDynamicSharedMemorySize, smem_attn);

    cvt_in_kernel<<<10240, 576>>>(Wq, Wk, Wv, Wo, x);
    qkv_mma<<<dim3(64, 24), 256, smem_gemm>>>(bq, bk, bv);
    vtrans<<<dim3(32, 32), 128>>>();
    attn_mma<<<dim3(16, 32), 256, smem_attn>>>();
    cvt_cat_kernel<<<8192, 576>>>();
    outproj_mma<<<dim3(64, 8), 256, smem_gemm>>>(bo, out);
    time_kernel<<<32, 256>>>(out);
}

// round 14
// speedup vs baseline: 2.8948x; 1.0982x over previous
#include <cuda_runtime.h>
#include <cuda_bf16.h>
#include <math.h>
#include <stdint.h>

#define Bsz   4
#define Nseq  2048
#define Dm    513
#define Hh    8
#define Mrows 8192
#define KPAD  576
#define INVK  10.0f
#define KCURV 0.1f
#define EPSf  1e-9f
#define S2f   0.18033688011112042f   // 0.125 * log2(e)

// ---------------- device scratch ----------------
__device__ float OutCat[(size_t)Mrows*512];
__device__ float HSS[Mrows*Hh];
__device__ float Part2[Mrows*8];
__device__ __nv_bfloat16 Xhi[(size_t)Mrows*KPAD];
__device__ __nv_bfloat16 Xlo[(size_t)Mrows*KPAD];
__device__ __nv_bfloat16 WqkvHi[24*64*KPAD];
__device__ __nv_bfloat16 WqkvLo[24*64*KPAD];
__device__ __nv_bfloat16 WoTHi[512*KPAD];
__device__ __nv_bfloat16 WoTLo[512*KPAD];
__device__ __nv_bfloat16 Chi[(size_t)Mrows*KPAD];
__device__ __nv_bfloat16 Clo[(size_t)Mrows*KPAD];
__device__ uint32_t QKiW[(size_t)32*2048*64];
__device__ uint32_t KKiW[(size_t)32*2048*64];
__device__ float Tqg[32*2048];
__device__ float Tkg[32*2048];
__device__ __nv_bfloat16 Vh_[(size_t)32*2048*65];
__device__ __nv_bfloat16 Vl_[(size_t)32*2048*65];
__device__ __nv_bfloat16 VTiE[(size_t)32*72*32*128];

__device__ __forceinline__ void bsplit(float v, __nv_bfloat16& h, __nv_bfloat16& l) {
    h = __float2bfloat16(v);
    l = __float2bfloat16(v - __bfloat162float(h));
}
__device__ __forceinline__ uint32_t pack2(__nv_bfloat16 a, __nv_bfloat16 b) {
    __nv_bfloat162 t2; t2.x = a; t2.y = b;
    uint32_t r; memcpy(&r, &t2, 4); return r;
}
__device__ __forceinline__ uint32_t cvtpk(float lo, float hi) {
    uint32_t r;
    asm("cvt.rn.bf16x2.f32 %0, %1, %2;" : "=r"(r) : "f"(hi), "f"(lo));
    return r;
}

__device__ __forceinline__ float exp2p(float y) {
    y = fmaxf(y, -120.f);
    float z = y + 12582912.f;
    int ib = __float_as_int(z);
    float n = z - 12582912.f;
    float f = y - n;
    float p = 1.3333558146e-3f;
    p = fmaf(p, f, 9.6181291076e-3f);
    p = fmaf(p, f, 5.5504108664e-2f);
    p = fmaf(p, f, 2.4022650696e-1f);
    p = fmaf(p, f, 6.9314718056e-1f);
    p = fmaf(p, f, 1.0f);
    return __int_as_float(__float_as_int(p) + (ib << 23));
}

#define MMA16816(D, A, B) \
    asm volatile("mma.sync.aligned.m16n8k16.row.col.f32.bf16.bf16.f32 " \
        "{%0,%1,%2,%3}, {%4,%5,%6,%7}, {%8,%9}, {%0,%1,%2,%3};" \
        : "+f"((D)[0]), "+f"((D)[1]), "+f"((D)[2]), "+f"((D)[3]) \
        : "r"((A)[0]), "r"((A)[1]), "r"((A)[2]), "r"((A)[3]), \
          "r"((B)[0]), "r"((B)[1]))

#define CP_ASYNC16(dst, src) \
    asm volatile("cp.async.cg.shared.global [%0], [%1], 16;" :: "r"(dst), "l"(src))
#define CP_COMMIT() asm volatile("cp.async.commit_group;" ::: "memory")
#define CP_WAIT(n)  asm volatile("cp.async.wait_group %0;" :: "n"(n) : "memory")

// projection GEMM smem geometry (words); double-buffered
#define RS 36
#define GA_HI 0
#define GA_LO 4608
#define GB_HI 9216
#define GB_LO 11520
#define GBUF  13824
#define WBIAS 27648
#define WSSP  27712
#define WTOT  27968          // *4 = 111872 bytes

// attention smem geometry (words)
#define RSA   80
#define VOFF  5120
#define TKOFF 10880
#define ABUF  10944

__device__ __forceinline__ int ipos(int j) {
    return 16 * (j >> 3) + 4 * (j & 3) + ((j >> 2) & 1);
}
__device__ __forceinline__ uint32_t smem_u32(const void* p) {
    uint32_t a;
    asm("{ .reg .u64 t; cvta.to.shared.u64 t, %1; cvt.u32.u64 %0, t; }" : "=r"(a) : "l"(p));
    return a;
}

// =====================================================================
// input conversion (row-indexed, proven)
// =====================================================================
__global__ __launch_bounds__(576) void cvt_in_kernel(
    const float* __restrict__ Wq, const float* __restrict__ Wk,
    const float* __restrict__ Wv, const float* __restrict__ Wo,
    const float* __restrict__ x)
{
    const int bid = blockIdx.x;
    const int k = threadIdx.x;
    if (bid < 1536) {
        int n = bid & 63;
        int s = bid >> 6;
        int which = s >> 3, h = s & 7;
        const float* W = (which == 0) ? Wq : (which == 1) ? Wk : Wv;
        float v = (k < Dm) ? W[((size_t)h * Dm + k) * 64 + n] : 0.f;
        size_t i = (size_t)bid * KPAD + k;
        bsplit(v, WqkvHi[i], WqkvLo[i]);
    } else if (bid < 2048) {
        int n = bid - 1536;
        float v = (k < Dm) ? Wo[(size_t)k * 512 + n] : 0.f;
        size_t i = (size_t)n * KPAD + k;
        bsplit(v, WoTHi[i], WoTLo[i]);
    } else {
        size_t row = bid - 2048;
        float v = (k < Dm) ? x[row * Dm + k] : 0.f;
        size_t i = row * KPAD + k;
        bsplit(v, Xhi[i], Xlo[i]);
    }
}

__global__ __launch_bounds__(576) void cvt_cat_kernel()
{
    const size_t row = blockIdx.x;
    const int k = threadIdx.x;
    float v;
    if (k == 0) {
        float ss = 0.f;
        #pragma unroll
        for (int hh = 0; hh < 8; hh++) ss += HSS[row * 8 + hh];
        v = sqrtf(fmaxf(INVK + ss, EPSf));
    } else if (k < Dm) {
        v = OutCat[row * 512 + k - 1];
    } else v = 0.f;
    size_t i = row * KPAD + k;
    bsplit(v, Chi[i], Clo[i]);
}

// =====================================================================
// pipelined projection GEMM mainloop (cp.async double-buffered)
// =====================================================================
__device__ __forceinline__ void gemm_issue_chunk(
    uint32_t smb, int bufw, int k0, int tid,
    const __nv_bfloat16* __restrict__ Ah, const __nv_bfloat16* __restrict__ Al,
    const __nv_bfloat16* __restrict__ Bh, const __nv_bfloat16* __restrict__ Bl)
{
    for (int i = tid; i < 3072; i += 256) {
        uint32_t dstw; const void* src;
        if (i < 1024) {
            int r = i >> 3, q = i & 7;
            dstw = bufw + GA_HI + r * RS + q * 4;
            src = Ah + (size_t)r * KPAD + k0 + q * 8;
        } else if (i < 2048) {
            int j = i - 1024, r = j >> 3, q = j & 7;
            dstw = bufw + GA_LO + r * RS + q * 4;
            src = Al + (size_t)r * KPAD + k0 + q * 8;
        } else if (i < 2560) {
            int j = i - 2048, r = j >> 3, q = j & 7;
            dstw = bufw + GB_HI + r * RS + q * 4;
            src = Bh + (size_t)r * KPAD + k0 + q * 8;
        } else {
            int j = i - 2560, r = j >> 3, q = j & 7;
            dstw = bufw + GB_LO + r * RS + q * 4;
            src = Bl + (size_t)r * KPAD + k0 + q * 8;
        }
        CP_ASYNC16(smb + dstw * 4, src);
    }
}

__device__ __forceinline__ void gemm_mainloop(
    uint32_t* smw, int tid,
    const __nv_bfloat16* Ah, const __nv_bfloat16* Al,
    const __nv_bfloat16* Bh, const __nv_bfloat16* Bl,
    float acc[2][4][4])
{
    const int wid = tid >> 5, lane = tid & 31;
    const int wm = wid & 3, wn = wid >> 2;
    const int g = lane >> 2, t = lane & 3;
    const uint32_t smb = smem_u32(smw);

    gemm_issue_chunk(smb, 0, 0, tid, Ah, Al, Bh, Bl);
    CP_COMMIT();

    for (int c = 0; c < 9; c++) {
        const int cur = (c & 1) * GBUF;
        if (c < 8) {
            gemm_issue_chunk(smb, ((c + 1) & 1) * GBUF, (c + 1) * 64, tid, Ah, Al, Bh, Bl);
            CP_COMMIT();
            CP_WAIT(1);
        } else {
            CP_WAIT(0);
        }
        __syncthreads();

        #pragma unroll
        for (int ks = 0; ks < 4; ks++) {
            uint32_t ah[2][4], al[2][4], bh[4][2], bl[4][2];
            const int kw = ks * 8 + t;
            #pragma unroll
            for (int mt = 0; mt < 2; mt++) {
                int r = wm * 32 + mt * 16 + g;
                ah[mt][0] = smw[cur + GA_HI + r * RS + kw];
                ah[mt][1] = smw[cur + GA_HI + (r + 8) * RS + kw];
                ah[mt][2] = smw[cur + GA_HI + r * RS + kw + 4];
                ah[mt][3] = smw[cur + GA_HI + (r + 8) * RS + kw + 4];
                al[mt][0] = smw[cur + GA_LO + r * RS + kw];
                al[mt][1] = smw[cur + GA_LO + (r + 8) * RS + kw];
                al[mt][2] = smw[cur + GA_LO + r * RS + kw + 4];
                al[mt][3] = smw[cur + GA_LO + (r + 8) * RS + kw + 4];
            }
            #pragma unroll
            for (int nt = 0; nt < 4; nt++) {
                int n = wn * 32 + nt * 8 + g;
                bh[nt][0] = smw[cur + GB_HI + n * RS + kw];
                bh[nt][1] = smw[cur + GB_HI + n * RS + kw + 4];
                bl[nt][0] = smw[cur + GB_LO + n * RS + kw];
                bl[nt][1] = smw[cur + GB_LO + n * RS + kw + 4];
            }
            #pragma unroll
            for (int mt = 0; mt < 2; mt++)
                #pragma unroll
                for (int nt = 0; nt < 4; nt++) {
                    MMA16816(acc[mt][nt], ah[mt], bh[nt]);
                    MMA16816(acc[mt][nt], ah[mt], bl[nt]);
                    MMA16816(acc[mt][nt], al[mt], bh[nt]);
                }
        }
        __syncthreads();
    }
}

// =====================================================================
// K1: QKV GEMM (epilogue unchanged)
// =====================================================================
__global__ __launch_bounds__(256) void qkv_mma(
    const float* __restrict__ bq, const float* __restrict__ bk, const float* __restrict__ bv)
{
    extern __shared__ uint32_t smw[];
    const int tid = threadIdx.x;
    const int wid = tid >> 5, lane = tid & 31;
    const int wm = wid & 3, wn = wid >> 2;
    const int g = lane >> 2, t = lane & 3;
    const int which = blockIdx.y % 3;
    const int h     = blockIdx.y / 3;
    const int slot  = which * 8 + h;
    const int m0    = blockIdx.x * 128;

    {
        const float* bias = (which == 0) ? bq : (which == 1) ? bk : bv;
        if (tid < 64) ((float*)(smw + WBIAS))[tid] = bias[h * 64 + tid];
    }

    float acc[2][4][4];
    #pragma unroll
    for (int mt = 0; mt < 2; mt++)
        #pragma unroll
        for (int nt = 0; nt < 4; nt++)
            #pragma unroll
            for (int i = 0; i < 4; i++) acc[mt][nt][i] = 0.f;

    gemm_mainloop(smw, tid,
                  Xhi + (size_t)m0 * KPAD, Xlo + (size_t)m0 * KPAD,
                  WqkvHi + (size_t)slot * 64 * KPAD, WqkvLo + (size_t)slot * 64 * KPAD,
                  acc);

    const float* biass = (const float*)(smw + WBIAS);
    float* ssP = (float*)(smw + WSSP);

    __syncthreads();
    #pragma unroll
    for (int mt = 0; mt < 2; mt++) {
        #pragma unroll
        for (int half = 0; half < 2; half++) {
            int lrow = wm * 32 + mt * 16 + g + half * 8;
            int row = m0 + lrow;
            int b = row >> 11, n = row & (Nseq - 1);
            size_t rbase = (size_t)(b * 8 + h) * 2048 + n;
            float ss = 0.f;
            #pragma unroll
            for (int nt = 0; nt < 4; nt++) {
                int col0 = wn * 32 + nt * 8 + 2 * t;
                float v0 = acc[mt][nt][half * 2 + 0] + biass[col0];
                float v1 = acc[mt][nt][half * 2 + 1] + biass[col0 + 1];
                ss += v0 * v0 + v1 * v1;
                __nv_bfloat16 h0, l0, h1, l1;
                bsplit(v0, h0, l0); bsplit(v1, h1, l1);
                if (which == 2) {
                    Vh_[rbase * 65 + 1 + col0] = h0;  Vh_[rbase * 65 + 2 + col0] = h1;
                    Vl_[rbase * 65 + 1 + col0] = l0;  Vl_[rbase * 65 + 2 + col0] = l1;
                } else {
                    int j = col0 >> 1;
                    int pos = ipos(j);
                    uint32_t* dst = (which == 0) ? QKiW : KKiW;
                    dst[rbase * 64 + pos]     = pack2(h0, h1);
                    dst[rbase * 64 + pos + 2] = pack2(l0, l1);
                }
            }
            ss += __shfl_xor_sync(0xffffffffu, ss, 1);
            ss += __shfl_xor_sync(0xffffffffu, ss, 2);
            if (t == 0) ssP[lrow * 2 + wn] = ss;
        }
    }
    __syncthreads();
    if (wn == 0 && t == 0) {
        #pragma unroll
        for (int mt = 0; mt < 2; mt++)
            #pragma unroll
            for (int half = 0; half < 2; half++) {
                int lrow = wm * 32 + mt * 16 + g + half * 8;
                int row = m0 + lrow;
                int b = row >> 11, n = row & (Nseq - 1);
                size_t rbase = (size_t)(b * 8 + h) * 2048 + n;
                float ss = ssP[lrow * 2] + ssP[lrow * 2 + 1];
                float tv = sqrtf(fmaxf(INVK + ss, EPSf));
                if (which == 0) Tqg[rbase] = tv;
                else if (which == 1) Tkg[rbase] = tv;
                else { bsplit(tv, Vh_[rbase * 65], Vl_[rbase * 65]); }
            }
    }
}

// =====================================================================
// V transpose (unchanged)
// =====================================================================
__global__ __launch_bounds__(128) void vtrans()
{
    __shared__ __nv_bfloat16 sh[64][73];
    __shared__ __nv_bfloat16 sl[64][73];
    const int bh = blockIdx.y, k0 = blockIdx.x * 64, tid = threadIdx.x;
    const int blk = blockIdx.x;
    const __nv_bfloat16 z = __float2bfloat16(0.f);
    for (int i = tid; i < 64 * 72; i += 128) {
        int r = i / 72, d = i % 72;
        sh[r][d] = (d < 65) ? Vh_[((size_t)bh * 2048 + k0 + r) * 65 + d] : z;
        sl[r][d] = (d < 65) ? Vl_[((size_t)bh * 2048 + k0 + r) * 65 + d] : z;
    }
    __syncthreads();
    for (int i = tid; i < 72 * 64; i += 128) {
        int d = i >> 6, k = i & 63;
        int jj = k >> 1, e = k & 1;
        int pos = ipos(jj);
        size_t eb = (((size_t)bh * 72 + d) * 32 + blk) * 128;
        VTiE[eb + pos * 2 + e]       = sh[k][d];
        VTiE[eb + (pos + 2) * 2 + e] = sl[k][d];
    }
}

// =====================================================================
// K2: pipelined flash attention (unchanged from R12)
// =====================================================================
__device__ __forceinline__ void attn_issue_tile(
    uint32_t smb, int bufw, int kt, int tid, int bh, size_t base)
{
    const int k0 = kt * 64;
    for (int i = tid; i < 2192; i += 256) {
        uint32_t dstw; const void* src;
        if (i < 1024) {
            int r = i >> 4, ch = i & 15;
            dstw = bufw + r * RSA + ch * 4;
            src = KKiW + (base + k0 + r) * 64 + ch * 4;
        } else if (i < 2176) {
            int j = i - 1024, d = j >> 4, ch = j & 15;
            dstw = bufw + VOFF + d * RSA + ch * 4;
            src = VTiE + (((size_t)bh * 72 + d) * 32 + kt) * 128 + ch * 8;
        } else {
            int j = i - 2176;
            dstw = bufw + TKOFF + j * 4;
            src = Tkg + base + k0 + j * 4;
        }
        CP_ASYNC16(smb + dstw * 4, src);
    }
}

__global__ __launch_bounds__(256, 2) void attn_mma()
{
    extern __shared__ uint32_t sw[];
    const int tid = threadIdx.x;
    const int w = tid >> 5, lane = tid & 31;
    const int g = lane >> 2, t = lane & 3;
    const int bh = blockIdx.y;
    const int b = bh >> 3, h = bh & 7;
    const int n0 = blockIdx.x * 128;
    const size_t base = (size_t)bh * 2048;
    const uint32_t smb = smem_u32(sw);

    attn_issue_tile(smb, 0, 0, tid, bh, base);
    CP_COMMIT();

    for (int i = tid; i < 2048; i += 256) {
        int r = i >> 4, ch = i & 15;
        *(uint4*)(sw + ABUF + r * RSA + ch * 4) =
            *(const uint4*)(QKiW + (base + n0 + r) * 64 + ch * 4);
    }
    __syncthreads();
    uint32_t qh[4][4], ql[4][4];
    const int r0 = w * 16 + g;
    #pragma unroll
    for (int ks = 0; ks < 4; ks++) {
        uint4 a  = *(const uint4*)(sw + ABUF + r0 * RSA + 16 * ks + 4 * t);
        uint4 b2 = *(const uint4*)(sw + ABUF + (r0 + 8) * RSA + 16 * ks + 4 * t);
        qh[ks][0] = a.x;  qh[ks][1] = b2.x;  qh[ks][2] = a.y;  qh[ks][3] = b2.y;
        ql[ks][0] = a.z;  ql[ks][1] = b2.z;  ql[ks][2] = a.w;  ql[ks][3] = b2.w;
    }
    const float tqa = Tqg[base + n0 + r0];
    const float tqb = Tqg[base + n0 + r0 + 8];
    __syncthreads();

    float accO[9][4];
    #pragma unroll
    for (int nd = 0; nd < 9; nd++)
        #pragma unroll
        for (int c = 0; c < 4; c++) accO[nd][c] = 0.f;
    float lA = 0.f, lB = 0.f;

    for (int kt = 0; kt < 32; kt++) {
        const int cur = (kt & 1) * ABUF;
        if (kt < 31) {
            attn_issue_tile(smb, ((kt + 1) & 1) * ABUF, kt + 1, tid, bh, base);
            CP_COMMIT();
            CP_WAIT(1);
        } else {
            CP_WAIT(0);
        }
        __syncthreads();

        const float* tks = (const float*)(sw + cur + TKOFF);

        float sacc[8][4];
        #pragma unroll
        for (int nt = 0; nt < 8; nt++)
            #pragma unroll
            for (int c = 0; c < 4; c++) sacc[nt][c] = 0.f;

        #pragma unroll
        for (int ks = 0; ks < 4; ks++) {
            #pragma unroll
            for (int nt = 0; nt < 8; nt++) {
                int n = nt * 8 + g;
                uint4 kv = *(const uint4*)(sw + cur + n * RSA + 16 * ks + 4 * t);
                uint32_t kb[2]  = { kv.x, kv.y };
                uint32_t klr[2] = { kv.z, kv.w };
                MMA16816(sacc[nt], qh[ks], kb);
                MMA16816(sacc[nt], qh[ks], klr);
                MMA16816(sacc[nt], ql[ks], kb);
            }
        }

        #pragma unroll
        for (int kb2 = 0; kb2 < 4; kb2++) {
            uint32_t Ahi[4];
            #pragma unroll
            for (int half = 0; half < 2; half++) {
                const int nt = 2 * kb2 + half;
                float2 tk = *(const float2*)(tks + nt * 8 + 2 * t);
                float e0 = exp2p((sacc[nt][0] - tqa * tk.x) * S2f);
                float e1 = exp2p((sacc[nt][1] - tqa * tk.y) * S2f);
                float e2 = exp2p((sacc[nt][2] - tqb * tk.x) * S2f);
                float e3 = exp2p((sacc[nt][3] - tqb * tk.y) * S2f);
                lA += e0 + e1;
                lB += e2 + e3;
                Ahi[half * 2 + 0] = cvtpk(e0, e1);
                Ahi[half * 2 + 1] = cvtpk(e2, e3);
            }
            #pragma unroll
            for (int nd = 0; nd < 9; nd++) {
                int n = nd * 8 + g;
                uint4 vv = *(const uint4*)(sw + cur + VOFF + n * RSA + 16 * kb2 + 4 * t);
                uint32_t vb[2] = { vv.x, vv.y };
                uint32_t vl[2] = { vv.z, vv.w };
                MMA16816(accO[nd], Ahi, vb);
                MMA16816(accO[nd], Ahi, vl);
            }
        }
        __syncthreads();
    }

    lA += __shfl_xor_sync(0xffffffffu, lA, 1);
    lA += __shfl_xor_sync(0xffffffffu, lA, 2);
    lB += __shfl_xor_sync(0xffffffffu, lB, 1);
    lB += __shfl_xor_sync(0xffffffffu, lB, 2);

    const float linA = 1.f / lA, linB = 1.f / lB;
    float ssA = 0.f, ssB = 0.f;
    #pragma unroll
    for (int nd = 0; nd < 9; nd++) {
        accO[nd][0] *= linA;  accO[nd][1] *= linA;
        accO[nd][2] *= linB;  accO[nd][3] *= linB;
        ssA += accO[nd][0] * accO[nd][0] + accO[nd][1] * accO[nd][1];
        ssB += accO[nd][2] * accO[nd][2] + accO[nd][3] * accO[nd][3];
    }
    ssA += __shfl_xor_sync(0xffffffffu, ssA, 1);
    ssA += __shfl_xor_sync(0xffffffffu, ssA, 2);
    ssB += __shfl_xor_sync(0xffffffffu, ssB, 1);
    ssB += __shfl_xor_sync(0xffffffffu, ssB, 2);
    float tA = __shfl_sync(0xffffffffu, accO[0][0], lane & ~3);
    float tB = __shfl_sync(0xffffffffu, accO[0][2], lane & ~3);
    float spA = ssA - tA * tA;
    float spB = ssB - tB * tB;
    float idnA = rsqrtf(fmaxf(KCURV * (tA * tA - spA), EPSf));
    float idnB = rsqrtf(fmaxf(KCURV * (tB * tB - spB), EPSf));

    const int rowA = b * 2048 + n0 + w * 16 + g;
    const int rowB = rowA + 8;
    #pragma unroll
    for (int nd = 0; nd < 9; nd++) {
        #pragma unroll
        for (int c = 0; c < 2; c++) {
            int d = nd * 8 + 2 * t + c;
            if (d >= 1 && d < 65) {
                OutCat[(size_t)rowA * 512 + h * 64 + d - 1] = accO[nd][c] * idnA;
                OutCat[(size_t)rowB * 512 + h * 64 + d - 1] = accO[nd][c + 2] * idnB;
            }
        }
    }
    if (t == 0) {
        HSS[rowA * 8 + h] = spA * idnA * idnA;
        HSS[rowB * 8 + h] = spB * idnB * idnB;
    }
}

// =====================================================================
// K3: output projection (epilogue unchanged)
// =====================================================================
__global__ __launch_bounds__(256) void outproj_mma(
    const float* __restrict__ bo, float* __restrict__ out)
{
    extern __shared__ uint32_t smw[];
    const int tid = threadIdx.x;
    const int wid = tid >> 5, lane = tid & 31;
    const int wm = wid & 3, wn = wid >> 2;
    const int g = lane >> 2, t = lane & 3;
    const int m0 = blockIdx.x * 128;
    const int c0 = blockIdx.y * 64;

    if (tid < 64) ((float*)(smw + WBIAS))[tid] = bo[c0 + tid];

    float acc[2][4][4];
    #pragma unroll
    for (int mt = 0; mt < 2; mt++)
        #pragma unroll
        for (int nt = 0; nt < 4; nt++)
            #pragma unroll
            for (int i = 0; i < 4; i++) acc[mt][nt][i] = 0.f;

    gemm_mainloop(smw, tid,
                  Chi + (size_t)m0 * KPAD, Clo + (size_t)m0 * KPAD,
                  WoTHi + (size_t)c0 * KPAD, WoTLo + (size_t)c0 * KPAD,
                  acc);

    const float* biass = (const float*)(smw + WBIAS);
    float* ssP = (float*)(smw + WSSP);

    __syncthreads();
    #pragma unroll
    for (int mt = 0; mt < 2; mt++) {
        #pragma unroll
        for (int half = 0; half < 2; half++) {
            int lrow = wm * 32 + mt * 16 + g + half * 8;
            int row = m0 + lrow;
            float ss = 0.f;
            #pragma unroll
            for (int nt = 0; nt < 4; nt++) {
                #pragma unroll
                for (int cc = 0; cc < 2; cc++) {
                    int col = wn * 32 + nt * 8 + 2 * t + cc;
                    float v = acc[mt][nt][half * 2 + cc] + biass[col];
                    out[(size_t)row * Dm + 1 + c0 + col] = v;
                    ss += v * v;
                }
            }
            ss += __shfl_xor_sync(0xffffffffu, ss, 1);
            ss += __shfl_xor_sync(0xffffffffu, ss, 2);
            if (t == 0) ssP[lrow * 2 + wn] = ss;
        }
    }
    __syncthreads();
    if (wn == 0 && t == 0) {
        #pragma unroll
        for (int mt = 0; mt < 2; mt++)
            #pragma unroll
            for (int half = 0; half < 2; half++) {
                int lrow = wm * 32 + mt * 16 + g + half * 8;
                int row = m0 + lrow;
                Part2[row * 8 + blockIdx.y] = ssP[lrow * 2] + ssP[lrow * 2 + 1];
            }
    }
}

__global__ void time_kernel(float* __restrict__ out)
{
    int row = blockIdx.x * 256 + threadIdx.x;
    if (row < Mrows) {
        float ss = 0.f;
        #pragma unroll
        for (int j = 0; j < 8; j++) ss += Part2[row * 8 + j];
        out[(size_t)row * Dm] = sqrtf(fmaxf(INVK + ss, EPSf));
    }
}

// =====================================================================
extern "C" void kernel_launch(void* const* d_in, const int* in_sizes, int n_in,
                              void* d_out, int out_size)
{
    const float* x  = (const float*)d_in[0];
    const float* Wq = (const float*)d_in[1];
    const float* bq = (const float*)d_in[2];
    const float* Wk = (const float*)d_in[3];
    const float* bk = (const float*)d_in[4];
    const float* Wv = (const float*)d_in[5];
    const float* bv = (const float*)d_in[6];
    const float* Wo = (const float*)d_in[7];
    const float* bo = (const float*)d_in[8];
    float* out = (float*)d_out;

    const int smem_gemm = WTOT * 4;          // 111872 bytes
    const int smem_attn = 2 * ABUF * 4;
    cudaFuncSetAttribute(qkv_mma, cudaFuncAttributeMaxDynamicSharedMemorySize, smem_gemm);
    cudaFuncSetAttribute(outproj_mma, cudaFuncAttributeMaxDynamicSharedMemorySize, smem_gemm);
    cudaFuncSetAttribute(attn_mma, cudaFuncAttributeMaxDynamicSharedMemorySize, smem_attn);

    cvt_in_kernel<<<10240, 576>>>(Wq, Wk, Wv, Wo, x);
    qkv_mma<<<dim3(64, 24), 256, smem_gemm>>>(bq, bk, bv);
    vtrans<<<dim3(32, 32), 128>>>();
    attn_mma<<<dim3(16, 32), 256, smem_attn>>>();
    cvt_cat_kernel<<<8192, 576>>>();
    outproj_mma<<<dim3(64, 8), 256, smem_gemm>>>(bo, out);
    time_kernel<<<32, 256>>>(out);
}